// round 3
// baseline (speedup 1.0000x reference)
#include <cuda_runtime.h>
#include <math.h>

#define B_    4
#define S_    2048
#define DIN_  768
#define E_    768
#define H_    12
#define HD_   64
#define QKV3_ 2304

#define TQ_   32            // query tile
#define TK_   64            // key chunk
#define LSTR_ 449           // logits row stride (window union <= 442)
#define KSTR_ 68            // K/V/Q smem row stride (16B-aligned, conflict-free)
#define PW_   416           // probs scratch row stride (window <= 411)

// ---------------- scratch (device globals: allowed, no runtime alloc) -------
__device__ float g_qkv[(size_t)B_ * S_ * QKV3_];            // [B,S,3E]
__device__ float g_vals[(size_t)B_ * S_ * E_];              // [B,S,E]
__device__ float g_probs[(size_t)B_ * H_ * S_ * PW_];       // per-head window probs
__device__ int   g_w[B_];

// ---------------- per-batch window size -------------------------------------
__global__ void wsz_kernel(const int* __restrict__ mask) {
    __shared__ int red[256];
    int b = blockIdx.x;
    int s = 0;
    for (int i = threadIdx.x; i < S_; i += 256) s += (mask[b * S_ + i] == 0);
    red[threadIdx.x] = s;
    __syncthreads();
    for (int o = 128; o > 0; o >>= 1) {
        if (threadIdx.x < o) red[threadIdx.x] += red[threadIdx.x + o];
        __syncthreads();
    }
    if (threadIdx.x == 0) {
        int len = red[0];
        if (len > 2048) len = 2048;
        float w = ceilf((float)len * 10.0f / 100.0f);
        w = fmaxf(w, 2.0f);
        g_w[b] = (int)w;
    }
}

// ---------------- SGEMM: C[m,n] = sum_k A[m,k]*Bw[n,k] + bias[n] ------------
__global__ __launch_bounds__(256) void sgemm_tn(
    const float* __restrict__ A, const float* __restrict__ Bw,
    const float* __restrict__ bias, float* __restrict__ C,
    int M, int N, int K)
{
    __shared__ float As[8][128];
    __shared__ float Bs[8][128];

    const int tid = threadIdx.x;
    const int blockRow = blockIdx.y;
    const int blockCol = blockIdx.x;

    const float* Ab = A  + (size_t)blockRow * 128 * K;
    const float* Bb = Bw + (size_t)blockCol * 128 * K;

    const int lr = tid >> 1;
    const int lc = (tid & 1) * 4;
    const int tr = (tid >> 4) * 8;
    const int tc = (tid & 15) * 8;

    float acc[8][8];
    #pragma unroll
    for (int i = 0; i < 8; ++i)
        #pragma unroll
        for (int j = 0; j < 8; ++j) acc[i][j] = 0.0f;

    for (int k0 = 0; k0 < K; k0 += 8) {
        float4 a4 = *(const float4*)(Ab + (size_t)lr * K + k0 + lc);
        float4 b4 = *(const float4*)(Bb + (size_t)lr * K + k0 + lc);
        As[lc + 0][lr] = a4.x; As[lc + 1][lr] = a4.y;
        As[lc + 2][lr] = a4.z; As[lc + 3][lr] = a4.w;
        Bs[lc + 0][lr] = b4.x; Bs[lc + 1][lr] = b4.y;
        Bs[lc + 2][lr] = b4.z; Bs[lc + 3][lr] = b4.w;
        __syncthreads();

        #pragma unroll
        for (int k = 0; k < 8; ++k) {
            float ra[8], rb[8];
            #pragma unroll
            for (int i = 0; i < 4; ++i) {
                float4 v = *(const float4*)(&As[k][tr + i * 4]);
                ra[i*4+0] = v.x; ra[i*4+1] = v.y; ra[i*4+2] = v.z; ra[i*4+3] = v.w;
            }
            #pragma unroll
            for (int j = 0; j < 4; ++j) {
                float4 v = *(const float4*)(&Bs[k][tc + j * 4]);
                rb[j*4+0] = v.x; rb[j*4+1] = v.y; rb[j*4+2] = v.z; rb[j*4+3] = v.w;
            }
            #pragma unroll
            for (int i = 0; i < 8; ++i)
                #pragma unroll
                for (int j = 0; j < 8; ++j)
                    acc[i][j] = fmaf(ra[i], rb[j], acc[i][j]);
        }
        __syncthreads();
    }

    const int grow = blockRow * 128 + tr;
    const int gcol = blockCol * 128 + tc;
    float bb[8];
    #pragma unroll
    for (int j = 0; j < 8; ++j) bb[j] = bias[gcol + j];
    #pragma unroll
    for (int i = 0; i < 8; ++i) {
        float4 o0, o1;
        o0.x = acc[i][0]+bb[0]; o0.y = acc[i][1]+bb[1];
        o0.z = acc[i][2]+bb[2]; o0.w = acc[i][3]+bb[3];
        o1.x = acc[i][4]+bb[4]; o1.y = acc[i][5]+bb[5];
        o1.z = acc[i][6]+bb[6]; o1.w = acc[i][7]+bb[7];
        float* cp = C + (size_t)(grow + i) * N + gcol;
        *(float4*)(cp)     = o0;
        *(float4*)(cp + 4) = o1;
    }
}

// ---------------- flash-style windowed attention ----------------------------
// Block per (q-tile=32, head, batch). 256 threads.
// Full union-window logits in smem (no online softmax); out-of-window entries
// get -1e9 -> exp underflows to exact 0, matching the reference fp32 softmax.
__global__ __launch_bounds__(256, 2) void attn_tile_kernel(
    const float* __restrict__ matrix_mask)
{
    extern __shared__ float sm[];
    float* Ls  = sm;                          // [TQ_][LSTR_]
    float* Qs  = Ls  + TQ_ * LSTR_;           // [TQ_][KSTR_]
    float* KsT = Qs  + TQ_ * KSTR_;           // [64 d][KSTR_] (d-major!)
    float* Vs  = KsT + TK_ * KSTR_;           // [TK_ j][KSTR_]

    const int q0  = blockIdx.x * TQ_;
    const int h   = blockIdx.y;
    const int b   = blockIdx.z;
    const int tid = threadIdx.x;

    const int w    = g_w[b];
    const int jlo0 = max(q0 - w, 0);
    const int jhi0 = min(q0 + TQ_ - 1 + w, S_ - 1);
    const int WU   = jhi0 - jlo0 + 1;                 // <= 442
    const int nchunks = (WU + TK_ - 1) / TK_;

    const float* qkvb = g_qkv + (size_t)b * S_ * QKV3_;

    // ---- load Q tile: Qs[r][d] ----
    for (int idx = tid; idx < TQ_ * 64; idx += 256) {
        int r = idx >> 6, d = idx & 63;
        Qs[r * KSTR_ + d] = qkvb[(size_t)(q0 + r) * QKV3_ + h * 192 + d];
    }

    const int r   = tid >> 3;            // 0..31 query row
    const int c0  = (tid & 7) * 8;       // 8-wide column group
    const int q   = q0 + r;
    const float scale = 0.125f;
    const float* mmrow = matrix_mask + ((size_t)b * S_ + q) * S_;

    // ---- QK: logits into Ls ----
    for (int kc = 0; kc < nchunks; ++kc) {
        const int jbase = jlo0 + kc * TK_;
        __syncthreads();
        // load K chunk transposed: KsT[d][jj]
        {
            int jj = tid >> 2;
            int d0 = (tid & 3) * 16;
            int jg = min(jbase + jj, S_ - 1);
            const float* kp = qkvb + (size_t)jg * QKV3_ + h * 192 + 64 + d0;
            #pragma unroll
            for (int i = 0; i < 16; i += 4) {
                float4 kk = *(const float4*)(kp + i);
                KsT[(d0 + i + 0) * KSTR_ + jj] = kk.x;
                KsT[(d0 + i + 1) * KSTR_ + jj] = kk.y;
                KsT[(d0 + i + 2) * KSTR_ + jj] = kk.z;
                KsT[(d0 + i + 3) * KSTR_ + jj] = kk.w;
            }
        }
        __syncthreads();

        float acc[8];
        #pragma unroll
        for (int i = 0; i < 8; ++i) acc[i] = 0.0f;

        #pragma unroll 4
        for (int d = 0; d < 64; ++d) {
            float qv = Qs[r * KSTR_ + d];
            float4 k0 = *(const float4*)(&KsT[d * KSTR_ + c0]);
            float4 k1 = *(const float4*)(&KsT[d * KSTR_ + c0 + 4]);
            acc[0] = fmaf(qv, k0.x, acc[0]); acc[1] = fmaf(qv, k0.y, acc[1]);
            acc[2] = fmaf(qv, k0.z, acc[2]); acc[3] = fmaf(qv, k0.w, acc[3]);
            acc[4] = fmaf(qv, k1.x, acc[4]); acc[5] = fmaf(qv, k1.y, acc[5]);
            acc[6] = fmaf(qv, k1.z, acc[6]); acc[7] = fmaf(qv, k1.w, acc[7]);
        }

        #pragma unroll
        for (int i = 0; i < 8; ++i) {
            int jgl = jbase + c0 + i;
            bool valid = (jgl <= jhi0) && (abs(jgl - q) <= w);
            float mval = valid ? mmrow[jgl] : -1e9f;
            Ls[r * LSTR_ + kc * TK_ + c0 + i] = acc[i] * scale + mval;
        }
    }
    __syncthreads();

    // ---- softmax per row (warp per 4 rows) + probs scratch write ----
    {
        const int warp = tid >> 5, lane = tid & 31;
        for (int rr = warp; rr < TQ_; rr += 8) {
            float* row = Ls + rr * LSTR_;
            float mx = -3.0e38f;
            for (int t = lane; t < WU; t += 32) mx = fmaxf(mx, row[t]);
            #pragma unroll
            for (int o = 16; o > 0; o >>= 1)
                mx = fmaxf(mx, __shfl_xor_sync(0xFFFFFFFFu, mx, o));
            float sum = 0.0f;
            for (int t = lane; t < WU; t += 32) {
                float e = __expf(row[t] - mx);
                row[t] = e;
                sum += e;
            }
            #pragma unroll
            for (int o = 16; o > 0; o >>= 1)
                sum += __shfl_xor_sync(0xFFFFFFFFu, sum, o);
            const float inv = 1.0f / sum;
            const int qq   = q0 + rr;
            const int jloq = max(qq - w, 0);
            const int jhiq = min(qq + w, S_ - 1);
            const int Wq   = jhiq - jloq + 1;
            const int off  = jloq - jlo0;
            float* prow = g_probs + (((size_t)(b * H_ + h) * S_) + qq) * PW_;
            for (int t = lane; t < WU; t += 32) row[t] *= inv;
            __syncwarp();
            for (int t = lane; t < Wq; t += 32) prow[t] = row[off + t];
        }
    }

    // ---- PV: O[r][d] = sum_j P[r][j] * V[j][d] ----
    float o[8];
    #pragma unroll
    for (int i = 0; i < 8; ++i) o[i] = 0.0f;

    for (int kc = 0; kc < nchunks; ++kc) {
        const int jbase = jlo0 + kc * TK_;
        __syncthreads();
        {
            int jj = tid >> 2;
            int d0 = (tid & 3) * 16;
            int jg = min(jbase + jj, S_ - 1);
            const float* vp = qkvb + (size_t)jg * QKV3_ + h * 192 + 128 + d0;
            float4 v0 = *(const float4*)(vp);
            float4 v1 = *(const float4*)(vp + 4);
            float4 v2 = *(const float4*)(vp + 8);
            float4 v3 = *(const float4*)(vp + 12);
            *(float4*)(&Vs[jj * KSTR_ + d0])      = v0;
            *(float4*)(&Vs[jj * KSTR_ + d0 + 4])  = v1;
            *(float4*)(&Vs[jj * KSTR_ + d0 + 8])  = v2;
            *(float4*)(&Vs[jj * KSTR_ + d0 + 12]) = v3;
        }
        __syncthreads();

        const int nk = min(TK_, WU - kc * TK_);
        #pragma unroll 4
        for (int jj = 0; jj < nk; ++jj) {
            float p = Ls[r * LSTR_ + kc * TK_ + jj];
            float4 v0 = *(const float4*)(&Vs[jj * KSTR_ + c0]);
            float4 v1 = *(const float4*)(&Vs[jj * KSTR_ + c0 + 4]);
            o[0] = fmaf(p, v0.x, o[0]); o[1] = fmaf(p, v0.y, o[1]);
            o[2] = fmaf(p, v0.z, o[2]); o[3] = fmaf(p, v0.w, o[3]);
            o[4] = fmaf(p, v1.x, o[4]); o[5] = fmaf(p, v1.y, o[5]);
            o[6] = fmaf(p, v1.z, o[6]); o[7] = fmaf(p, v1.w, o[7]);
        }
    }

    float* op = g_vals + (size_t)(b * S_ + q) * E_ + h * 64 + c0;
    *(float4*)(op)     = make_float4(o[0], o[1], o[2], o[3]);
    *(float4*)(op + 4) = make_float4(o[4], o[5], o[6], o[7]);
}

// ---------------- attn_mean: deterministic head reduction --------------------
__global__ __launch_bounds__(256) void mean_kernel(float* __restrict__ out_attn) {
    const int bq = blockIdx.x;
    const int b  = bq >> 11;
    const int q  = bq & 2047;
    const int w  = g_w[b];
    const int jlo = max(q - w, 0);
    const int jhi = min(q + w, S_ - 1);

    float* arow = out_attn + (size_t)bq * S_;
    const float* pbase = g_probs + ((size_t)b * H_ * S_ + q) * PW_;

    for (int j = threadIdx.x; j < S_; j += 256) {
        float m = 0.0f;
        if (j >= jlo && j <= jhi) {
            int t = j - jlo;
            #pragma unroll
            for (int hh = 0; hh < H_; ++hh)
                m += pbase[(size_t)hh * S_ * PW_ + t];
            m *= (1.0f / 12.0f);
        }
        arow[j] = m;
    }
}

// ---------------- launch -----------------------------------------------------
extern "C" void kernel_launch(void* const* d_in, const int* in_sizes, int n_in,
                              void* d_out, int out_size) {
    const float* x      = (const float*)d_in[0];
    const int*   skpm   = (const int*)  d_in[1];
    const float* mmask  = (const float*)d_in[2];
    const float* qkv_w  = (const float*)d_in[3];
    const float* qkv_b  = (const float*)d_in[4];
    const float* o_w    = (const float*)d_in[5];
    const float* o_b    = (const float*)d_in[6];

    float* out      = (float*)d_out;
    float* out_o    = out;                          // [B,S,E]
    float* out_attn = out + (size_t)B_ * S_ * E_;   // [B,S,S]

    float* qkv_ptr = nullptr;
    float* val_ptr = nullptr;
    cudaGetSymbolAddress((void**)&qkv_ptr, g_qkv);
    cudaGetSymbolAddress((void**)&val_ptr, g_vals);

    const int attn_smem = (TQ_ * LSTR_ + TQ_ * KSTR_ + 2 * TK_ * KSTR_) * 4;
    cudaFuncSetAttribute(attn_tile_kernel,
                         cudaFuncAttributeMaxDynamicSharedMemorySize, attn_smem);

    // 1) per-batch window size
    wsz_kernel<<<B_, 256>>>(skpm);

    // 2) QKV projection
    {
        dim3 grid(QKV3_ / 128, (B_ * S_) / 128);
        sgemm_tn<<<grid, 256>>>(x, qkv_w, qkv_b, qkv_ptr, B_ * S_, QKV3_, DIN_);
    }

    // 3) windowed attention (probs -> g_probs, values -> g_vals)
    {
        dim3 grid(S_ / TQ_, H_, B_);
        attn_tile_kernel<<<grid, 256, attn_smem>>>(mmask);
    }

    // 4) attn_mean reduction (deterministic, no atomics)
    mean_kernel<<<B_ * S_, 256>>>(out_attn);

    // 5) output projection
    {
        dim3 grid(E_ / 128, (B_ * S_) / 128);
        sgemm_tn<<<grid, 256>>>(val_ptr, o_w, o_b, out_o, B_ * S_, E_, E_);
    }
}

// round 9
// speedup vs baseline: 1.2446x; 1.2446x over previous
#include <cuda_runtime.h>
#include <cuda_bf16.h>
#include <math.h>
#include <stdint.h>

#define B_    4
#define S_    2048
#define DIN_  768
#define E_    768
#define H_    12
#define HD_   64
#define QKV3_ 2304

#define TQ_   32
#define TK_   64
#define LSTR_ 449
#define KSTR_ 68
#define PW_   416

// tcgen05 PTX is only legal when compiling for an arch-specific feature target
// (compute_103a / compute_100a). A plain compute_103 pass must not see any
// tcgen05 instruction, or ptxas hard-fails. Guard + FFMA fallback.
#if defined(__CUDA_ARCH_FEAT_SM103_ALL) || defined(__CUDA_ARCH_FEAT_SM100_ALL) || defined(__CUDA_ARCH_FEAT_SM101_ALL)
#define GB_HAS_TC 1
#else
#define GB_HAS_TC 0
#endif

// ---------------- scratch ----------------------------------------------------
__device__ float g_qkv[(size_t)B_ * S_ * QKV3_];
__device__ float g_vals[(size_t)B_ * S_ * E_];
__device__ float g_probs[(size_t)B_ * H_ * S_ * PW_];
__device__ int   g_w[B_];

// ======================= tcgen05 helpers (feature-gated) =====================
#if GB_HAS_TC
__device__ __forceinline__ uint32_t smem_u32(const void* p) {
    uint32_t a;
    asm("{ .reg .u64 t; cvta.to.shared.u64 t, %1; cvt.u32.u64 %0, t; }"
        : "=r"(a) : "l"(p));
    return a;
}
__device__ __forceinline__ uint32_t elect_one() {
    uint32_t pred;
    asm volatile("{\n\t.reg .pred p;\n\telect.sync _|p, 0xFFFFFFFF;\n\t"
                 "selp.b32 %0, 1, 0, p;\n\t}" : "=r"(pred));
    return pred;
}
#define MBAR_INIT(addr, cnt) \
    asm volatile("mbarrier.init.shared.b64 [%0], %1;" :: "r"(addr), "r"(cnt) : "memory")
#define MBAR_INVAL(addr) \
    asm volatile("mbarrier.inval.shared.b64 [%0];" :: "r"(addr) : "memory")
#define MBAR_WAIT(addr, par) do {                                              \
    uint32_t _m = (addr), _p = (par), _d;                                      \
    asm volatile("{\n\t.reg .pred p;\n\t"                                      \
        "mbarrier.try_wait.parity.acquire.cta.shared::cta.b64 p, [%1], %2;\n\t"\
        "selp.b32 %0, 1, 0, p;\n\t}" : "=r"(_d) : "r"(_m), "r"(_p) : "memory");\
    if (!_d) {                                                                 \
        asm volatile("{\n\t.reg .pred P1;\n\tWL_%=: \n\t"                      \
            "mbarrier.try_wait.parity.acquire.cta.shared::cta.b64 P1, [%0], %1, 0x989680;\n\t" \
            "@P1 bra.uni WD_%=;\n\tbra.uni WL_%=;\n\tWD_%=: \n\t}"            \
            :: "r"(_m), "r"(_p) : "memory");                                   \
    }                                                                          \
} while (0)
#define TC_ALLOC(slot, n) \
    asm volatile("tcgen05.alloc.cta_group::1.sync.aligned.shared::cta.b32 [%0], %1;" \
                 :: "r"(slot), "r"((uint32_t)(n)) : "memory")
#define TC_DEALLOC(tm, n) \
    asm volatile("tcgen05.dealloc.cta_group::1.sync.aligned.b32 %0, %1;" \
                 :: "r"(tm), "r"((uint32_t)(n)))
#define TC_COMMIT(mb) \
    asm volatile("tcgen05.commit.cta_group::1.mbarrier::arrive::one.shared::cluster.b64 [%0];" \
                 :: "r"(mb) : "memory")
#define TC_FENCE_AFTER()  asm volatile("tcgen05.fence::after_thread_sync;" ::: "memory")
#define TC_FENCE_BEFORE() asm volatile("tcgen05.fence::before_thread_sync;" ::: "memory")
#define TC_WAIT_LD() asm volatile("tcgen05.wait::ld.sync.aligned;" ::: "memory")
#define FENCE_ASYNC_SHARED() asm volatile("fence.proxy.async.shared::cta;" ::: "memory")
#define TC_LD_X32(r, tm)                                                       \
    asm volatile("tcgen05.ld.sync.aligned.32x32b.x32.b32 "                     \
        "{%0, %1, %2, %3, %4, %5, %6, %7, %8, %9, %10, %11, %12, %13, %14, %15, " \
        " %16, %17, %18, %19, %20, %21, %22, %23, %24, %25, %26, %27, %28, %29, %30, %31}, [%32];" \
        : "=r"((r)[0]),  "=r"((r)[1]),  "=r"((r)[2]),  "=r"((r)[3]),           \
          "=r"((r)[4]),  "=r"((r)[5]),  "=r"((r)[6]),  "=r"((r)[7]),           \
          "=r"((r)[8]),  "=r"((r)[9]),  "=r"((r)[10]), "=r"((r)[11]),          \
          "=r"((r)[12]), "=r"((r)[13]), "=r"((r)[14]), "=r"((r)[15]),          \
          "=r"((r)[16]), "=r"((r)[17]), "=r"((r)[18]), "=r"((r)[19]),          \
          "=r"((r)[20]), "=r"((r)[21]), "=r"((r)[22]), "=r"((r)[23]),          \
          "=r"((r)[24]), "=r"((r)[25]), "=r"((r)[26]), "=r"((r)[27]),          \
          "=r"((r)[28]), "=r"((r)[29]), "=r"((r)[30]), "=r"((r)[31])           \
        : "r"(tm))

static constexpr uint64_t SDESC_BASE_SW128 =
    (uint64_t(2) << 61) | (uint64_t(1) << 46) | (uint64_t(64) << 32) | (uint64_t(1) << 16);
#define MK_DESC(addr) (SDESC_BASE_SW128 | ((uint64_t)((addr) >> 4) & 0x3FFF))
#define SW128(off) ((off) ^ (((off) >> 3) & 0x70))

__device__ __forceinline__ void mma_f16_ss(uint32_t d_tmem, uint64_t a_desc,
                                           uint64_t b_desc, uint32_t idesc,
                                           uint32_t en) {
    asm volatile("{\n\t.reg .pred p;\n\tsetp.ne.u32 p, %5, 0;\n\t"
                 "tcgen05.mma.cta_group::1.kind::f16 [%0], %1, %2, %3, {%4, %4, %4, %4}, p;\n\t}"
                 :: "r"(d_tmem), "l"(a_desc), "l"(b_desc), "r"(idesc),
                    "r"(0u), "r"(en) : "memory");
}

__device__ __forceinline__ uint32_t pk_bf16(__nv_bfloat16 a, __nv_bfloat16 b) {
    return ((uint32_t)__bfloat16_as_ushort(b) << 16) | __bfloat16_as_ushort(a);
}
#endif  // GB_HAS_TC

// ---------------- per-batch window size -------------------------------------
__global__ void wsz_kernel(const int* __restrict__ mask) {
    __shared__ int red[256];
    int b = blockIdx.x;
    int s = 0;
    for (int i = threadIdx.x; i < S_; i += 256) s += (mask[b * S_ + i] == 0);
    red[threadIdx.x] = s;
    __syncthreads();
    for (int o = 128; o > 0; o >>= 1) {
        if (threadIdx.x < o) red[threadIdx.x] += red[threadIdx.x + o];
        __syncthreads();
    }
    if (threadIdx.x == 0) {
        int len = red[0];
        if (len > 2048) len = 2048;
        float w = ceilf((float)len * 10.0f / 100.0f);
        w = fmaxf(w, 2.0f);
        g_w[b] = (int)w;
    }
}

// ================= GEMM: C = A @ Bw^T + bias =================================
// Tensor path (sm_103a feature pass): 128x128 tile, bf16x3 split on tcgen05.
// Fallback path (plain compute_103 pass): 128x128x8 FFMA SGEMM.
#define GBM 128
#define GBN 128
#define GKC 64
#define GTILE (GBM * GKC * 2)         // 16 KB per bf16 tile
#define GSMEM (1024 + 8 * GTILE)      // 129 KB: pad + 2 stages * 4 tiles

#if GB_HAS_TC
static constexpr uint32_t G_IDESC =
    (1u << 4) | (1u << 7) | (1u << 10) | ((GBN / 8) << 17) | ((GBM / 16) << 24);

// fill one [128 rows x 64 cols] fp32 -> bf16 hi/lo pair of SW128 tiles
__device__ __forceinline__ void fill_bf16(const float* __restrict__ src, int ld,
                                          char* sm_hi, char* sm_lo, int t) {
    const int row  = t >> 1;
    const int half = t & 1;
    const float* p = src + (size_t)row * ld + half * 32;
    #pragma unroll
    for (int i = 0; i < 8; ++i) {
        float4 v = *(const float4*)(p + i * 4);
        __nv_bfloat16 hx = __float2bfloat16_rn(v.x);
        __nv_bfloat16 hy = __float2bfloat16_rn(v.y);
        __nv_bfloat16 hz = __float2bfloat16_rn(v.z);
        __nv_bfloat16 hw = __float2bfloat16_rn(v.w);
        float lx = v.x - __bfloat162float(hx);
        float ly = v.y - __bfloat162float(hy);
        float lz = v.z - __bfloat162float(hz);
        float lw = v.w - __bfloat162float(hw);
        uint32_t off = SW128((uint32_t)(row * 128 + half * 64 + i * 8));
        *(uint2*)(sm_hi + off) = make_uint2(pk_bf16(hx, hy), pk_bf16(hz, hw));
        *(uint2*)(sm_lo + off) = make_uint2(
            pk_bf16(__float2bfloat16_rn(lx), __float2bfloat16_rn(ly)),
            pk_bf16(__float2bfloat16_rn(lz), __float2bfloat16_rn(lw)));
    }
}
#endif

__global__ __launch_bounds__(256, 1) void gemm_tc(
    const float* __restrict__ A, const float* __restrict__ Bw,
    const float* __restrict__ bias, float* __restrict__ C,
    int M, int N, int K)
{
    extern __shared__ char dsm[];
#if GB_HAS_TC
    // ---------------- tcgen05 bf16x3 path ----------------
    __shared__ uint32_t s_tmem[1];
    __shared__ uint64_t s_mbar[3];        // stage0, stage1, final

    const int tid = threadIdx.x;
    const int wid = tid >> 5;
    const int lane = tid & 31;
    const int m0 = blockIdx.y * GBM;
    const int n0 = blockIdx.x * GBN;

    const uint32_t raw  = smem_u32(dsm);
    const uint32_t base = (raw + 1023u) & ~1023u;
    char* sbase = dsm + (base - raw);

    const uint32_t mb0 = smem_u32(&s_mbar[0]);
    const uint32_t mb1 = smem_u32(&s_mbar[1]);
    const uint32_t mbF = smem_u32(&s_mbar[2]);
    const uint32_t slot = smem_u32(&s_tmem[0]);

    if (tid == 0) {
        MBAR_INIT(mb0, 1);
        MBAR_INIT(mb1, 1);
        MBAR_INIT(mbF, 1);
    }
    if (wid == 0) TC_ALLOC(slot, 128);
    __syncthreads();
    const uint32_t tmem = s_tmem[0];

    const int NC = K / GKC;
    for (int c = 0; c < NC; ++c) {
        const int s = c & 1;
        const int u = c >> 1;
        const uint32_t mbs = s ? mb1 : mb0;
        if (u >= 1) MBAR_WAIT(mbs, (u - 1) & 1);

        char* stg = sbase + s * 4 * GTILE;
        fill_bf16(A  + (size_t)m0 * K + c * GKC, K, stg,             stg + GTILE,     tid);
        fill_bf16(Bw + (size_t)n0 * K + c * GKC, K, stg + 2 * GTILE, stg + 3 * GTILE, tid);
        FENCE_ASYNC_SHARED();
        __syncthreads();

        if (wid == 0 && elect_one()) {
            const uint32_t sb = base + s * 4 * GTILE;
            const uint64_t dAh = MK_DESC(sb);
            const uint64_t dAl = MK_DESC(sb + GTILE);
            const uint64_t dBh = MK_DESC(sb + 2 * GTILE);
            const uint64_t dBl = MK_DESC(sb + 3 * GTILE);
            #pragma unroll
            for (int kk = 0; kk < 4; ++kk)
                mma_f16_ss(tmem, dAh + kk * 2, dBh + kk * 2, G_IDESC,
                           (c == 0 && kk == 0) ? 0u : 1u);
            #pragma unroll
            for (int kk = 0; kk < 4; ++kk)
                mma_f16_ss(tmem, dAh + kk * 2, dBl + kk * 2, G_IDESC, 1u);
            #pragma unroll
            for (int kk = 0; kk < 4; ++kk)
                mma_f16_ss(tmem, dAl + kk * 2, dBh + kk * 2, G_IDESC, 1u);
            TC_COMMIT(mbs);
            if (c == NC - 1) TC_COMMIT(mbF);
        }
    }

    MBAR_WAIT(mbF, 0);
    TC_FENCE_AFTER();

    if (wid < 4) {
        const int row = wid * 32 + lane;
        float* crow = C + (size_t)(m0 + row) * N + n0;
        #pragma unroll
        for (int bb = 0; bb < 4; ++bb) {
            uint32_t r[32];
            TC_LD_X32(r, tmem + bb * 32);
            TC_WAIT_LD();
            #pragma unroll
            for (int i = 0; i < 32; i += 4) {
                float4 o;
                o.x = __uint_as_float(r[i + 0]) + bias[n0 + bb * 32 + i + 0];
                o.y = __uint_as_float(r[i + 1]) + bias[n0 + bb * 32 + i + 1];
                o.z = __uint_as_float(r[i + 2]) + bias[n0 + bb * 32 + i + 2];
                o.w = __uint_as_float(r[i + 3]) + bias[n0 + bb * 32 + i + 3];
                *(float4*)(crow + bb * 32 + i) = o;
            }
        }
        TC_FENCE_BEFORE();
    }
    __syncthreads();
    if (tid == 0) { MBAR_INVAL(mb0); MBAR_INVAL(mb1); MBAR_INVAL(mbF); }
    if (wid == 0) TC_DEALLOC(tmem, 128);
#else
    // ---------------- FFMA fallback (proven round-3 SGEMM) ----------------
    float* As = (float*)dsm;            // [8][128]
    float* Bs = As + 8 * 128;           // [8][128]

    const int tid = threadIdx.x;
    const int blockRow = blockIdx.y;
    const int blockCol = blockIdx.x;

    const float* Ab = A  + (size_t)blockRow * 128 * K;
    const float* Bb = Bw + (size_t)blockCol * 128 * K;

    const int lr = tid >> 1;
    const int lc = (tid & 1) * 4;
    const int tr = (tid >> 4) * 8;
    const int tc = (tid & 15) * 8;

    float acc[8][8];
    #pragma unroll
    for (int i = 0; i < 8; ++i)
        #pragma unroll
        for (int j = 0; j < 8; ++j) acc[i][j] = 0.0f;

    for (int k0 = 0; k0 < K; k0 += 8) {
        float4 a4 = *(const float4*)(Ab + (size_t)lr * K + k0 + lc);
        float4 b4 = *(const float4*)(Bb + (size_t)lr * K + k0 + lc);
        As[(lc + 0) * 128 + lr] = a4.x; As[(lc + 1) * 128 + lr] = a4.y;
        As[(lc + 2) * 128 + lr] = a4.z; As[(lc + 3) * 128 + lr] = a4.w;
        Bs[(lc + 0) * 128 + lr] = b4.x; Bs[(lc + 1) * 128 + lr] = b4.y;
        Bs[(lc + 2) * 128 + lr] = b4.z; Bs[(lc + 3) * 128 + lr] = b4.w;
        __syncthreads();

        #pragma unroll
        for (int k = 0; k < 8; ++k) {
            float ra[8], rb[8];
            #pragma unroll
            for (int i = 0; i < 4; ++i) {
                float4 v = *(const float4*)(&As[k * 128 + tr + i * 4]);
                ra[i*4+0] = v.x; ra[i*4+1] = v.y; ra[i*4+2] = v.z; ra[i*4+3] = v.w;
            }
            #pragma unroll
            for (int j = 0; j < 4; ++j) {
                float4 v = *(const float4*)(&Bs[k * 128 + tc + j * 4]);
                rb[j*4+0] = v.x; rb[j*4+1] = v.y; rb[j*4+2] = v.z; rb[j*4+3] = v.w;
            }
            #pragma unroll
            for (int i = 0; i < 8; ++i)
                #pragma unroll
                for (int j = 0; j < 8; ++j)
                    acc[i][j] = fmaf(ra[i], rb[j], acc[i][j]);
        }
        __syncthreads();
    }

    const int grow = blockRow * 128 + tr;
    const int gcol = blockCol * 128 + tc;
    float bb[8];
    #pragma unroll
    for (int j = 0; j < 8; ++j) bb[j] = bias[gcol + j];
    #pragma unroll
    for (int i = 0; i < 8; ++i) {
        float4 o0, o1;
        o0.x = acc[i][0]+bb[0]; o0.y = acc[i][1]+bb[1];
        o0.z = acc[i][2]+bb[2]; o0.w = acc[i][3]+bb[3];
        o1.x = acc[i][4]+bb[4]; o1.y = acc[i][5]+bb[5];
        o1.z = acc[i][6]+bb[6]; o1.w = acc[i][7]+bb[7];
        float* cp = C + (size_t)(grow + i) * N + gcol;
        *(float4*)(cp)     = o0;
        *(float4*)(cp + 4) = o1;
    }
#endif
}

// ---------------- flash-style windowed attention (unchanged) ----------------
__global__ __launch_bounds__(256, 2) void attn_tile_kernel(
    const float* __restrict__ matrix_mask)
{
    extern __shared__ float sm[];
    float* Ls  = sm;
    float* Qs  = Ls  + TQ_ * LSTR_;
    float* KsT = Qs  + TQ_ * KSTR_;
    float* Vs  = KsT + TK_ * KSTR_;

    const int q0  = blockIdx.x * TQ_;
    const int h   = blockIdx.y;
    const int b   = blockIdx.z;
    const int tid = threadIdx.x;

    const int w    = g_w[b];
    const int jlo0 = max(q0 - w, 0);
    const int jhi0 = min(q0 + TQ_ - 1 + w, S_ - 1);
    const int WU   = jhi0 - jlo0 + 1;
    const int nchunks = (WU + TK_ - 1) / TK_;

    const float* qkvb = g_qkv + (size_t)b * S_ * QKV3_;

    for (int idx = tid; idx < TQ_ * 64; idx += 256) {
        int r = idx >> 6, d = idx & 63;
        Qs[r * KSTR_ + d] = qkvb[(size_t)(q0 + r) * QKV3_ + h * 192 + d];
    }

    const int r   = tid >> 3;
    const int c0  = (tid & 7) * 8;
    const int q   = q0 + r;
    const float scale = 0.125f;
    const float* mmrow = matrix_mask + ((size_t)b * S_ + q) * S_;

    for (int kc = 0; kc < nchunks; ++kc) {
        const int jbase = jlo0 + kc * TK_;
        __syncthreads();
        {
            int jj = tid >> 2;
            int d0 = (tid & 3) * 16;
            int jg = min(jbase + jj, S_ - 1);
            const float* kp = qkvb + (size_t)jg * QKV3_ + h * 192 + 64 + d0;
            #pragma unroll
            for (int i = 0; i < 16; i += 4) {
                float4 kk = *(const float4*)(kp + i);
                KsT[(d0 + i + 0) * KSTR_ + jj] = kk.x;
                KsT[(d0 + i + 1) * KSTR_ + jj] = kk.y;
                KsT[(d0 + i + 2) * KSTR_ + jj] = kk.z;
                KsT[(d0 + i + 3) * KSTR_ + jj] = kk.w;
            }
        }
        __syncthreads();

        float acc[8];
        #pragma unroll
        for (int i = 0; i < 8; ++i) acc[i] = 0.0f;

        #pragma unroll 4
        for (int d = 0; d < 64; ++d) {
            float qv = Qs[r * KSTR_ + d];
            float4 k0 = *(const float4*)(&KsT[d * KSTR_ + c0]);
            float4 k1 = *(const float4*)(&KsT[d * KSTR_ + c0 + 4]);
            acc[0] = fmaf(qv, k0.x, acc[0]); acc[1] = fmaf(qv, k0.y, acc[1]);
            acc[2] = fmaf(qv, k0.z, acc[2]); acc[3] = fmaf(qv, k0.w, acc[3]);
            acc[4] = fmaf(qv, k1.x, acc[4]); acc[5] = fmaf(qv, k1.y, acc[5]);
            acc[6] = fmaf(qv, k1.z, acc[6]); acc[7] = fmaf(qv, k1.w, acc[7]);
        }

        #pragma unroll
        for (int i = 0; i < 8; ++i) {
            int jgl = jbase + c0 + i;
            bool valid = (jgl <= jhi0) && (abs(jgl - q) <= w);
            float mval = valid ? mmrow[jgl] : -1e9f;
            Ls[r * LSTR_ + kc * TK_ + c0 + i] = acc[i] * scale + mval;
        }
    }
    __syncthreads();

    {
        const int warp = tid >> 5, lane = tid & 31;
        for (int rr = warp; rr < TQ_; rr += 8) {
            float* row = Ls + rr * LSTR_;
            float mx = -3.0e38f;
            for (int t = lane; t < WU; t += 32) mx = fmaxf(mx, row[t]);
            #pragma unroll
            for (int o = 16; o > 0; o >>= 1)
                mx = fmaxf(mx, __shfl_xor_sync(0xFFFFFFFFu, mx, o));
            float sum = 0.0f;
            for (int t = lane; t < WU; t += 32) {
                float e = __expf(row[t] - mx);
                row[t] = e;
                sum += e;
            }
            #pragma unroll
            for (int o = 16; o > 0; o >>= 1)
                sum += __shfl_xor_sync(0xFFFFFFFFu, sum, o);
            const float inv = 1.0f / sum;
            const int qq   = q0 + rr;
            const int jloq = max(qq - w, 0);
            const int jhiq = min(qq + w, S_ - 1);
            const int Wq   = jhiq - jloq + 1;
            const int off  = jloq - jlo0;
            float* prow = g_probs + (((size_t)(b * H_ + h) * S_) + qq) * PW_;
            for (int t = lane; t < WU; t += 32) row[t] *= inv;
            __syncwarp();
            for (int t = lane; t < Wq; t += 32) prow[t] = row[off + t];
        }
    }

    float o[8];
    #pragma unroll
    for (int i = 0; i < 8; ++i) o[i] = 0.0f;

    for (int kc = 0; kc < nchunks; ++kc) {
        const int jbase = jlo0 + kc * TK_;
        __syncthreads();
        {
            int jj = tid >> 2;
            int d0 = (tid & 3) * 16;
            int jg = min(jbase + jj, S_ - 1);
            const float* vp = qkvb + (size_t)jg * QKV3_ + h * 192 + 128 + d0;
            float4 v0 = *(const float4*)(vp);
            float4 v1 = *(const float4*)(vp + 4);
            float4 v2 = *(const float4*)(vp + 8);
            float4 v3 = *(const float4*)(vp + 12);
            *(float4*)(&Vs[jj * KSTR_ + d0])      = v0;
            *(float4*)(&Vs[jj * KSTR_ + d0 + 4])  = v1;
            *(float4*)(&Vs[jj * KSTR_ + d0 + 8])  = v2;
            *(float4*)(&Vs[jj * KSTR_ + d0 + 12]) = v3;
        }
        __syncthreads();

        const int nk = min(TK_, WU - kc * TK_);
        #pragma unroll 4
        for (int jj = 0; jj < nk; ++jj) {
            float p = Ls[r * LSTR_ + kc * TK_ + jj];
            float4 v0 = *(const float4*)(&Vs[jj * KSTR_ + c0]);
            float4 v1 = *(const float4*)(&Vs[jj * KSTR_ + c0 + 4]);
            o[0] = fmaf(p, v0.x, o[0]); o[1] = fmaf(p, v0.y, o[1]);
            o[2] = fmaf(p, v0.z, o[2]); o[3] = fmaf(p, v0.w, o[3]);
            o[4] = fmaf(p, v1.x, o[4]); o[5] = fmaf(p, v1.y, o[5]);
            o[6] = fmaf(p, v1.z, o[6]); o[7] = fmaf(p, v1.w, o[7]);
        }
    }

    float* op = g_vals + (size_t)(b * S_ + q) * E_ + h * 64 + c0;
    *(float4*)(op)     = make_float4(o[0], o[1], o[2], o[3]);
    *(float4*)(op + 4) = make_float4(o[4], o[5], o[6], o[7]);
}

// ---------------- attn_mean reduction (unchanged) ----------------------------
__global__ __launch_bounds__(256) void mean_kernel(float* __restrict__ out_attn) {
    const int bq = blockIdx.x;
    const int b  = bq >> 11;
    const int q  = bq & 2047;
    const int w  = g_w[b];
    const int jlo = max(q - w, 0);
    const int jhi = min(q + w, S_ - 1);

    float* arow = out_attn + (size_t)bq * S_;
    const float* pbase = g_probs + ((size_t)b * H_ * S_ + q) * PW_;

    for (int j = threadIdx.x; j < S_; j += 256) {
        float m = 0.0f;
        if (j >= jlo && j <= jhi) {
            int t = j - jlo;
            #pragma unroll
            for (int hh = 0; hh < H_; ++hh)
                m += pbase[(size_t)hh * S_ * PW_ + t];
            m *= (1.0f / 12.0f);
        }
        arow[j] = m;
    }
}

// ---------------- launch -----------------------------------------------------
extern "C" void kernel_launch(void* const* d_in, const int* in_sizes, int n_in,
                              void* d_out, int out_size) {
    const float* x      = (const float*)d_in[0];
    const int*   skpm   = (const int*)  d_in[1];
    const float* mmask  = (const float*)d_in[2];
    const float* qkv_w  = (const float*)d_in[3];
    const float* qkv_b  = (const float*)d_in[4];
    const float* o_w    = (const float*)d_in[5];
    const float* o_b    = (const float*)d_in[6];

    float* out      = (float*)d_out;
    float* out_o    = out;
    float* out_attn = out + (size_t)B_ * S_ * E_;

    float* qkv_ptr = nullptr;
    float* val_ptr = nullptr;
    cudaGetSymbolAddress((void**)&qkv_ptr, g_qkv);
    cudaGetSymbolAddress((void**)&val_ptr, g_vals);

    const int attn_smem = (TQ_ * LSTR_ + TQ_ * KSTR_ + 2 * TK_ * KSTR_) * 4;
    cudaFuncSetAttribute(attn_tile_kernel,
                         cudaFuncAttributeMaxDynamicSharedMemorySize, attn_smem);
    cudaFuncSetAttribute(gemm_tc,
                         cudaFuncAttributeMaxDynamicSharedMemorySize, GSMEM);

    // 1) per-batch window size
    wsz_kernel<<<B_, 256>>>(skpm);

    // 2) QKV projection
    {
        dim3 grid(QKV3_ / GBN, (B_ * S_) / GBM);
        gemm_tc<<<grid, 256, GSMEM>>>(x, qkv_w, qkv_b, qkv_ptr,
                                      B_ * S_, QKV3_, DIN_);
    }

    // 3) windowed attention
    {
        dim3 grid(S_ / TQ_, H_, B_);
        attn_tile_kernel<<<grid, 256, attn_smem>>>(mmask);
    }

    // 4) attn_mean reduction
    mean_kernel<<<B_ * S_, 256>>>(out_attn);

    // 5) output projection
    {
        dim3 grid(E_ / GBN, (B_ * S_) / GBM);
        gemm_tc<<<grid, 256, GSMEM>>>(val_ptr, o_w, o_b, out_o,
                                      B_ * S_, E_, E_);
    }
}

// round 10
// speedup vs baseline: 1.4480x; 1.1634x over previous
#include <cuda_runtime.h>
#include <cuda_bf16.h>
#include <math.h>
#include <stdint.h>

#define B_    4
#define S_    2048
#define DIN_  768
#define E_    768
#define H_    12
#define HD_   64
#define QKV3_ 2304

#define TQ_   32
#define TK_   64
#define LSTR_ 449
#define KSTR_ 68
#define PW_   416

#define NA_   (B_ * S_ * DIN_)      // 6291456  (x / g_vals elements)
#define NWQ_  (QKV3_ * DIN_)        // 1769472  (qkv_w elements)

// tcgen05 PTX is only legal on the arch-feature pass (compute_103a); the plain
// compute_103 pass gets an FFMA fallback.
#if defined(__CUDA_ARCH_FEAT_SM103_ALL) || defined(__CUDA_ARCH_FEAT_SM100_ALL) || defined(__CUDA_ARCH_FEAT_SM101_ALL)
#define GB_HAS_TC 1
#else
#define GB_HAS_TC 0
#endif

// ---------------- scratch ----------------------------------------------------
__device__ float g_qkv[(size_t)B_ * S_ * QKV3_];
__device__ float g_vals[(size_t)B_ * S_ * E_];
__device__ float g_probs[(size_t)B_ * H_ * S_ * PW_];
__device__ int   g_w[B_];
// bf16 hi/lo split operands (16B-aligned for cp.async)
__device__ __align__(256) __nv_bfloat16 g_a_hi[NA_];
__device__ __align__(256) __nv_bfloat16 g_a_lo[NA_];
__device__ __align__(256) __nv_bfloat16 g_w_hi[NWQ_];
__device__ __align__(256) __nv_bfloat16 g_w_lo[NWQ_];

// ---------------- fp32 -> bf16 hi/lo splitter --------------------------------
__global__ __launch_bounds__(256) void cvt_split(
    const float* __restrict__ in, __nv_bfloat16* __restrict__ hi,
    __nv_bfloat16* __restrict__ lo, int n)
{
    int i = (blockIdx.x * 256 + threadIdx.x) * 4;
    if (i >= n) return;
    float4 v = *(const float4*)(in + i);
    __nv_bfloat16 hx = __float2bfloat16_rn(v.x);
    __nv_bfloat16 hy = __float2bfloat16_rn(v.y);
    __nv_bfloat16 hz = __float2bfloat16_rn(v.z);
    __nv_bfloat16 hw = __float2bfloat16_rn(v.w);
    __nv_bfloat162 h01, h23, l01, l23;
    h01.x = hx; h01.y = hy; h23.x = hz; h23.y = hw;
    l01.x = __float2bfloat16_rn(v.x - __bfloat162float(hx));
    l01.y = __float2bfloat16_rn(v.y - __bfloat162float(hy));
    l23.x = __float2bfloat16_rn(v.z - __bfloat162float(hz));
    l23.y = __float2bfloat16_rn(v.w - __bfloat162float(hw));
    *(__nv_bfloat162*)(hi + i)     = h01;
    *(__nv_bfloat162*)(hi + i + 2) = h23;
    *(__nv_bfloat162*)(lo + i)     = l01;
    *(__nv_bfloat162*)(lo + i + 2) = l23;
}

// ======================= tcgen05 helpers (feature-gated) =====================
#if GB_HAS_TC
__device__ __forceinline__ uint32_t smem_u32(const void* p) {
    uint32_t a;
    asm("{ .reg .u64 t; cvta.to.shared.u64 t, %1; cvt.u32.u64 %0, t; }"
        : "=r"(a) : "l"(p));
    return a;
}
__device__ __forceinline__ uint32_t elect_one() {
    uint32_t pred;
    asm volatile("{\n\t.reg .pred p;\n\telect.sync _|p, 0xFFFFFFFF;\n\t"
                 "selp.b32 %0, 1, 0, p;\n\t}" : "=r"(pred));
    return pred;
}
#define MBAR_INIT(addr, cnt) \
    asm volatile("mbarrier.init.shared.b64 [%0], %1;" :: "r"(addr), "r"(cnt) : "memory")
#define MBAR_INVAL(addr) \
    asm volatile("mbarrier.inval.shared.b64 [%0];" :: "r"(addr) : "memory")
#define MBAR_WAIT(addr, par) do {                                              \
    uint32_t _m = (addr), _p = (par), _d;                                      \
    asm volatile("{\n\t.reg .pred p;\n\t"                                      \
        "mbarrier.try_wait.parity.acquire.cta.shared::cta.b64 p, [%1], %2;\n\t"\
        "selp.b32 %0, 1, 0, p;\n\t}" : "=r"(_d) : "r"(_m), "r"(_p) : "memory");\
    if (!_d) {                                                                 \
        asm volatile("{\n\t.reg .pred P1;\n\tWL_%=: \n\t"                      \
            "mbarrier.try_wait.parity.acquire.cta.shared::cta.b64 P1, [%0], %1, 0x989680;\n\t" \
            "@P1 bra.uni WD_%=;\n\tbra.uni WL_%=;\n\tWD_%=: \n\t}"            \
            :: "r"(_m), "r"(_p) : "memory");                                   \
    }                                                                          \
} while (0)
#define TC_ALLOC(slot, n) \
    asm volatile("tcgen05.alloc.cta_group::1.sync.aligned.shared::cta.b32 [%0], %1;" \
                 :: "r"(slot), "r"((uint32_t)(n)) : "memory")
#define TC_DEALLOC(tm, n) \
    asm volatile("tcgen05.dealloc.cta_group::1.sync.aligned.b32 %0, %1;" \
                 :: "r"(tm), "r"((uint32_t)(n)))
#define TC_COMMIT(mb) \
    asm volatile("tcgen05.commit.cta_group::1.mbarrier::arrive::one.shared::cluster.b64 [%0];" \
                 :: "r"(mb) : "memory")
#define TC_FENCE_AFTER()  asm volatile("tcgen05.fence::after_thread_sync;" ::: "memory")
#define TC_FENCE_BEFORE() asm volatile("tcgen05.fence::before_thread_sync;" ::: "memory")
#define TC_WAIT_LD() asm volatile("tcgen05.wait::ld.sync.aligned;" ::: "memory")
#define FENCE_ASYNC_SHARED() asm volatile("fence.proxy.async.shared::cta;" ::: "memory")
#define CP_COMMIT() asm volatile("cp.async.commit_group;" ::: "memory")
#define CP_WAIT(n)  asm volatile("cp.async.wait_group %0;" :: "n"(n) : "memory")
#define TC_LD_X32(r, tm)                                                       \
    asm volatile("tcgen05.ld.sync.aligned.32x32b.x32.b32 "                     \
        "{%0, %1, %2, %3, %4, %5, %6, %7, %8, %9, %10, %11, %12, %13, %14, %15, " \
        " %16, %17, %18, %19, %20, %21, %22, %23, %24, %25, %26, %27, %28, %29, %30, %31}, [%32];" \
        : "=r"((r)[0]),  "=r"((r)[1]),  "=r"((r)[2]),  "=r"((r)[3]),           \
          "=r"((r)[4]),  "=r"((r)[5]),  "=r"((r)[6]),  "=r"((r)[7]),           \
          "=r"((r)[8]),  "=r"((r)[9]),  "=r"((r)[10]), "=r"((r)[11]),          \
          "=r"((r)[12]), "=r"((r)[13]), "=r"((r)[14]), "=r"((r)[15]),          \
          "=r"((r)[16]), "=r"((r)[17]), "=r"((r)[18]), "=r"((r)[19]),          \
          "=r"((r)[20]), "=r"((r)[21]), "=r"((r)[22]), "=r"((r)[23]),          \
          "=r"((r)[24]), "=r"((r)[25]), "=r"((r)[26]), "=r"((r)[27]),          \
          "=r"((r)[28]), "=r"((r)[29]), "=r"((r)[30]), "=r"((r)[31])           \
        : "r"(tm))

static constexpr uint64_t SDESC_BASE_SW128 =
    (uint64_t(2) << 61) | (uint64_t(1) << 46) | (uint64_t(64) << 32) | (uint64_t(1) << 16);
#define MK_DESC(addr) (SDESC_BASE_SW128 | ((uint64_t)((addr) >> 4) & 0x3FFF))
#define SW128(off) ((off) ^ (((off) >> 3) & 0x70))

__device__ __forceinline__ void mma_f16_ss(uint32_t d_tmem, uint64_t a_desc,
                                           uint64_t b_desc, uint32_t idesc,
                                           uint32_t en) {
    asm volatile("{\n\t.reg .pred p;\n\tsetp.ne.u32 p, %5, 0;\n\t"
                 "tcgen05.mma.cta_group::1.kind::f16 [%0], %1, %2, %3, {%4, %4, %4, %4}, p;\n\t}"
                 :: "r"(d_tmem), "l"(a_desc), "l"(b_desc), "r"(idesc),
                    "r"(0u), "r"(en) : "memory");
}
__device__ __forceinline__ void cp16(uint32_t dst, const void* src) {
    asm volatile("cp.async.ca.shared.global [%0], [%1], 16;"
                 :: "r"(dst), "l"(src) : "memory");
}
#endif  // GB_HAS_TC

// ---------------- per-batch window size -------------------------------------
__global__ void wsz_kernel(const int* __restrict__ mask) {
    __shared__ int red[256];
    int b = blockIdx.x;
    int s = 0;
    for (int i = threadIdx.x; i < S_; i += 256) s += (mask[b * S_ + i] == 0);
    red[threadIdx.x] = s;
    __syncthreads();
    for (int o = 128; o > 0; o >>= 1) {
        if (threadIdx.x < o) red[threadIdx.x] += red[threadIdx.x + o];
        __syncthreads();
    }
    if (threadIdx.x == 0) {
        int len = red[0];
        if (len > 2048) len = 2048;
        float w = ceilf((float)len * 10.0f / 100.0f);
        w = fmaxf(w, 2.0f);
        g_w[b] = (int)w;
    }
}

// ================= GEMM: C = A @ Bw^T + bias =================================
#define GBM 128
#define GBN 128
#define GKC 64
#define GTILE (GBM * GKC * 2)         // 16 KB per bf16 tile
#define GSMEM (1024 + 8 * GTILE)      // pad + 2 stages * 4 tiles

#if GB_HAS_TC
static constexpr uint32_t G_IDESC =
    (1u << 4) | (1u << 7) | (1u << 10) | ((GBN / 8) << 17) | ((GBM / 16) << 24);

// async-copy one [128 x 64] bf16 tile (row = 128B) into SW128 smem
__device__ __forceinline__ void copy_tile(const __nv_bfloat16* __restrict__ g,
                                          int ldK, int kbase,
                                          uint32_t sm_tile, int tid) {
    const int row = tid >> 1;
    const int u0  = (tid & 1) * 4;               // 16B-unit start (0 or 4)
    const char* src = (const char*)(g + (size_t)row * ldK + kbase) + u0 * 16;
    #pragma unroll
    for (int j = 0; j < 4; ++j) {
        uint32_t off = SW128((uint32_t)(row * 128 + (u0 + j) * 16));
        cp16(sm_tile + off, src + j * 16);
    }
}
#endif

__global__ __launch_bounds__(256, 1) void gemm_tc(
    const float* __restrict__ A, const float* __restrict__ Bw,
    const __nv_bfloat16* __restrict__ Ah, const __nv_bfloat16* __restrict__ Al,
    const __nv_bfloat16* __restrict__ Bh, const __nv_bfloat16* __restrict__ Bl,
    const float* __restrict__ bias, float* __restrict__ C,
    int M, int N, int K)
{
    extern __shared__ char dsm[];
#if GB_HAS_TC
    // ---------------- tcgen05 bf16x3, cp.async-fed ----------------
    __shared__ uint32_t s_tmem[1];
    __shared__ uint64_t s_mbar[3];        // stage0, stage1, final

    const int tid = threadIdx.x;
    const int wid = tid >> 5;
    const int lane = tid & 31;
    const int m0 = blockIdx.y * GBM;
    const int n0 = blockIdx.x * GBN;

    const uint32_t raw  = smem_u32(dsm);
    const uint32_t base = (raw + 1023u) & ~1023u;

    const uint32_t mb0 = smem_u32(&s_mbar[0]);
    const uint32_t mb1 = smem_u32(&s_mbar[1]);
    const uint32_t mbF = smem_u32(&s_mbar[2]);
    const uint32_t slot = smem_u32(&s_tmem[0]);

    if (tid == 0) {
        MBAR_INIT(mb0, 1);
        MBAR_INIT(mb1, 1);
        MBAR_INIT(mbF, 1);
    }
    if (wid == 0) TC_ALLOC(slot, 128);
    __syncthreads();
    const uint32_t tmem = s_tmem[0];

    const __nv_bfloat16* Ahb = Ah + (size_t)m0 * K;
    const __nv_bfloat16* Alb = Al + (size_t)m0 * K;
    const __nv_bfloat16* Bhb = Bh + (size_t)n0 * K;
    const __nv_bfloat16* Blb = Bl + (size_t)n0 * K;

    const int NC = K / GKC;

    // prefetch chunk 0 into stage 0
    {
        const uint32_t st = base;
        copy_tile(Ahb, K, 0, st,             tid);
        copy_tile(Alb, K, 0, st + GTILE,     tid);
        copy_tile(Bhb, K, 0, st + 2 * GTILE, tid);
        copy_tile(Blb, K, 0, st + 3 * GTILE, tid);
        CP_COMMIT();
    }

    for (int c = 0; c < NC; ++c) {
        const int s = c & 1;
        // prefetch next chunk into the other stage (after its MMAs drained)
        if (c + 1 < NC) {
            const int s2 = (c + 1) & 1;
            const int u2 = (c + 1) >> 1;
            if (u2 >= 1) MBAR_WAIT(s2 ? mb1 : mb0, (u2 - 1) & 1);
            const uint32_t st = base + s2 * 4 * GTILE;
            const int kb = (c + 1) * GKC;
            copy_tile(Ahb, K, kb, st,             tid);
            copy_tile(Alb, K, kb, st + GTILE,     tid);
            copy_tile(Bhb, K, kb, st + 2 * GTILE, tid);
            copy_tile(Blb, K, kb, st + 3 * GTILE, tid);
            CP_COMMIT();
            CP_WAIT(1);                    // chunk c landed, c+1 in flight
        } else {
            CP_WAIT(0);
        }
        FENCE_ASYNC_SHARED();
        __syncthreads();

        if (wid == 0 && elect_one()) {
            const uint32_t sb = base + s * 4 * GTILE;
            const uint64_t dAh = MK_DESC(sb);
            const uint64_t dAl = MK_DESC(sb + GTILE);
            const uint64_t dBh = MK_DESC(sb + 2 * GTILE);
            const uint64_t dBl = MK_DESC(sb + 3 * GTILE);
            #pragma unroll
            for (int kk = 0; kk < 4; ++kk)
                mma_f16_ss(tmem, dAh + kk * 2, dBh + kk * 2, G_IDESC,
                           (c == 0 && kk == 0) ? 0u : 1u);
            #pragma unroll
            for (int kk = 0; kk < 4; ++kk)
                mma_f16_ss(tmem, dAh + kk * 2, dBl + kk * 2, G_IDESC, 1u);
            #pragma unroll
            for (int kk = 0; kk < 4; ++kk)
                mma_f16_ss(tmem, dAl + kk * 2, dBh + kk * 2, G_IDESC, 1u);
            TC_COMMIT(s ? mb1 : mb0);
            if (c == NC - 1) TC_COMMIT(mbF);
        }
    }

    MBAR_WAIT(mbF, 0);
    TC_FENCE_AFTER();

    if (wid < 4) {
        const int row = wid * 32 + lane;
        float* crow = C + (size_t)(m0 + row) * N + n0;
        #pragma unroll
        for (int bb = 0; bb < 4; ++bb) {
            uint32_t r[32];
            TC_LD_X32(r, tmem + bb * 32);
            TC_WAIT_LD();
            #pragma unroll
            for (int i = 0; i < 32; i += 4) {
                float4 o;
                o.x = __uint_as_float(r[i + 0]) + bias[n0 + bb * 32 + i + 0];
                o.y = __uint_as_float(r[i + 1]) + bias[n0 + bb * 32 + i + 1];
                o.z = __uint_as_float(r[i + 2]) + bias[n0 + bb * 32 + i + 2];
                o.w = __uint_as_float(r[i + 3]) + bias[n0 + bb * 32 + i + 3];
                *(float4*)(crow + bb * 32 + i) = o;
            }
        }
        TC_FENCE_BEFORE();
    }
    __syncthreads();
    if (tid == 0) { MBAR_INVAL(mb0); MBAR_INVAL(mb1); MBAR_INVAL(mbF); }
    if (wid == 0) TC_DEALLOC(tmem, 128);
#else
    // ---------------- FFMA fallback (proven SGEMM) ----------------
    float* As = (float*)dsm;
    float* Bs = As + 8 * 128;

    const int tid = threadIdx.x;
    const int blockRow = blockIdx.y;
    const int blockCol = blockIdx.x;

    const float* Ab = A  + (size_t)blockRow * 128 * K;
    const float* Bb = Bw + (size_t)blockCol * 128 * K;

    const int lr = tid >> 1;
    const int lc = (tid & 1) * 4;
    const int tr = (tid >> 4) * 8;
    const int tc = (tid & 15) * 8;

    float acc[8][8];
    #pragma unroll
    for (int i = 0; i < 8; ++i)
        #pragma unroll
        for (int j = 0; j < 8; ++j) acc[i][j] = 0.0f;

    for (int k0 = 0; k0 < K; k0 += 8) {
        float4 a4 = *(const float4*)(Ab + (size_t)lr * K + k0 + lc);
        float4 b4 = *(const float4*)(Bb + (size_t)lr * K + k0 + lc);
        As[(lc + 0) * 128 + lr] = a4.x; As[(lc + 1) * 128 + lr] = a4.y;
        As[(lc + 2) * 128 + lr] = a4.z; As[(lc + 3) * 128 + lr] = a4.w;
        Bs[(lc + 0) * 128 + lr] = b4.x; Bs[(lc + 1) * 128 + lr] = b4.y;
        Bs[(lc + 2) * 128 + lr] = b4.z; Bs[(lc + 3) * 128 + lr] = b4.w;
        __syncthreads();

        #pragma unroll
        for (int k = 0; k < 8; ++k) {
            float ra[8], rb[8];
            #pragma unroll
            for (int i = 0; i < 4; ++i) {
                float4 v = *(const float4*)(&As[k * 128 + tr + i * 4]);
                ra[i*4+0] = v.x; ra[i*4+1] = v.y; ra[i*4+2] = v.z; ra[i*4+3] = v.w;
            }
            #pragma unroll
            for (int j = 0; j < 4; ++j) {
                float4 v = *(const float4*)(&Bs[k * 128 + tc + j * 4]);
                rb[j*4+0] = v.x; rb[j*4+1] = v.y; rb[j*4+2] = v.z; rb[j*4+3] = v.w;
            }
            #pragma unroll
            for (int i = 0; i < 8; ++i)
                #pragma unroll
                for (int j = 0; j < 8; ++j)
                    acc[i][j] = fmaf(ra[i], rb[j], acc[i][j]);
        }
        __syncthreads();
    }

    const int grow = blockRow * 128 + tr;
    const int gcol = blockCol * 128 + tc;
    float bb[8];
    #pragma unroll
    for (int j = 0; j < 8; ++j) bb[j] = bias[gcol + j];
    #pragma unroll
    for (int i = 0; i < 8; ++i) {
        float4 o0, o1;
        o0.x = acc[i][0]+bb[0]; o0.y = acc[i][1]+bb[1];
        o0.z = acc[i][2]+bb[2]; o0.w = acc[i][3]+bb[3];
        o1.x = acc[i][4]+bb[4]; o1.y = acc[i][5]+bb[5];
        o1.z = acc[i][6]+bb[6]; o1.w = acc[i][7]+bb[7];
        float* cp = C + (size_t)(grow + i) * N + gcol;
        *(float4*)(cp)     = o0;
        *(float4*)(cp + 4) = o1;
    }
#endif
}

// ---------------- flash-style windowed attention (unchanged) ----------------
__global__ __launch_bounds__(256, 2) void attn_tile_kernel(
    const float* __restrict__ matrix_mask)
{
    extern __shared__ float sm[];
    float* Ls  = sm;
    float* Qs  = Ls  + TQ_ * LSTR_;
    float* KsT = Qs  + TQ_ * KSTR_;
    float* Vs  = KsT + TK_ * KSTR_;

    const int q0  = blockIdx.x * TQ_;
    const int h   = blockIdx.y;
    const int b   = blockIdx.z;
    const int tid = threadIdx.x;

    const int w    = g_w[b];
    const int jlo0 = max(q0 - w, 0);
    const int jhi0 = min(q0 + TQ_ - 1 + w, S_ - 1);
    const int WU   = jhi0 - jlo0 + 1;
    const int nchunks = (WU + TK_ - 1) / TK_;

    const float* qkvb = g_qkv + (size_t)b * S_ * QKV3_;

    for (int idx = tid; idx < TQ_ * 64; idx += 256) {
        int r = idx >> 6, d = idx & 63;
        Qs[r * KSTR_ + d] = qkvb[(size_t)(q0 + r) * QKV3_ + h * 192 + d];
    }

    const int r   = tid >> 3;
    const int c0  = (tid & 7) * 8;
    const int q   = q0 + r;
    const float scale = 0.125f;
    const float* mmrow = matrix_mask + ((size_t)b * S_ + q) * S_;

    for (int kc = 0; kc < nchunks; ++kc) {
        const int jbase = jlo0 + kc * TK_;
        __syncthreads();
        {
            int jj = tid >> 2;
            int d0 = (tid & 3) * 16;
            int jg = min(jbase + jj, S_ - 1);
            const float* kp = qkvb + (size_t)jg * QKV3_ + h * 192 + 64 + d0;
            #pragma unroll
            for (int i = 0; i < 16; i += 4) {
                float4 kk = *(const float4*)(kp + i);
                KsT[(d0 + i + 0) * KSTR_ + jj] = kk.x;
                KsT[(d0 + i + 1) * KSTR_ + jj] = kk.y;
                KsT[(d0 + i + 2) * KSTR_ + jj] = kk.z;
                KsT[(d0 + i + 3) * KSTR_ + jj] = kk.w;
            }
        }
        __syncthreads();

        float acc[8];
        #pragma unroll
        for (int i = 0; i < 8; ++i) acc[i] = 0.0f;

        #pragma unroll 4
        for (int d = 0; d < 64; ++d) {
            float qv = Qs[r * KSTR_ + d];
            float4 k0 = *(const float4*)(&KsT[d * KSTR_ + c0]);
            float4 k1 = *(const float4*)(&KsT[d * KSTR_ + c0 + 4]);
            acc[0] = fmaf(qv, k0.x, acc[0]); acc[1] = fmaf(qv, k0.y, acc[1]);
            acc[2] = fmaf(qv, k0.z, acc[2]); acc[3] = fmaf(qv, k0.w, acc[3]);
            acc[4] = fmaf(qv, k1.x, acc[4]); acc[5] = fmaf(qv, k1.y, acc[5]);
            acc[6] = fmaf(qv, k1.z, acc[6]); acc[7] = fmaf(qv, k1.w, acc[7]);
        }

        #pragma unroll
        for (int i = 0; i < 8; ++i) {
            int jgl = jbase + c0 + i;
            bool valid = (jgl <= jhi0) && (abs(jgl - q) <= w);
            float mval = valid ? mmrow[jgl] : -1e9f;
            Ls[r * LSTR_ + kc * TK_ + c0 + i] = acc[i] * scale + mval;
        }
    }
    __syncthreads();

    {
        const int warp = tid >> 5, lane = tid & 31;
        for (int rr = warp; rr < TQ_; rr += 8) {
            float* row = Ls + rr * LSTR_;
            float mx = -3.0e38f;
            for (int t = lane; t < WU; t += 32) mx = fmaxf(mx, row[t]);
            #pragma unroll
            for (int o = 16; o > 0; o >>= 1)
                mx = fmaxf(mx, __shfl_xor_sync(0xFFFFFFFFu, mx, o));
            float sum = 0.0f;
            for (int t = lane; t < WU; t += 32) {
                float e = __expf(row[t] - mx);
                row[t] = e;
                sum += e;
            }
            #pragma unroll
            for (int o = 16; o > 0; o >>= 1)
                sum += __shfl_xor_sync(0xFFFFFFFFu, sum, o);
            const float inv = 1.0f / sum;
            const int qq   = q0 + rr;
            const int jloq = max(qq - w, 0);
            const int jhiq = min(qq + w, S_ - 1);
            const int Wq   = jhiq - jloq + 1;
            const int off  = jloq - jlo0;
            float* prow = g_probs + (((size_t)(b * H_ + h) * S_) + qq) * PW_;
            for (int t = lane; t < WU; t += 32) row[t] *= inv;
            __syncwarp();
            for (int t = lane; t < Wq; t += 32) prow[t] = row[off + t];
        }
    }

    float o[8];
    #pragma unroll
    for (int i = 0; i < 8; ++i) o[i] = 0.0f;

    for (int kc = 0; kc < nchunks; ++kc) {
        const int jbase = jlo0 + kc * TK_;
        __syncthreads();
        {
            int jj = tid >> 2;
            int d0 = (tid & 3) * 16;
            int jg = min(jbase + jj, S_ - 1);
            const float* vp = qkvb + (size_t)jg * QKV3_ + h * 192 + 128 + d0;
            float4 v0 = *(const float4*)(vp);
            float4 v1 = *(const float4*)(vp + 4);
            float4 v2 = *(const float4*)(vp + 8);
            float4 v3 = *(const float4*)(vp + 12);
            *(float4*)(&Vs[jj * KSTR_ + d0])      = v0;
            *(float4*)(&Vs[jj * KSTR_ + d0 + 4])  = v1;
            *(float4*)(&Vs[jj * KSTR_ + d0 + 8])  = v2;
            *(float4*)(&Vs[jj * KSTR_ + d0 + 12]) = v3;
        }
        __syncthreads();

        const int nk = min(TK_, WU - kc * TK_);
        #pragma unroll 4
        for (int jj = 0; jj < nk; ++jj) {
            float p = Ls[r * LSTR_ + kc * TK_ + jj];
            float4 v0 = *(const float4*)(&Vs[jj * KSTR_ + c0]);
            float4 v1 = *(const float4*)(&Vs[jj * KSTR_ + c0 + 4]);
            o[0] = fmaf(p, v0.x, o[0]); o[1] = fmaf(p, v0.y, o[1]);
            o[2] = fmaf(p, v0.z, o[2]); o[3] = fmaf(p, v0.w, o[3]);
            o[4] = fmaf(p, v1.x, o[4]); o[5] = fmaf(p, v1.y, o[5]);
            o[6] = fmaf(p, v1.z, o[6]); o[7] = fmaf(p, v1.w, o[7]);
        }
    }

    float* op = g_vals + (size_t)(b * S_ + q) * E_ + h * 64 + c0;
    *(float4*)(op)     = make_float4(o[0], o[1], o[2], o[3]);
    *(float4*)(op + 4) = make_float4(o[4], o[5], o[6], o[7]);
}

// ---------------- attn_mean reduction (unchanged) ----------------------------
__global__ __launch_bounds__(256) void mean_kernel(float* __restrict__ out_attn) {
    const int bq = blockIdx.x;
    const int b  = bq >> 11;
    const int q  = bq & 2047;
    const int w  = g_w[b];
    const int jlo = max(q - w, 0);
    const int jhi = min(q + w, S_ - 1);

    float* arow = out_attn + (size_t)bq * S_;
    const float* pbase = g_probs + ((size_t)b * H_ * S_ + q) * PW_;

    for (int j = threadIdx.x; j < S_; j += 256) {
        float m = 0.0f;
        if (j >= jlo && j <= jhi) {
            int t = j - jlo;
            #pragma unroll
            for (int hh = 0; hh < H_; ++hh)
                m += pbase[(size_t)hh * S_ * PW_ + t];
            m *= (1.0f / 12.0f);
        }
        arow[j] = m;
    }
}

// ---------------- launch -----------------------------------------------------
extern "C" void kernel_launch(void* const* d_in, const int* in_sizes, int n_in,
                              void* d_out, int out_size) {
    const float* x      = (const float*)d_in[0];
    const int*   skpm   = (const int*)  d_in[1];
    const float* mmask  = (const float*)d_in[2];
    const float* qkv_w  = (const float*)d_in[3];
    const float* qkv_b  = (const float*)d_in[4];
    const float* o_w    = (const float*)d_in[5];
    const float* o_b    = (const float*)d_in[6];

    float* out      = (float*)d_out;
    float* out_o    = out;
    float* out_attn = out + (size_t)B_ * S_ * E_;

    float* qkv_ptr = nullptr;
    float* val_ptr = nullptr;
    __nv_bfloat16 *ah, *al, *wh, *wl;
    cudaGetSymbolAddress((void**)&qkv_ptr, g_qkv);
    cudaGetSymbolAddress((void**)&val_ptr, g_vals);
    cudaGetSymbolAddress((void**)&ah, g_a_hi);
    cudaGetSymbolAddress((void**)&al, g_a_lo);
    cudaGetSymbolAddress((void**)&wh, g_w_hi);
    cudaGetSymbolAddress((void**)&wl, g_w_lo);

    const int attn_smem = (TQ_ * LSTR_ + TQ_ * KSTR_ + 2 * TK_ * KSTR_) * 4;
    cudaFuncSetAttribute(attn_tile_kernel,
                         cudaFuncAttributeMaxDynamicSharedMemorySize, attn_smem);
    cudaFuncSetAttribute(gemm_tc,
                         cudaFuncAttributeMaxDynamicSharedMemorySize, GSMEM);

    // 1) per-batch window size
    wsz_kernel<<<B_, 256>>>(skpm);

    // 2) split x and qkv_w to bf16 hi/lo, then QKV projection
    cvt_split<<<NA_ / 1024, 256>>>(x, ah, al, NA_);
    cvt_split<<<NWQ_ / 1024, 256>>>(qkv_w, wh, wl, NWQ_);
    {
        dim3 grid(QKV3_ / GBN, (B_ * S_) / GBM);
        gemm_tc<<<grid, 256, GSMEM>>>(x, qkv_w, ah, al, wh, wl,
                                      qkv_b, qkv_ptr, B_ * S_, QKV3_, DIN_);
    }

    // 3) windowed attention
    {
        dim3 grid(S_ / TQ_, H_, B_);
        attn_tile_kernel<<<grid, 256, attn_smem>>>(mmask);
    }

    // 4) attn_mean reduction
    mean_kernel<<<B_ * S_, 256>>>(out_attn);

    // 5) split vals and o_w, then output projection
    cvt_split<<<NA_ / 1024, 256>>>(val_ptr, ah, al, B_ * S_ * E_);
    cvt_split<<<(E_ * E_) / 1024, 256>>>(o_w, wh, wl, E_ * E_);
    {
        dim3 grid(E_ / GBN, (B_ * S_) / GBM);
        gemm_tc<<<grid, 256, GSMEM>>>(val_ptr, o_w, ah, al, wh, wl,
                                      o_b, out_o, B_ * S_, E_, E_);
    }
}

// round 13
// speedup vs baseline: 3.7750x; 2.6071x over previous
#include <cuda_runtime.h>
#include <cuda_bf16.h>
#include <math.h>
#include <stdint.h>

#define B_    4
#define S_    2048
#define DIN_  768
#define E_    768
#define H_    12
#define HD_   64
#define QKV3_ 2304

#define NA_   (B_ * S_ * DIN_)
#define NWQ_  (QKV3_ * DIN_)

#define LSTRIDE_ 640     // logits scratch row stride (max union 538, 5x128)
#define PSTRIDE_ 576     // probs scratch row stride (9x64)

#if defined(__CUDA_ARCH_FEAT_SM103_ALL) || defined(__CUDA_ARCH_FEAT_SM100_ALL) || defined(__CUDA_ARCH_FEAT_SM101_ALL)
#define GB_HAS_TC 1
#else
#define GB_HAS_TC 0
#endif

// ---------------- scratch ----------------------------------------------------
__device__ float g_qkv[(size_t)B_ * S_ * QKV3_];
__device__ float g_vals[(size_t)B_ * S_ * E_];
__device__ int   g_w[B_];
__device__ __align__(256) __nv_bfloat16 g_a_hi[NA_];
__device__ __align__(256) __nv_bfloat16 g_a_lo[NA_];
__device__ __align__(256) __nv_bfloat16 g_w_hi[NWQ_];
__device__ __align__(256) __nv_bfloat16 g_w_lo[NWQ_];
// attention scratch
__device__ __align__(256) __nv_bfloat16 g_qh[(size_t)B_ * H_ * S_ * HD_];
__device__ __align__(256) __nv_bfloat16 g_ql[(size_t)B_ * H_ * S_ * HD_];
__device__ __align__(256) __nv_bfloat16 g_kh[(size_t)B_ * H_ * S_ * HD_];
__device__ __align__(256) __nv_bfloat16 g_kl[(size_t)B_ * H_ * S_ * HD_];
__device__ __align__(256) float g_logits[(size_t)B_ * H_ * 16 * 128 * LSTRIDE_];
__device__ __align__(256) __nv_bfloat16 g_p_hi[(size_t)B_ * H_ * 16 * 128 * PSTRIDE_];
__device__ __align__(256) __nv_bfloat16 g_p_lo[(size_t)B_ * H_ * 16 * 128 * PSTRIDE_];

// ---------------- fp32 -> bf16 hi/lo splitter --------------------------------
__global__ __launch_bounds__(256) void cvt_split(
    const float* __restrict__ in, __nv_bfloat16* __restrict__ hi,
    __nv_bfloat16* __restrict__ lo, int n)
{
    int i = (blockIdx.x * 256 + threadIdx.x) * 4;
    if (i >= n) return;
    float4 v = *(const float4*)(in + i);
    __nv_bfloat16 hx = __float2bfloat16_rn(v.x);
    __nv_bfloat16 hy = __float2bfloat16_rn(v.y);
    __nv_bfloat16 hz = __float2bfloat16_rn(v.z);
    __nv_bfloat16 hw = __float2bfloat16_rn(v.w);
    __nv_bfloat162 h01, h23, l01, l23;
    h01.x = hx; h01.y = hy; h23.x = hz; h23.y = hw;
    l01.x = __float2bfloat16_rn(v.x - __bfloat162float(hx));
    l01.y = __float2bfloat16_rn(v.y - __bfloat162float(hy));
    l23.x = __float2bfloat16_rn(v.z - __bfloat162float(hz));
    l23.y = __float2bfloat16_rn(v.w - __bfloat162float(hw));
    *(__nv_bfloat162*)(hi + i)     = h01;
    *(__nv_bfloat162*)(hi + i + 2) = h23;
    *(__nv_bfloat162*)(lo + i)     = l01;
    *(__nv_bfloat162*)(lo + i + 2) = l23;
}

// ---------------- split q/k from g_qkv into [b,h,s,64] bf16 hi/lo -------------
__global__ __launch_bounds__(256) void split_qk() {
    const int bq = blockIdx.x;
    const int b = bq >> 11, s = bq & 2047;
    const float* src = g_qkv + (size_t)bq * QKV3_;
    for (int e = threadIdx.x; e < 384; e += 256) {
        const int h = e >> 5, dp = e & 31, d = dp * 2;
        const size_t di = ((size_t)((b * H_ + h) * S_ + s) * 64 + d) >> 1;
        float q0 = src[h * 192 + d],      q1 = src[h * 192 + d + 1];
        float k0 = src[h * 192 + 64 + d], k1 = src[h * 192 + 64 + d + 1];
        __nv_bfloat162 qh2, ql2, kh2, kl2;
        qh2.x = __float2bfloat16_rn(q0); qh2.y = __float2bfloat16_rn(q1);
        ql2.x = __float2bfloat16_rn(q0 - __bfloat162float(qh2.x));
        ql2.y = __float2bfloat16_rn(q1 - __bfloat162float(qh2.y));
        kh2.x = __float2bfloat16_rn(k0); kh2.y = __float2bfloat16_rn(k1);
        kl2.x = __float2bfloat16_rn(k0 - __bfloat162float(kh2.x));
        kl2.y = __float2bfloat16_rn(k1 - __bfloat162float(kh2.y));
        ((__nv_bfloat162*)g_qh)[di] = qh2;
        ((__nv_bfloat162*)g_ql)[di] = ql2;
        ((__nv_bfloat162*)g_kh)[di] = kh2;
        ((__nv_bfloat162*)g_kl)[di] = kl2;
    }
}

// ======================= tcgen05 helpers (feature-gated) =====================
#if GB_HAS_TC
__device__ __forceinline__ uint32_t smem_u32(const void* p) {
    uint32_t a;
    asm("{ .reg .u64 t; cvta.to.shared.u64 t, %1; cvt.u32.u64 %0, t; }"
        : "=r"(a) : "l"(p));
    return a;
}
__device__ __forceinline__ uint32_t elect_one() {
    uint32_t pred;
    asm volatile("{\n\t.reg .pred p;\n\telect.sync _|p, 0xFFFFFFFF;\n\t"
                 "selp.b32 %0, 1, 0, p;\n\t}" : "=r"(pred));
    return pred;
}
#define MBAR_INIT(addr, cnt) \
    asm volatile("mbarrier.init.shared.b64 [%0], %1;" :: "r"(addr), "r"(cnt) : "memory")
#define MBAR_INVAL(addr) \
    asm volatile("mbarrier.inval.shared.b64 [%0];" :: "r"(addr) : "memory")
#define MBAR_WAIT(addr, par) do {                                              \
    uint32_t _m = (addr), _p = (par), _d;                                      \
    asm volatile("{\n\t.reg .pred p;\n\t"                                      \
        "mbarrier.try_wait.parity.acquire.cta.shared::cta.b64 p, [%1], %2;\n\t"\
        "selp.b32 %0, 1, 0, p;\n\t}" : "=r"(_d) : "r"(_m), "r"(_p) : "memory");\
    if (!_d) {                                                                 \
        asm volatile("{\n\t.reg .pred P1;\n\tWL_%=: \n\t"                      \
            "mbarrier.try_wait.parity.acquire.cta.shared::cta.b64 P1, [%0], %1, 0x989680;\n\t" \
            "@P1 bra.uni WD_%=;\n\tbra.uni WL_%=;\n\tWD_%=: \n\t}"            \
            :: "r"(_m), "r"(_p) : "memory");                                   \
    }                                                                          \
} while (0)
#define TC_ALLOC(slot, n) \
    asm volatile("tcgen05.alloc.cta_group::1.sync.aligned.shared::cta.b32 [%0], %1;" \
                 :: "r"(slot), "r"((uint32_t)(n)) : "memory")
#define TC_DEALLOC(tm, n) \
    asm volatile("tcgen05.dealloc.cta_group::1.sync.aligned.b32 %0, %1;" \
                 :: "r"(tm), "r"((uint32_t)(n)))
#define TC_COMMIT(mb) \
    asm volatile("tcgen05.commit.cta_group::1.mbarrier::arrive::one.shared::cluster.b64 [%0];" \
                 :: "r"(mb) : "memory")
#define TC_FENCE_AFTER()  asm volatile("tcgen05.fence::after_thread_sync;" ::: "memory")
#define TC_FENCE_BEFORE() asm volatile("tcgen05.fence::before_thread_sync;" ::: "memory")
#define TC_WAIT_LD() asm volatile("tcgen05.wait::ld.sync.aligned;" ::: "memory")
#define FENCE_ASYNC_SHARED() asm volatile("fence.proxy.async.shared::cta;" ::: "memory")
#define CP_COMMIT() asm volatile("cp.async.commit_group;" ::: "memory")
#define CP_WAIT(n)  asm volatile("cp.async.wait_group %0;" :: "n"(n) : "memory")
#define TC_LD_X32(r, tm)                                                       \
    asm volatile("tcgen05.ld.sync.aligned.32x32b.x32.b32 "                     \
        "{%0, %1, %2, %3, %4, %5, %6, %7, %8, %9, %10, %11, %12, %13, %14, %15, " \
        " %16, %17, %18, %19, %20, %21, %22, %23, %24, %25, %26, %27, %28, %29, %30, %31}, [%32];" \
        : "=r"((r)[0]),  "=r"((r)[1]),  "=r"((r)[2]),  "=r"((r)[3]),           \
          "=r"((r)[4]),  "=r"((r)[5]),  "=r"((r)[6]),  "=r"((r)[7]),           \
          "=r"((r)[8]),  "=r"((r)[9]),  "=r"((r)[10]), "=r"((r)[11]),          \
          "=r"((r)[12]), "=r"((r)[13]), "=r"((r)[14]), "=r"((r)[15]),          \
          "=r"((r)[16]), "=r"((r)[17]), "=r"((r)[18]), "=r"((r)[19]),          \
          "=r"((r)[20]), "=r"((r)[21]), "=r"((r)[22]), "=r"((r)[23]),          \
          "=r"((r)[24]), "=r"((r)[25]), "=r"((r)[26]), "=r"((r)[27]),          \
          "=r"((r)[28]), "=r"((r)[29]), "=r"((r)[30]), "=r"((r)[31])           \
        : "r"(tm))

static constexpr uint64_t SDESC_BASE_SW128 =
    (uint64_t(2) << 61) | (uint64_t(1) << 46) | (uint64_t(64) << 32) | (uint64_t(1) << 16);
#define MK_DESC(addr) (SDESC_BASE_SW128 | ((uint64_t)((addr) >> 4) & 0x3FFF))
#define SW128(off) ((off) ^ (((off) >> 3) & 0x70))

__device__ __forceinline__ void mma_f16_ss(uint32_t d_tmem, uint64_t a_desc,
                                           uint64_t b_desc, uint32_t idesc,
                                           uint32_t en) {
    asm volatile("{\n\t.reg .pred p;\n\tsetp.ne.u32 p, %5, 0;\n\t"
                 "tcgen05.mma.cta_group::1.kind::f16 [%0], %1, %2, %3, {%4, %4, %4, %4}, p;\n\t}"
                 :: "r"(d_tmem), "l"(a_desc), "l"(b_desc), "r"(idesc),
                    "r"(0u), "r"(en) : "memory");
}
__device__ __forceinline__ void cp16(uint32_t dst, const void* src) {
    asm volatile("cp.async.ca.shared.global [%0], [%1], 16;"
                 :: "r"(dst), "l"(src) : "memory");
}
#endif  // GB_HAS_TC

// ---------------- per-batch window size -------------------------------------
__global__ void wsz_kernel(const int* __restrict__ mask) {
    __shared__ int red[256];
    int b = blockIdx.x;
    int s = 0;
    for (int i = threadIdx.x; i < S_; i += 256) s += (mask[b * S_ + i] == 0);
    red[threadIdx.x] = s;
    __syncthreads();
    for (int o = 128; o > 0; o >>= 1) {
        if (threadIdx.x < o) red[threadIdx.x] += red[threadIdx.x + o];
        __syncthreads();
    }
    if (threadIdx.x == 0) {
        int len = red[0];
        if (len > 2048) len = 2048;
        float w = ceilf((float)len * 10.0f / 100.0f);
        w = fmaxf(w, 2.0f);
        g_w[b] = (int)w;
    }
}

// ================= dense GEMM: C = A @ Bw^T + bias (unchanged r10) ===========
#define GBM 128
#define GBN 128
#define GKC 64
#define GTILE (GBM * GKC * 2)
#define GSMEM (1024 + 8 * GTILE)

#if GB_HAS_TC
static constexpr uint32_t G_IDESC =
    (1u << 4) | (1u << 7) | (1u << 10) | ((GBN / 8) << 17) | ((GBM / 16) << 24);
static constexpr uint32_t PV_IDESC =
    (1u << 4) | (1u << 7) | (1u << 10) | ((64 / 8) << 17) | ((128 / 16) << 24);

__device__ __forceinline__ void copy_tile(const __nv_bfloat16* __restrict__ g,
                                          int ldK, int kbase,
                                          uint32_t sm_tile, int tid) {
    const int row = tid >> 1;
    const int u0  = (tid & 1) * 4;
    const char* src = (const char*)(g + (size_t)row * ldK + kbase) + u0 * 16;
    #pragma unroll
    for (int j = 0; j < 4; ++j) {
        uint32_t off = SW128((uint32_t)(row * 128 + (u0 + j) * 16));
        cp16(sm_tile + off, src + j * 16);
    }
}
#endif

__global__ __launch_bounds__(256, 1) void gemm_tc(
    const float* __restrict__ A, const float* __restrict__ Bw,
    const __nv_bfloat16* __restrict__ Ah, const __nv_bfloat16* __restrict__ Al,
    const __nv_bfloat16* __restrict__ Bh, const __nv_bfloat16* __restrict__ Bl,
    const float* __restrict__ bias, float* __restrict__ C,
    int M, int N, int K)
{
    extern __shared__ char dsm[];
#if GB_HAS_TC
    __shared__ uint32_t s_tmem[1];
    __shared__ uint64_t s_mbar[3];

    const int tid = threadIdx.x;
    const int wid = tid >> 5;
    const int lane = tid & 31;
    const int m0 = blockIdx.y * GBM;
    const int n0 = blockIdx.x * GBN;

    const uint32_t raw  = smem_u32(dsm);
    const uint32_t base = (raw + 1023u) & ~1023u;

    const uint32_t mb0 = smem_u32(&s_mbar[0]);
    const uint32_t mb1 = smem_u32(&s_mbar[1]);
    const uint32_t mbF = smem_u32(&s_mbar[2]);
    const uint32_t slot = smem_u32(&s_tmem[0]);

    if (tid == 0) { MBAR_INIT(mb0, 1); MBAR_INIT(mb1, 1); MBAR_INIT(mbF, 1); }
    if (wid == 0) TC_ALLOC(slot, 128);
    __syncthreads();
    const uint32_t tmem = s_tmem[0];

    const __nv_bfloat16* Ahb = Ah + (size_t)m0 * K;
    const __nv_bfloat16* Alb = Al + (size_t)m0 * K;
    const __nv_bfloat16* Bhb = Bh + (size_t)n0 * K;
    const __nv_bfloat16* Blb = Bl + (size_t)n0 * K;

    const int NC = K / GKC;
    {
        const uint32_t st = base;
        copy_tile(Ahb, K, 0, st,             tid);
        copy_tile(Alb, K, 0, st + GTILE,     tid);
        copy_tile(Bhb, K, 0, st + 2 * GTILE, tid);
        copy_tile(Blb, K, 0, st + 3 * GTILE, tid);
        CP_COMMIT();
    }

    for (int c = 0; c < NC; ++c) {
        const int s = c & 1;
        if (c + 1 < NC) {
            const int s2 = (c + 1) & 1;
            const int u2 = (c + 1) >> 1;
            if (u2 >= 1) MBAR_WAIT(s2 ? mb1 : mb0, (u2 - 1) & 1);
            const uint32_t st = base + s2 * 4 * GTILE;
            const int kb = (c + 1) * GKC;
            copy_tile(Ahb, K, kb, st,             tid);
            copy_tile(Alb, K, kb, st + GTILE,     tid);
            copy_tile(Bhb, K, kb, st + 2 * GTILE, tid);
            copy_tile(Blb, K, kb, st + 3 * GTILE, tid);
            CP_COMMIT();
            CP_WAIT(1);
        } else {
            CP_WAIT(0);
        }
        FENCE_ASYNC_SHARED();
        __syncthreads();

        if (wid == 0 && elect_one()) {
            const uint32_t sb = base + s * 4 * GTILE;
            const uint64_t dAh = MK_DESC(sb);
            const uint64_t dAl = MK_DESC(sb + GTILE);
            const uint64_t dBh = MK_DESC(sb + 2 * GTILE);
            const uint64_t dBl = MK_DESC(sb + 3 * GTILE);
            #pragma unroll
            for (int kk = 0; kk < 4; ++kk)
                mma_f16_ss(tmem, dAh + kk * 2, dBh + kk * 2, G_IDESC,
                           (c == 0 && kk == 0) ? 0u : 1u);
            #pragma unroll
            for (int kk = 0; kk < 4; ++kk)
                mma_f16_ss(tmem, dAh + kk * 2, dBl + kk * 2, G_IDESC, 1u);
            #pragma unroll
            for (int kk = 0; kk < 4; ++kk)
                mma_f16_ss(tmem, dAl + kk * 2, dBh + kk * 2, G_IDESC, 1u);
            TC_COMMIT(s ? mb1 : mb0);
            if (c == NC - 1) TC_COMMIT(mbF);
        }
    }

    MBAR_WAIT(mbF, 0);
    TC_FENCE_AFTER();

    if (wid < 4) {
        const int row = wid * 32 + lane;
        float* crow = C + (size_t)(m0 + row) * N + n0;
        #pragma unroll
        for (int bb = 0; bb < 4; ++bb) {
            uint32_t r[32];
            TC_LD_X32(r, tmem + bb * 32);
            TC_WAIT_LD();
            #pragma unroll
            for (int i = 0; i < 32; i += 4) {
                float4 o;
                o.x = __uint_as_float(r[i + 0]) + bias[n0 + bb * 32 + i + 0];
                o.y = __uint_as_float(r[i + 1]) + bias[n0 + bb * 32 + i + 1];
                o.z = __uint_as_float(r[i + 2]) + bias[n0 + bb * 32 + i + 2];
                o.w = __uint_as_float(r[i + 3]) + bias[n0 + bb * 32 + i + 3];
                *(float4*)(crow + bb * 32 + i) = o;
            }
        }
        TC_FENCE_BEFORE();
    }
    __syncthreads();
    if (tid == 0) { MBAR_INVAL(mb0); MBAR_INVAL(mb1); MBAR_INVAL(mbF); }
    if (wid == 0) TC_DEALLOC(tmem, 128);
#else
    float* As = (float*)dsm;
    float* Bs = As + 8 * 128;
    const int tid = threadIdx.x;
    const float* Ab = A  + (size_t)blockIdx.y * 128 * K;
    const float* Bb = Bw + (size_t)blockIdx.x * 128 * K;
    const int lr = tid >> 1, lc = (tid & 1) * 4;
    const int tr = (tid >> 4) * 8, tc = (tid & 15) * 8;
    float acc[8][8];
    #pragma unroll
    for (int i = 0; i < 8; ++i)
        #pragma unroll
        for (int j = 0; j < 8; ++j) acc[i][j] = 0.0f;
    for (int k0 = 0; k0 < K; k0 += 8) {
        float4 a4 = *(const float4*)(Ab + (size_t)lr * K + k0 + lc);
        float4 b4 = *(const float4*)(Bb + (size_t)lr * K + k0 + lc);
        As[(lc+0)*128+lr] = a4.x; As[(lc+1)*128+lr] = a4.y;
        As[(lc+2)*128+lr] = a4.z; As[(lc+3)*128+lr] = a4.w;
        Bs[(lc+0)*128+lr] = b4.x; Bs[(lc+1)*128+lr] = b4.y;
        Bs[(lc+2)*128+lr] = b4.z; Bs[(lc+3)*128+lr] = b4.w;
        __syncthreads();
        #pragma unroll
        for (int k = 0; k < 8; ++k) {
            float ra[8], rb[8];
            #pragma unroll
            for (int i = 0; i < 8; ++i) ra[i] = As[k*128+tr+i];
            #pragma unroll
            for (int j = 0; j < 8; ++j) rb[j] = Bs[k*128+tc+j];
            #pragma unroll
            for (int i = 0; i < 8; ++i)
                #pragma unroll
                for (int j = 0; j < 8; ++j)
                    acc[i][j] = fmaf(ra[i], rb[j], acc[i][j]);
        }
        __syncthreads();
    }
    const int grow = blockIdx.y * 128 + tr, gcol = blockIdx.x * 128 + tc;
    #pragma unroll
    for (int i = 0; i < 8; ++i)
        #pragma unroll
        for (int j = 0; j < 8; ++j)
            C[(size_t)(grow+i)*N + gcol+j] = acc[i][j] + bias[gcol+j];
#endif
}

// ================= qk_tc: banded QK^T on tensor cores =========================
#define QK_SMEM 99328   // 1024 pad + Qhi/lo 32K + K 2-stage hi/lo 64K
__global__ __launch_bounds__(256, 2) void qk_tc_kernel() {
    const int qt = blockIdx.x, h = blockIdx.y, b = blockIdx.z;
    const int tid = threadIdx.x, wid = tid >> 5, lane = tid & 31;
    const int q0 = qt * 128;
    const int w = g_w[b];
    const int jlo0 = max(q0 - w, 0);
    const int jhi0 = min(q0 + 127 + w, S_ - 1);
    const int WU = jhi0 - jlo0 + 1;
    const int NKC = (WU + 127) >> 7;
    const int bh = b * H_ + h;
    float* lbase = g_logits + (size_t)(bh * 16 + qt) * (128 * LSTRIDE_);
#if GB_HAS_TC
    extern __shared__ char dsm[];
    __shared__ uint32_t s_tmem[1];
    __shared__ uint64_t s_mbar[2];

    const uint32_t raw  = smem_u32(dsm);
    const uint32_t base = (raw + 1023u) & ~1023u;
    const uint32_t mb0 = smem_u32(&s_mbar[0]);
    const uint32_t mb1 = smem_u32(&s_mbar[1]);
    const uint32_t slot = smem_u32(&s_tmem[0]);

    if (tid == 0) { MBAR_INIT(mb0, 1); MBAR_INIT(mb1, 1); }
    if (wid == 0) TC_ALLOC(slot, 256);
    __syncthreads();
    const uint32_t tmem = s_tmem[0];

    const __nv_bfloat16* qh = g_qh + (size_t)bh * S_ * 64;
    const __nv_bfloat16* ql = g_ql + (size_t)bh * S_ * 64;
    const __nv_bfloat16* kh = g_kh + (size_t)bh * S_ * 64;
    const __nv_bfloat16* kl = g_kl + (size_t)bh * S_ * 64;

    const int row = tid >> 1, half = tid & 1;

    // stage Q tile + K chunk 0
    {
        const char* sqh = (const char*)(qh + (size_t)(q0 + row) * 64) + half * 64;
        const char* sql = (const char*)(ql + (size_t)(q0 + row) * 64) + half * 64;
        const int j0 = min(jlo0 + row, S_ - 1);
        const char* skh = (const char*)(kh + (size_t)j0 * 64) + half * 64;
        const char* skl = (const char*)(kl + (size_t)j0 * 64) + half * 64;
        #pragma unroll
        for (int i = 0; i < 4; ++i) {
            uint32_t off = SW128((uint32_t)(row * 128 + half * 64 + i * 16));
            cp16(base + off,          sqh + i * 16);
            cp16(base + 16384 + off,  sql + i * 16);
            cp16(base + 32768 + off,  skh + i * 16);
            cp16(base + 49152 + off,  skl + i * 16);
        }
        CP_COMMIT();
    }
    CP_WAIT(0); FENCE_ASYNC_SHARED(); __syncthreads();

    const uint64_t dQh = MK_DESC(base);
    const uint64_t dQl = MK_DESC(base + 16384);

    for (int c = 0; c < NKC; ++c) {
        const uint32_t reg = tmem + (uint32_t)(c & 1) * 128;
        const uint32_t kb  = base + 32768 + (uint32_t)(c & 1) * 32768;
        if (wid == 0 && elect_one()) {
            const uint64_t dKh = MK_DESC(kb);
            const uint64_t dKl = MK_DESC(kb + 16384);
            #pragma unroll
            for (int kk = 0; kk < 4; ++kk)
                mma_f16_ss(reg, dQh + kk * 2, dKh + kk * 2, G_IDESC, kk > 0 ? 1u : 0u);
            #pragma unroll
            for (int kk = 0; kk < 4; ++kk)
                mma_f16_ss(reg, dQh + kk * 2, dKl + kk * 2, G_IDESC, 1u);
            #pragma unroll
            for (int kk = 0; kk < 4; ++kk)
                mma_f16_ss(reg, dQl + kk * 2, dKh + kk * 2, G_IDESC, 1u);
            TC_COMMIT((c & 1) ? mb1 : mb0);
        }
        if (c + 1 < NKC) {
            const int j = min(jlo0 + (c + 1) * 128 + row, S_ - 1);
            const uint32_t kb2 = base + 32768 + (uint32_t)((c + 1) & 1) * 32768;
            const char* skh = (const char*)(kh + (size_t)j * 64) + half * 64;
            const char* skl = (const char*)(kl + (size_t)j * 64) + half * 64;
            #pragma unroll
            for (int i = 0; i < 4; ++i) {
                uint32_t off = SW128((uint32_t)(row * 128 + half * 64 + i * 16));
                cp16(kb2 + off,         skh + i * 16);
                cp16(kb2 + 16384 + off, skl + i * 16);
            }
            CP_COMMIT();
        }
        MBAR_WAIT((c & 1) ? mb1 : mb0, (c >> 1) & 1);
        TC_FENCE_AFTER();
        {
            const int rrow = (wid & 3) * 32 + lane;
            const int cb   = (wid >> 2) * 64;
            uint32_t r0[32], r1[32];
            TC_LD_X32(r0, reg + cb);
            TC_LD_X32(r1, reg + cb + 32);
            TC_WAIT_LD();
            float* dst = lbase + (size_t)rrow * LSTRIDE_ + c * 128 + cb;
            #pragma unroll
            for (int i = 0; i < 32; i += 4)
                *(float4*)(dst + i) = make_float4(
                    __uint_as_float(r0[i]),   __uint_as_float(r0[i+1]),
                    __uint_as_float(r0[i+2]), __uint_as_float(r0[i+3]));
            #pragma unroll
            for (int i = 0; i < 32; i += 4)
                *(float4*)(dst + 32 + i) = make_float4(
                    __uint_as_float(r1[i]),   __uint_as_float(r1[i+1]),
                    __uint_as_float(r1[i+2]), __uint_as_float(r1[i+3]));
            TC_FENCE_BEFORE();
        }
        if (c + 1 < NKC) { CP_WAIT(0); FENCE_ASYNC_SHARED(); }
        __syncthreads();
    }
    if (tid == 0) { MBAR_INVAL(mb0); MBAR_INVAL(mb1); }
    __syncthreads();
    if (wid == 0) TC_DEALLOC(tmem, 256);
#else
    // correctness-only fallback
    const int Wp = NKC * 128;
    const float* qkvb = g_qkv + (size_t)b * S_ * QKV3_;
    for (int t = tid; t < 128 * Wp; t += 256) {
        int rr = t / Wp, cc = t - rr * Wp;
        int j = min(jlo0 + cc, S_ - 1);
        const float* qp = qkvb + (size_t)(q0 + rr) * QKV3_ + h * 192;
        const float* kp = qkvb + (size_t)j * QKV3_ + h * 192 + 64;
        float acc = 0.0f;
        for (int d = 0; d < 64; ++d) acc += qp[d] * kp[d];
        lbase[(size_t)rr * LSTRIDE_ + cc] = acc;
    }
#endif
}

// ================= softmax + attn_mean + P split =============================
__global__ __launch_bounds__(384) void softmax_mean(
    const float* __restrict__ matrix_mask, float* __restrict__ out_attn)
{
    __shared__ float smMask[416];
    __shared__ float smP[12 * 416];

    const int bq = blockIdx.x;
    const int b = bq >> 11, q = bq & 2047;
    const int w = g_w[b];
    const int jloq = max(q - w, 0);
    const int jhiq = min(q + w, S_ - 1);
    const int Wq = jhiq - jloq + 1;
    const int qt = q >> 7, row = q & 127;
    const int jlo0 = max(qt * 128 - w, 0);
    const int jhi0 = min(qt * 128 + 127 + w, S_ - 1);
    const int WU = jhi0 - jlo0 + 1;
    const int NC = (WU + 63) >> 6;
    const int PWU = NC * 64;
    const int off = jloq - jlo0;
    const int tid = threadIdx.x, hh = tid >> 5, lane = tid & 31;

    for (int t = tid; t < Wq; t += 384)
        smMask[t] = matrix_mask[(size_t)bq * S_ + jloq + t];
    __syncthreads();

    {
        const float* lb = g_logits + (size_t)((b * H_ + hh) * 16 + qt) * (128 * LSTRIDE_)
                        + (size_t)row * LSTRIDE_ + off;
        float* P = smP + hh * 416;
        float mx = -3.0e38f;
        for (int t = lane; t < Wq; t += 32) {
            float v = lb[t] * 0.125f + smMask[t];
            P[t] = v;
            mx = fmaxf(mx, v);
        }
        #pragma unroll
        for (int o = 16; o > 0; o >>= 1)
            mx = fmaxf(mx, __shfl_xor_sync(0xFFFFFFFFu, mx, o));
        float sum = 0.0f;
        for (int t = lane; t < Wq; t += 32) {
            float e = __expf(P[t] - mx);
            P[t] = e;
            sum += e;
        }
        #pragma unroll
        for (int o = 16; o > 0; o >>= 1)
            sum += __shfl_xor_sync(0xFFFFFFFFu, sum, o);
        const float inv = 1.0f / sum;
        for (int t = lane; t < Wq; t += 32) P[t] *= inv;
        __syncwarp();

        __nv_bfloat16* ph = g_p_hi + (size_t)((b * H_ + hh) * 16 + qt) * (128 * PSTRIDE_)
                          + (size_t)row * PSTRIDE_;
        __nv_bfloat16* pl = g_p_lo + (size_t)((b * H_ + hh) * 16 + qt) * (128 * PSTRIDE_)
                          + (size_t)row * PSTRIDE_;
        for (int t = lane; t < PWU; t += 32) {
            float v = (t >= off && t < off + Wq) ? P[t - off] : 0.0f;
            __nv_bfloat16 hi = __float2bfloat16_rn(v);
            ph[t] = hi;
            pl[t] = __float2bfloat16_rn(v - __bfloat162float(hi));
        }
    }
    __syncthreads();

    float* arow = out_attn + (size_t)bq * S_;
    for (int j = tid; j < S_; j += 384) {
        float m = 0.0f;
        if (j >= jloq && j <= jhiq) {
            const int t = j - jloq;
            #pragma unroll
            for (int k = 0; k < H_; ++k) m += smP[k * 416 + t];
            m *= (1.0f / 12.0f);
        }
        arow[j] = m;
    }
}

// ================= pv_tc: P @ V on tensor cores ==============================
#define PV_SMEM 99328   // 1024 pad + P 2-stage hi/lo 64K + V^T 2-stage hi/lo 32K
__global__ __launch_bounds__(256, 2) void pv_tc_kernel() {
    const int qt = blockIdx.x, h = blockIdx.y, b = blockIdx.z;
    const int tid = threadIdx.x, wid = tid >> 5, lane = tid & 31;
    const int q0 = qt * 128;
    const int w = g_w[b];
    const int jlo0 = max(q0 - w, 0);
    const int jhi0 = min(q0 + 127 + w, S_ - 1);
    const int WU = jhi0 - jlo0 + 1;
    const int NC = (WU + 63) >> 6;
    const int bh = b * H_ + h;
    const size_t pbo = (size_t)(bh * 16 + qt) * (128 * PSTRIDE_);
#if GB_HAS_TC
    extern __shared__ char dsm[];
    __shared__ uint32_t s_tmem[1];
    __shared__ uint64_t s_mbar[3];

    const uint32_t raw  = smem_u32(dsm);
    const uint32_t base = (raw + 1023u) & ~1023u;
    char* sptr = dsm + (base - raw);
    const uint32_t mb0 = smem_u32(&s_mbar[0]);
    const uint32_t mb1 = smem_u32(&s_mbar[1]);
    const uint32_t mbF = smem_u32(&s_mbar[2]);
    const uint32_t slot = smem_u32(&s_tmem[0]);

    if (tid == 0) { MBAR_INIT(mb0, 1); MBAR_INIT(mb1, 1); MBAR_INIT(mbF, 1); }
    if (wid == 0) TC_ALLOC(slot, 128);
    __syncthreads();
    const uint32_t tmem = s_tmem[0];

    const int row = tid >> 1, half = tid & 1;
    const int vj = tid >> 2, vd0 = (tid & 3) * 16;

    // stage chunk 0: P via cp.async, V^T via convert+transpose stores
    {
        const char* sph = (const char*)(g_p_hi + pbo + (size_t)row * PSTRIDE_) + half * 64;
        const char* spl = (const char*)(g_p_lo + pbo + (size_t)row * PSTRIDE_) + half * 64;
        #pragma unroll
        for (int i = 0; i < 4; ++i) {
            uint32_t off = SW128((uint32_t)(row * 128 + half * 64 + i * 16));
            cp16(base + off,         sph + i * 16);
            cp16(base + 16384 + off, spl + i * 16);
        }
        CP_COMMIT();
        const int jg = min(jlo0 + vj, S_ - 1);
        const float* vp = g_qkv + (size_t)(b * S_ + jg) * QKV3_ + h * 192 + 128 + vd0;
        #pragma unroll
        for (int i = 0; i < 16; ++i) {
            float v = vp[i];
            __nv_bfloat16 hi = __float2bfloat16_rn(v);
            uint32_t off = SW128((uint32_t)((vd0 + i) * 128 + vj * 2));
            *(__nv_bfloat16*)(sptr + 65536 + off) = hi;
            *(__nv_bfloat16*)(sptr + 73728 + off) =
                __float2bfloat16_rn(v - __bfloat162float(hi));
        }
    }
    CP_WAIT(0); FENCE_ASYNC_SHARED(); __syncthreads();

    for (int c = 0; c < NC; ++c) {
        const uint32_t pb = base + (uint32_t)(c & 1) * 32768;
        const uint32_t vb = base + 65536 + (uint32_t)(c & 1) * 16384;
        if (wid == 0 && elect_one()) {
            const uint64_t dPh = MK_DESC(pb);
            const uint64_t dPl = MK_DESC(pb + 16384);
            const uint64_t dVh = MK_DESC(vb);
            const uint64_t dVl = MK_DESC(vb + 8192);
            #pragma unroll
            for (int kk = 0; kk < 4; ++kk)
                mma_f16_ss(tmem, dPh + kk * 2, dVh + kk * 2, PV_IDESC,
                           (c == 0 && kk == 0) ? 0u : 1u);
            #pragma unroll
            for (int kk = 0; kk < 4; ++kk)
                mma_f16_ss(tmem, dPh + kk * 2, dVl + kk * 2, PV_IDESC, 1u);
            #pragma unroll
            for (int kk = 0; kk < 4; ++kk)
                mma_f16_ss(tmem, dPl + kk * 2, dVh + kk * 2, PV_IDESC, 1u);
            TC_COMMIT((c & 1) ? mb1 : mb0);
            if (c == NC - 1) TC_COMMIT(mbF);
        }
        if (c + 1 < NC) {
            if (c + 1 >= 2)
                MBAR_WAIT(((c + 1) & 1) ? mb1 : mb0, ((c - 1) >> 1) & 1);
            const uint32_t pb2 = base + (uint32_t)((c + 1) & 1) * 32768;
            const uint32_t vb2o = 65536 + (uint32_t)((c + 1) & 1) * 16384;
            const char* sph = (const char*)(g_p_hi + pbo + (size_t)row * PSTRIDE_
                                            + (c + 1) * 64) + half * 64;
            const char* spl = (const char*)(g_p_lo + pbo + (size_t)row * PSTRIDE_
                                            + (c + 1) * 64) + half * 64;
            #pragma unroll
            for (int i = 0; i < 4; ++i) {
                uint32_t off = SW128((uint32_t)(row * 128 + half * 64 + i * 16));
                cp16(pb2 + off,         sph + i * 16);
                cp16(pb2 + 16384 + off, spl + i * 16);
            }
            CP_COMMIT();
            const int jg = min(jlo0 + (c + 1) * 64 + vj, S_ - 1);
            const float* vp = g_qkv + (size_t)(b * S_ + jg) * QKV3_ + h * 192 + 128 + vd0;
            #pragma unroll
            for (int i = 0; i < 16; ++i) {
                float v = vp[i];
                __nv_bfloat16 hi = __float2bfloat16_rn(v);
                uint32_t off = SW128((uint32_t)((vd0 + i) * 128 + vj * 2));
                *(__nv_bfloat16*)(sptr + vb2o + off) = hi;
                *(__nv_bfloat16*)(sptr + vb2o + 8192 + off) =
                    __float2bfloat16_rn(v - __bfloat162float(hi));
            }
            CP_WAIT(0); FENCE_ASYNC_SHARED();
        }
        __syncthreads();
    }

    MBAR_WAIT(mbF, 0);
    TC_FENCE_AFTER();
    {
        const int rrow = (wid & 3) * 32 + lane;
        const int cb   = (wid >> 2) * 32;
        uint32_t r[32];
        TC_LD_X32(r, tmem + cb);
        TC_WAIT_LD();
        TC_FENCE_BEFORE();
        float* dst = g_vals + (size_t)(b * S_ + q0 + rrow) * E_ + h * 64 + cb;
        #pragma unroll
        for (int i = 0; i < 32; i += 4)
            *(float4*)(dst + i) = make_float4(
                __uint_as_float(r[i]),   __uint_as_float(r[i+1]),
                __uint_as_float(r[i+2]), __uint_as_float(r[i+3]));
    }
    __syncthreads();
    if (tid == 0) { MBAR_INVAL(mb0); MBAR_INVAL(mb1); MBAR_INVAL(mbF); }
    if (wid == 0) TC_DEALLOC(tmem, 128);
#else
    const int PWU = NC * 64;
    for (int t = tid; t < 128 * 64; t += 256) {
        int rr = t >> 6, d = t & 63;
        float acc = 0.0f;
        for (int c = 0; c < PWU; ++c) {
            float p = __bfloat162float(g_p_hi[pbo + (size_t)rr * PSTRIDE_ + c])
                    + __bfloat162float(g_p_lo[pbo + (size_t)rr * PSTRIDE_ + c]);
            int j = min(jlo0 + c, S_ - 1);
            acc += p * g_qkv[(size_t)(b * S_ + j) * QKV3_ + h * 192 + 128 + d];
        }
        g_vals[(size_t)(b * S_ + q0 + rr) * E_ + h * 64 + d] = acc;
    }
#endif
}

// ---------------- launch -----------------------------------------------------
extern "C" void kernel_launch(void* const* d_in, const int* in_sizes, int n_in,
                              void* d_out, int out_size) {
    const float* x      = (const float*)d_in[0];
    const int*   skpm   = (const int*)  d_in[1];
    const float* mmask  = (const float*)d_in[2];
    const float* qkv_w  = (const float*)d_in[3];
    const float* qkv_b  = (const float*)d_in[4];
    const float* o_w    = (const float*)d_in[5];
    const float* o_b    = (const float*)d_in[6];

    float* out      = (float*)d_out;
    float* out_o    = out;
    float* out_attn = out + (size_t)B_ * S_ * E_;

    float* qkv_ptr = nullptr;
    float* val_ptr = nullptr;
    __nv_bfloat16 *ah, *al, *wh, *wl;
    cudaGetSymbolAddress((void**)&qkv_ptr, g_qkv);
    cudaGetSymbolAddress((void**)&val_ptr, g_vals);
    cudaGetSymbolAddress((void**)&ah, g_a_hi);
    cudaGetSymbolAddress((void**)&al, g_a_lo);
    cudaGetSymbolAddress((void**)&wh, g_w_hi);
    cudaGetSymbolAddress((void**)&wl, g_w_lo);

    cudaFuncSetAttribute(gemm_tc,
                         cudaFuncAttributeMaxDynamicSharedMemorySize, GSMEM);
    cudaFuncSetAttribute(qk_tc_kernel,
                         cudaFuncAttributeMaxDynamicSharedMemorySize, QK_SMEM);
    cudaFuncSetAttribute(pv_tc_kernel,
                         cudaFuncAttributeMaxDynamicSharedMemorySize, PV_SMEM);

    // 1) per-batch window size
    wsz_kernel<<<B_, 256>>>(skpm);

    // 2) QKV projection (tcgen05 bf16x3, cp.async-fed)
    cvt_split<<<NA_ / 1024, 256>>>(x, ah, al, NA_);
    cvt_split<<<NWQ_ / 1024, 256>>>(qkv_w, wh, wl, NWQ_);
    {
        dim3 grid(QKV3_ / GBN, (B_ * S_) / GBM);
        gemm_tc<<<grid, 256, GSMEM>>>(x, qkv_w, ah, al, wh, wl,
                                      qkv_b, qkv_ptr, B_ * S_, QKV3_, DIN_);
    }

    // 3) split Q/K to bf16 hi/lo in [b,h,s,64] layout
    split_qk<<<B_ * S_, 256>>>();

    // 4) banded QK^T on tensor cores -> logits scratch
    {
        dim3 grid(16, H_, B_);
        qk_tc_kernel<<<grid, 256, QK_SMEM>>>();
    }

    // 5) softmax + attn_mean + P hi/lo split
    softmax_mean<<<B_ * S_, 384>>>(mmask, out_attn);

    // 6) P @ V on tensor cores -> g_vals
    {
        dim3 grid(16, H_, B_);
        pv_tc_kernel<<<grid, 256, PV_SMEM>>>();
    }

    // 7) output projection (tcgen05 bf16x3)
    cvt_split<<<NA_ / 1024, 256>>>(val_ptr, ah, al, B_ * S_ * E_);
    cvt_split<<<(E_ * E_) / 1024, 256>>>(o_w, wh, wl, E_ * E_);
    {
        dim3 grid(E_ / GBN, (B_ * S_) / GBM);
        gemm_tc<<<grid, 256, GSMEM>>>(val_ptr, o_w, ah, al, wh, wl,
                                      o_b, out_o, B_ * S_, E_, E_);
    }
}

// round 15
// speedup vs baseline: 4.4880x; 1.1889x over previous
#include <cuda_runtime.h>
#include <cuda_bf16.h>
#include <math.h>
#include <stdint.h>

#define B_    4
#define S_    2048
#define DIN_  768
#define E_    768
#define H_    12
#define HD_   64
#define QKV3_ 2304

#define NA_   (B_ * S_ * DIN_)
#define NWQ_  (QKV3_ * DIN_)

#define LSTRIDE_ 768       // logits row stride: up to 6 aligned 128-key tiles
#define PQCH_    12        // max P chunks (64 keys) per q-tile window

#if defined(__CUDA_ARCH_FEAT_SM103_ALL) || defined(__CUDA_ARCH_FEAT_SM100_ALL) || defined(__CUDA_ARCH_FEAT_SM101_ALL)
#define GB_HAS_TC 1
#else
#define GB_HAS_TC 0
#endif

#define SW128(off) ((off) ^ (((off) >> 3) & 0x70))

__device__ __forceinline__ uint32_t pk_bf16(__nv_bfloat16 a, __nv_bfloat16 b) {
    return ((uint32_t)__bfloat16_as_ushort(b) << 16) | __bfloat16_as_ushort(a);
}

// ---------------- scratch ----------------------------------------------------
__device__ float g_qkv[(size_t)B_ * S_ * QKV3_];
__device__ float g_vals[(size_t)B_ * S_ * E_];
__device__ int   g_w[B_];
// dense-GEMM operand tile images (SW128-swizzled 16KB tiles)
__device__ __align__(256) __nv_bfloat16 g_a_hi[NA_];
__device__ __align__(256) __nv_bfloat16 g_a_lo[NA_];
__device__ __align__(256) __nv_bfloat16 g_w_hi[NWQ_];
__device__ __align__(256) __nv_bfloat16 g_w_lo[NWQ_];
// attention tile images
__device__ __align__(256) __nv_bfloat16 g_qh[(size_t)B_ * H_ * S_ * HD_];
__device__ __align__(256) __nv_bfloat16 g_ql[(size_t)B_ * H_ * S_ * HD_];
__device__ __align__(256) __nv_bfloat16 g_kh[(size_t)B_ * H_ * S_ * HD_];
__device__ __align__(256) __nv_bfloat16 g_kl[(size_t)B_ * H_ * S_ * HD_];
__device__ __align__(256) __nv_bfloat16 g_vth[(size_t)B_ * H_ * S_ * HD_];
__device__ __align__(256) __nv_bfloat16 g_vtl[(size_t)B_ * H_ * S_ * HD_];
__device__ __align__(256) float g_logits[(size_t)B_ * H_ * 16 * 128 * LSTRIDE_];
__device__ __align__(256) __nv_bfloat16 g_p_hi[(size_t)B_ * H_ * 16 * PQCH_ * 128 * 64];
__device__ __align__(256) __nv_bfloat16 g_p_lo[(size_t)B_ * H_ * 16 * PQCH_ * 128 * 64];

// ---------------- fp32 -> bf16 hi/lo, tiled+swizzled image -------------------
// in: [M, K] row-major fp32. out: tiles [mt][kc] of 16KB, SW128 image.
__global__ __launch_bounds__(256) void cvt_split_tiled(
    const float* __restrict__ in, __nv_bfloat16* __restrict__ hi,
    __nv_bfloat16* __restrict__ lo, int M, int K)
{
    const int gu = blockIdx.x * 256 + threadIdx.x;   // one 16B output unit
    const int upr = K >> 3;                          // units per row
    if (gu >= M * upr) return;
    const int m = gu / upr, ku = gu - m * upr;
    const float* p = in + (size_t)m * K + ku * 8;
    float4 v0 = *(const float4*)(p);
    float4 v1 = *(const float4*)(p + 4);
    float f[8] = {v0.x, v0.y, v0.z, v0.w, v1.x, v1.y, v1.z, v1.w};
    uint32_t hw[4], lw[4];
    #pragma unroll
    for (int i = 0; i < 4; ++i) {
        __nv_bfloat16 h0 = __float2bfloat16_rn(f[2*i]);
        __nv_bfloat16 h1 = __float2bfloat16_rn(f[2*i+1]);
        hw[i] = pk_bf16(h0, h1);
        lw[i] = pk_bf16(__float2bfloat16_rn(f[2*i]   - __bfloat162float(h0)),
                        __float2bfloat16_rn(f[2*i+1] - __bfloat162float(h1)));
    }
    const size_t tile = (size_t)(m >> 7) * (K >> 6) + (ku >> 3);
    const uint32_t off = SW128((uint32_t)((m & 127) * 128 + (ku & 7) * 16));
    *(uint4*)((char*)hi + tile * 16384 + off) = make_uint4(hw[0], hw[1], hw[2], hw[3]);
    *(uint4*)((char*)lo + tile * 16384 + off) = make_uint4(lw[0], lw[1], lw[2], lw[3]);
}

// ---------------- split Q/K into per-(bh, stile) swizzled images -------------
__global__ __launch_bounds__(256) void split_qk() {
    const int st = blockIdx.x, b = blockIdx.y;
    for (int t = threadIdx.x; t < 128 * 12 * 2 * 8; t += 256) {
        const int u = t & 7;
        int r = t >> 3;
        const int h = r % 12; r /= 12;
        const int qk = r & 1;
        const int sl = r >> 1;
        const float* p = g_qkv + ((size_t)(b * S_) + st * 128 + sl) * QKV3_
                       + h * 192 + qk * 64 + u * 8;
        float4 v0 = *(const float4*)(p);
        float4 v1 = *(const float4*)(p + 4);
        float f[8] = {v0.x, v0.y, v0.z, v0.w, v1.x, v1.y, v1.z, v1.w};
        uint32_t hw[4], lw[4];
        #pragma unroll
        for (int i = 0; i < 4; ++i) {
            __nv_bfloat16 h0 = __float2bfloat16_rn(f[2*i]);
            __nv_bfloat16 h1 = __float2bfloat16_rn(f[2*i+1]);
            hw[i] = pk_bf16(h0, h1);
            lw[i] = pk_bf16(__float2bfloat16_rn(f[2*i]   - __bfloat162float(h0)),
                            __float2bfloat16_rn(f[2*i+1] - __bfloat162float(h1)));
        }
        const size_t img = ((size_t)(b * H_ + h) * 16 + st) * 16384;
        const uint32_t off = SW128((uint32_t)(sl * 128 + u * 16));
        char* dh = (char*)(qk ? g_kh : g_qh) + img + off;
        char* dl = (char*)(qk ? g_kl : g_ql) + img + off;
        *(uint4*)dh = make_uint4(hw[0], hw[1], hw[2], hw[3]);
        *(uint4*)dl = make_uint4(lw[0], lw[1], lw[2], lw[3]);
    }
}

// ---------------- split V transposed into per-(bh, 64-key chunk) images ------
// image: [64 d rows][64 keys] bf16, 128B rows, SW128 -> 8KB each
__global__ __launch_bounds__(256) void split_v() {
    __shared__ float sm[64 * 68];
    const int ch = blockIdx.x, b = blockIdx.y;
    for (int h = 0; h < H_; ++h) {
        for (int idx = threadIdx.x; idx < 64 * 64; idx += 256) {
            const int sl = idx >> 6, d = idx & 63;
            sm[sl * 68 + d] = g_qkv[((size_t)(b * S_) + ch * 64 + sl) * QKV3_
                                    + h * 192 + 128 + d];
        }
        __syncthreads();
        const size_t img = ((size_t)(b * H_ + h) * 32 + ch) * 8192;
        for (int task = threadIdx.x; task < 64 * 8; task += 256) {
            const int d = task >> 3, su = task & 7;
            uint32_t hw[4], lw[4];
            #pragma unroll
            for (int i = 0; i < 4; ++i) {
                float f0 = sm[(su * 8 + 2*i)     * 68 + d];
                float f1 = sm[(su * 8 + 2*i + 1) * 68 + d];
                __nv_bfloat16 h0 = __float2bfloat16_rn(f0);
                __nv_bfloat16 h1 = __float2bfloat16_rn(f1);
                hw[i] = pk_bf16(h0, h1);
                lw[i] = pk_bf16(__float2bfloat16_rn(f0 - __bfloat162float(h0)),
                                __float2bfloat16_rn(f1 - __bfloat162float(h1)));
            }
            const uint32_t off = SW128((uint32_t)(d * 128 + su * 16));
            *(uint4*)((char*)g_vth + img + off) = make_uint4(hw[0], hw[1], hw[2], hw[3]);
            *(uint4*)((char*)g_vtl + img + off) = make_uint4(lw[0], lw[1], lw[2], lw[3]);
        }
        __syncthreads();
    }
}

// ======================= tcgen05 helpers (feature-gated) =====================
#if GB_HAS_TC
__device__ __forceinline__ uint32_t smem_u32(const void* p) {
    uint32_t a;
    asm("{ .reg .u64 t; cvta.to.shared.u64 t, %1; cvt.u32.u64 %0, t; }"
        : "=r"(a) : "l"(p));
    return a;
}
__device__ __forceinline__ uint32_t elect_one() {
    uint32_t pred;
    asm volatile("{\n\t.reg .pred p;\n\telect.sync _|p, 0xFFFFFFFF;\n\t"
                 "selp.b32 %0, 1, 0, p;\n\t}" : "=r"(pred));
    return pred;
}
#define MBAR_INIT(addr, cnt) \
    asm volatile("mbarrier.init.shared.b64 [%0], %1;" :: "r"(addr), "r"(cnt) : "memory")
#define MBAR_INVAL(addr) \
    asm volatile("mbarrier.inval.shared.b64 [%0];" :: "r"(addr) : "memory")
#define MBAR_EXPECT(addr, bytes) \
    asm volatile("mbarrier.arrive.expect_tx.shared.b64 _, [%0], %1;" \
                 :: "r"(addr), "r"((uint32_t)(bytes)) : "memory")
#define MBAR_WAIT(addr, par) do {                                              \
    uint32_t _m = (addr), _p = (par), _d;                                      \
    asm volatile("{\n\t.reg .pred p;\n\t"                                      \
        "mbarrier.try_wait.parity.acquire.cta.shared::cta.b64 p, [%1], %2;\n\t"\
        "selp.b32 %0, 1, 0, p;\n\t}" : "=r"(_d) : "r"(_m), "r"(_p) : "memory");\
    if (!_d) {                                                                 \
        asm volatile("{\n\t.reg .pred P1;\n\tWL_%=: \n\t"                      \
            "mbarrier.try_wait.parity.acquire.cta.shared::cta.b64 P1, [%0], %1, 0x989680;\n\t" \
            "@P1 bra.uni WD_%=;\n\tbra.uni WL_%=;\n\tWD_%=: \n\t}"            \
            :: "r"(_m), "r"(_p) : "memory");                                   \
    }                                                                          \
} while (0)
#define TC_ALLOC(slot, n) \
    asm volatile("tcgen05.alloc.cta_group::1.sync.aligned.shared::cta.b32 [%0], %1;" \
                 :: "r"(slot), "r"((uint32_t)(n)) : "memory")
#define TC_DEALLOC(tm, n) \
    asm volatile("tcgen05.dealloc.cta_group::1.sync.aligned.b32 %0, %1;" \
                 :: "r"(tm), "r"((uint32_t)(n)))
#define TC_COMMIT(mb) \
    asm volatile("tcgen05.commit.cta_group::1.mbarrier::arrive::one.shared::cluster.b64 [%0];" \
                 :: "r"(mb) : "memory")
#define TC_FENCE_AFTER()  asm volatile("tcgen05.fence::after_thread_sync;" ::: "memory")
#define TC_FENCE_BEFORE() asm volatile("tcgen05.fence::before_thread_sync;" ::: "memory")
#define TC_WAIT_LD() asm volatile("tcgen05.wait::ld.sync.aligned;" ::: "memory")
#define TC_LD_X32(r, tm)                                                       \
    asm volatile("tcgen05.ld.sync.aligned.32x32b.x32.b32 "                     \
        "{%0, %1, %2, %3, %4, %5, %6, %7, %8, %9, %10, %11, %12, %13, %14, %15, " \
        " %16, %17, %18, %19, %20, %21, %22, %23, %24, %25, %26, %27, %28, %29, %30, %31}, [%32];" \
        : "=r"((r)[0]),  "=r"((r)[1]),  "=r"((r)[2]),  "=r"((r)[3]),           \
          "=r"((r)[4]),  "=r"((r)[5]),  "=r"((r)[6]),  "=r"((r)[7]),           \
          "=r"((r)[8]),  "=r"((r)[9]),  "=r"((r)[10]), "=r"((r)[11]),          \
          "=r"((r)[12]), "=r"((r)[13]), "=r"((r)[14]), "=r"((r)[15]),          \
          "=r"((r)[16]), "=r"((r)[17]), "=r"((r)[18]), "=r"((r)[19]),          \
          "=r"((r)[20]), "=r"((r)[21]), "=r"((r)[22]), "=r"((r)[23]),          \
          "=r"((r)[24]), "=r"((r)[25]), "=r"((r)[26]), "=r"((r)[27]),          \
          "=r"((r)[28]), "=r"((r)[29]), "=r"((r)[30]), "=r"((r)[31])           \
        : "r"(tm))

static constexpr uint64_t SDESC_BASE_SW128 =
    (uint64_t(2) << 61) | (uint64_t(1) << 46) | (uint64_t(64) << 32) | (uint64_t(1) << 16);
#define MK_DESC(addr) (SDESC_BASE_SW128 | ((uint64_t)((addr) >> 4) & 0x3FFF))

__device__ __forceinline__ void mma_f16_ss(uint32_t d_tmem, uint64_t a_desc,
                                           uint64_t b_desc, uint32_t idesc,
                                           uint32_t en) {
    asm volatile("{\n\t.reg .pred p;\n\tsetp.ne.u32 p, %5, 0;\n\t"
                 "tcgen05.mma.cta_group::1.kind::f16 [%0], %1, %2, %3, {%4, %4, %4, %4}, p;\n\t}"
                 :: "r"(d_tmem), "l"(a_desc), "l"(b_desc), "r"(idesc),
                    "r"(0u), "r"(en) : "memory");
}
// bulk G2S copy completing on an mbarrier (expect_tx-tracked)
__device__ __forceinline__ void cp_bulk(uint32_t dst, const void* src,
                                        uint32_t bytes, uint32_t mbar) {
    asm volatile(
        "cp.async.bulk.shared::cluster.global.mbarrier::complete_tx::bytes "
        "[%0], [%1], %2, [%3];"
        :: "r"(dst), "l"(src), "r"(bytes), "r"(mbar) : "memory");
}
#endif  // GB_HAS_TC

// ---------------- per-batch window size -------------------------------------
__global__ void wsz_kernel(const int* __restrict__ mask) {
    __shared__ int red[256];
    int b = blockIdx.x;
    int s = 0;
    for (int i = threadIdx.x; i < S_; i += 256) s += (mask[b * S_ + i] == 0);
    red[threadIdx.x] = s;
    __syncthreads();
    for (int o = 128; o > 0; o >>= 1) {
        if (threadIdx.x < o) red[threadIdx.x] += red[threadIdx.x + o];
        __syncthreads();
    }
    if (threadIdx.x == 0) {
        int len = red[0];
        if (len > 2048) len = 2048;
        float w = ceilf((float)len * 10.0f / 100.0f);
        w = fmaxf(w, 2.0f);
        g_w[b] = (int)w;
    }
}

// ================= dense GEMM: C = A @ Bw^T + bias, bulk-fed =================
#define GBM 128
#define GBN 128
#define GKC 64
#define GTILE 16384
#define GSMEM (1024 + 8 * GTILE)

#if GB_HAS_TC
static constexpr uint32_t G_IDESC =
    (1u << 4) | (1u << 7) | (1u << 10) | ((GBN / 8) << 17) | ((GBM / 16) << 24);
static constexpr uint32_t PV_IDESC =
    (1u << 4) | (1u << 7) | (1u << 10) | ((64 / 8) << 17) | ((128 / 16) << 24);
#endif

__global__ __launch_bounds__(256, 1) void gemm_tc(
    const float* __restrict__ A, const float* __restrict__ Bw,
    const __nv_bfloat16* __restrict__ Ah, const __nv_bfloat16* __restrict__ Al,
    const __nv_bfloat16* __restrict__ Bh, const __nv_bfloat16* __restrict__ Bl,
    const float* __restrict__ bias, float* __restrict__ C,
    int M, int N, int K)
{
    extern __shared__ char dsm[];
#if GB_HAS_TC
    __shared__ uint32_t s_tmem[1];
    __shared__ uint64_t s_mbar[5];    // full0, full1, empty0, empty1, final

    const int tid = threadIdx.x;
    const int wid = tid >> 5;
    const int lane = tid & 31;
    const int m0 = blockIdx.y * GBM;
    const int n0 = blockIdx.x * GBN;

    const uint32_t raw  = smem_u32(dsm);
    const uint32_t base = (raw + 1023u) & ~1023u;

    const uint32_t fu0 = smem_u32(&s_mbar[0]);
    const uint32_t fu1 = smem_u32(&s_mbar[1]);
    const uint32_t em0 = smem_u32(&s_mbar[2]);
    const uint32_t em1 = smem_u32(&s_mbar[3]);
    const uint32_t mbF = smem_u32(&s_mbar[4]);
    const uint32_t slot = smem_u32(&s_tmem[0]);

    if (tid == 0) {
        MBAR_INIT(fu0, 1); MBAR_INIT(fu1, 1);
        MBAR_INIT(em0, 1); MBAR_INIT(em1, 1);
        MBAR_INIT(mbF, 1);
    }
    if (wid == 0) TC_ALLOC(slot, 128);
    __syncthreads();
    const uint32_t tmem = s_tmem[0];

    const int NC = K / GKC;
    const size_t at0 = (size_t)(m0 >> 7) * NC;    // A tile base index
    const size_t bt0 = (size_t)(n0 >> 7) * NC;

    if (wid == 0 && elect_one()) {
        // prefetch chunk 0 into stage 0
        MBAR_EXPECT(fu0, 4 * GTILE);
        cp_bulk(base,             (const char*)Ah + (at0 + 0) * GTILE, GTILE, fu0);
        cp_bulk(base + GTILE,     (const char*)Al + (at0 + 0) * GTILE, GTILE, fu0);
        cp_bulk(base + 2 * GTILE, (const char*)Bh + (bt0 + 0) * GTILE, GTILE, fu0);
        cp_bulk(base + 3 * GTILE, (const char*)Bl + (bt0 + 0) * GTILE, GTILE, fu0);

        for (int c = 0; c < NC; ++c) {
            const int s = c & 1;
            if (c + 1 < NC) {
                const int s2 = (c + 1) & 1;
                const uint32_t fu2 = s2 ? fu1 : fu0;
                if (c + 1 >= 2) MBAR_WAIT(s2 ? em1 : em0, (((c + 1) >> 1) - 1) & 1);
                const uint32_t st = base + s2 * 4 * GTILE;
                MBAR_EXPECT(fu2, 4 * GTILE);
                cp_bulk(st,             (const char*)Ah + (at0 + c + 1) * GTILE, GTILE, fu2);
                cp_bulk(st + GTILE,     (const char*)Al + (at0 + c + 1) * GTILE, GTILE, fu2);
                cp_bulk(st + 2 * GTILE, (const char*)Bh + (bt0 + c + 1) * GTILE, GTILE, fu2);
                cp_bulk(st + 3 * GTILE, (const char*)Bl + (bt0 + c + 1) * GTILE, GTILE, fu2);
            }
            MBAR_WAIT(s ? fu1 : fu0, (c >> 1) & 1);
            const uint32_t sb = base + s * 4 * GTILE;
            const uint64_t dAh = MK_DESC(sb);
            const uint64_t dAl = MK_DESC(sb + GTILE);
            const uint64_t dBh = MK_DESC(sb + 2 * GTILE);
            const uint64_t dBl = MK_DESC(sb + 3 * GTILE);
            #pragma unroll
            for (int kk = 0; kk < 4; ++kk)
                mma_f16_ss(tmem, dAh + kk * 2, dBh + kk * 2, G_IDESC,
                           (c == 0 && kk == 0) ? 0u : 1u);
            #pragma unroll
            for (int kk = 0; kk < 4; ++kk)
                mma_f16_ss(tmem, dAh + kk * 2, dBl + kk * 2, G_IDESC, 1u);
            #pragma unroll
            for (int kk = 0; kk < 4; ++kk)
                mma_f16_ss(tmem, dAl + kk * 2, dBh + kk * 2, G_IDESC, 1u);
            TC_COMMIT(s ? em1 : em0);
            if (c == NC - 1) TC_COMMIT(mbF);
        }
    }

    MBAR_WAIT(mbF, 0);
    TC_FENCE_AFTER();

    if (wid < 4) {
        const int row = wid * 32 + lane;
        float* crow = C + (size_t)(m0 + row) * N + n0;
        #pragma unroll
        for (int bb = 0; bb < 4; ++bb) {
            uint32_t r[32];
            TC_LD_X32(r, tmem + bb * 32);
            TC_WAIT_LD();
            #pragma unroll
            for (int i = 0; i < 32; i += 4) {
                float4 o;
                o.x = __uint_as_float(r[i + 0]) + bias[n0 + bb * 32 + i + 0];
                o.y = __uint_as_float(r[i + 1]) + bias[n0 + bb * 32 + i + 1];
                o.z = __uint_as_float(r[i + 2]) + bias[n0 + bb * 32 + i + 2];
                o.w = __uint_as_float(r[i + 3]) + bias[n0 + bb * 32 + i + 3];
                *(float4*)(crow + bb * 32 + i) = o;
            }
        }
        TC_FENCE_BEFORE();
    }
    __syncthreads();
    if (tid == 0)
        for (int i = 0; i < 5; ++i) MBAR_INVAL(smem_u32(&s_mbar[i]));
    if (wid == 0) TC_DEALLOC(tmem, 128);
#else
    float* As = (float*)dsm;
    float* Bs = As + 8 * 128;
    const int tid = threadIdx.x;
    const float* Ab = A  + (size_t)blockIdx.y * 128 * K;
    const float* Bb = Bw + (size_t)blockIdx.x * 128 * K;
    const int lr = tid >> 1, lc = (tid & 1) * 4;
    const int tr = (tid >> 4) * 8, tc = (tid & 15) * 8;
    float acc[8][8];
    #pragma unroll
    for (int i = 0; i < 8; ++i)
        #pragma unroll
        for (int j = 0; j < 8; ++j) acc[i][j] = 0.0f;
    for (int k0 = 0; k0 < K; k0 += 8) {
        float4 a4 = *(const float4*)(Ab + (size_t)lr * K + k0 + lc);
        float4 b4 = *(const float4*)(Bb + (size_t)lr * K + k0 + lc);
        As[(lc+0)*128+lr] = a4.x; As[(lc+1)*128+lr] = a4.y;
        As[(lc+2)*128+lr] = a4.z; As[(lc+3)*128+lr] = a4.w;
        Bs[(lc+0)*128+lr] = b4.x; Bs[(lc+1)*128+lr] = b4.y;
        Bs[(lc+2)*128+lr] = b4.z; Bs[(lc+3)*128+lr] = b4.w;
        __syncthreads();
        #pragma unroll
        for (int k = 0; k < 8; ++k) {
            float ra[8], rb[8];
            #pragma unroll
            for (int i = 0; i < 8; ++i) ra[i] = As[k*128+tr+i];
            #pragma unroll
            for (int j = 0; j < 8; ++j) rb[j] = Bs[k*128+tc+j];
            #pragma unroll
            for (int i = 0; i < 8; ++i)
                #pragma unroll
                for (int j = 0; j < 8; ++j)
                    acc[i][j] = fmaf(ra[i], rb[j], acc[i][j]);
        }
        __syncthreads();
    }
    const int grow = blockIdx.y * 128 + tr, gcol = blockIdx.x * 128 + tc;
    #pragma unroll
    for (int i = 0; i < 8; ++i)
        #pragma unroll
        for (int j = 0; j < 8; ++j)
            C[(size_t)(grow+i)*N + gcol+j] = acc[i][j] + bias[gcol+j];
#endif
}

// ================= qk_tc: banded QK^T, 128-aligned key tiles, bulk-fed =======
#define QK_SMEM 99328   // pad + Q hi/lo 32K + K 2-stage hi/lo 64K
__global__ __launch_bounds__(256, 2) void qk_tc_kernel() {
    const int qt = blockIdx.x, h = blockIdx.y, b = blockIdx.z;
    const int tid = threadIdx.x, wid = tid >> 5, lane = tid & 31;
    const int q0 = qt * 128;
    const int w = g_w[b];
    const int t0 = max(q0 - w, 0) >> 7;
    const int t1 = min(q0 + 127 + w, S_ - 1) >> 7;
    const int NKC = t1 - t0 + 1;                       // <= 6
    const int bh = b * H_ + h;
    float* lbase = g_logits + (size_t)(bh * 16 + qt) * (128 * LSTRIDE_);
#if GB_HAS_TC
    extern __shared__ char dsm[];
    __shared__ uint32_t s_tmem[1];
    __shared__ uint64_t s_mbar[4];    // full0, full1, commit0, commit1

    const uint32_t raw  = smem_u32(dsm);
    const uint32_t base = (raw + 1023u) & ~1023u;
    const uint32_t fu0 = smem_u32(&s_mbar[0]);
    const uint32_t fu1 = smem_u32(&s_mbar[1]);
    const uint32_t cm0 = smem_u32(&s_mbar[2]);
    const uint32_t cm1 = smem_u32(&s_mbar[3]);
    const uint32_t slot = smem_u32(&s_tmem[0]);

    if (tid == 0) {
        MBAR_INIT(fu0, 1); MBAR_INIT(fu1, 1);
        MBAR_INIT(cm0, 1); MBAR_INIT(cm1, 1);
    }
    if (wid == 0) TC_ALLOC(slot, 256);
    __syncthreads();
    const uint32_t tmem = s_tmem[0];

    const size_t qimg = ((size_t)bh * 16 + qt) * 16384;
    const size_t kimg0 = ((size_t)bh * 16 + t0) * 16384;

    if (wid == 0 && elect_one()) {
        MBAR_EXPECT(fu0, 65536);       // Q hi/lo + K0 hi/lo
        cp_bulk(base,         (const char*)g_qh + qimg, 16384, fu0);
        cp_bulk(base + 16384, (const char*)g_ql + qimg, 16384, fu0);
        cp_bulk(base + 32768, (const char*)g_kh + kimg0, 16384, fu0);
        cp_bulk(base + 49152, (const char*)g_kl + kimg0, 16384, fu0);
    }
    __syncthreads();

    const uint64_t dQh = MK_DESC(base);
    const uint64_t dQl = MK_DESC(base + 16384);

    for (int c = 0; c < NKC; ++c) {
        const uint32_t reg = tmem + (uint32_t)(c & 1) * 128;
        if (wid == 0 && elect_one()) {
            if (c + 1 < NKC) {
                const uint32_t fu2 = ((c + 1) & 1) ? fu1 : fu0;
                const uint32_t kb2 = base + 32768 + (uint32_t)((c + 1) & 1) * 32768;
                const size_t ki = ((size_t)bh * 16 + t0 + c + 1) * 16384;
                MBAR_EXPECT(fu2, 32768);
                cp_bulk(kb2,         (const char*)g_kh + ki, 16384, fu2);
                cp_bulk(kb2 + 16384, (const char*)g_kl + ki, 16384, fu2);
            }
            MBAR_WAIT((c & 1) ? fu1 : fu0, (c >> 1) & 1);
            const uint32_t kb = base + 32768 + (uint32_t)(c & 1) * 32768;
            const uint64_t dKh = MK_DESC(kb);
            const uint64_t dKl = MK_DESC(kb + 16384);
            #pragma unroll
            for (int kk = 0; kk < 4; ++kk)
                mma_f16_ss(reg, dQh + kk * 2, dKh + kk * 2, G_IDESC, kk > 0 ? 1u : 0u);
            #pragma unroll
            for (int kk = 0; kk < 4; ++kk)
                mma_f16_ss(reg, dQh + kk * 2, dKl + kk * 2, G_IDESC, 1u);
            #pragma unroll
            for (int kk = 0; kk < 4; ++kk)
                mma_f16_ss(reg, dQl + kk * 2, dKh + kk * 2, G_IDESC, 1u);
            TC_COMMIT((c & 1) ? cm1 : cm0);
        }
        MBAR_WAIT((c & 1) ? cm1 : cm0, (c >> 1) & 1);
        TC_FENCE_AFTER();
        {
            const int rrow = (wid & 3) * 32 + lane;
            const int cb   = (wid >> 2) * 64;
            uint32_t r0[32], r1[32];
            TC_LD_X32(r0, reg + cb);
            TC_LD_X32(r1, reg + cb + 32);
            TC_WAIT_LD();
            float* dst = lbase + (size_t)rrow * LSTRIDE_ + c * 128 + cb;
            #pragma unroll
            for (int i = 0; i < 32; i += 4)
                *(float4*)(dst + i) = make_float4(
                    __uint_as_float(r0[i]),   __uint_as_float(r0[i+1]),
                    __uint_as_float(r0[i+2]), __uint_as_float(r0[i+3]));
            #pragma unroll
            for (int i = 0; i < 32; i += 4)
                *(float4*)(dst + 32 + i) = make_float4(
                    __uint_as_float(r1[i]),   __uint_as_float(r1[i+1]),
                    __uint_as_float(r1[i+2]), __uint_as_float(r1[i+3]));
            TC_FENCE_BEFORE();
        }
        __syncthreads();
    }
    if (tid == 0)
        for (int i = 0; i < 4; ++i) MBAR_INVAL(smem_u32(&s_mbar[i]));
    __syncthreads();
    if (wid == 0) TC_DEALLOC(tmem, 256);
#else
    const int Wp = NKC * 128;
    const float* qkvb = g_qkv + (size_t)b * S_ * QKV3_;
    for (int t = tid; t < 128 * Wp; t += 256) {
        int rr = t / Wp, cc = t - rr * Wp;
        int j = min(t0 * 128 + cc, S_ - 1);
        const float* qp = qkvb + (size_t)(q0 + rr) * QKV3_ + h * 192;
        const float* kp = qkvb + (size_t)j * QKV3_ + h * 192 + 64;
        float acc = 0.0f;
        for (int d = 0; d < 64; ++d) acc += qp[d] * kp[d];
        lbase[(size_t)rr * LSTRIDE_ + cc] = acc;
    }
#endif
}

// ================= softmax + attn_mean + swizzled P-image write ==============
__global__ __launch_bounds__(384) void softmax_mean(
    const float* __restrict__ matrix_mask, float* __restrict__ out_attn)
{
    __shared__ float smMask[416];
    __shared__ float smP[12 * 416];

    const int bq = blockIdx.x;
    const int b = bq >> 11, q = bq & 2047;
    const int w = g_w[b];
    const int jloq = max(q - w, 0);
    const int jhiq = min(q + w, S_ - 1);
    const int Wq = jhiq - jloq + 1;
    const int qt = q >> 7, row = q & 127;
    const int q0 = qt * 128;
    const int t0 = max(q0 - w, 0) >> 7;
    const int t1 = min(q0 + 127 + w, S_ - 1) >> 7;
    const int PWU = (t1 - t0 + 1) * 128;
    const int off = jloq - t0 * 128;
    const int tid = threadIdx.x, hh = tid >> 5, lane = tid & 31;

    for (int t = tid; t < Wq; t += 384)
        smMask[t] = matrix_mask[(size_t)bq * S_ + jloq + t];
    __syncthreads();

    {
        const float* lb = g_logits
            + ((size_t)((b * H_ + hh) * 16 + qt) * 128 + row) * LSTRIDE_ + off;
        float* P = smP + hh * 416;
        float mx = -3.0e38f;
        for (int t = lane; t < Wq; t += 32) {
            float v = lb[t] * 0.125f + smMask[t];
            P[t] = v;
            mx = fmaxf(mx, v);
        }
        #pragma unroll
        for (int o = 16; o > 0; o >>= 1)
            mx = fmaxf(mx, __shfl_xor_sync(0xFFFFFFFFu, mx, o));
        float sum = 0.0f;
        for (int t = lane; t < Wq; t += 32) {
            float e = __expf(P[t] - mx);
            P[t] = e;
            sum += e;
        }
        #pragma unroll
        for (int o = 16; o > 0; o >>= 1)
            sum += __shfl_xor_sync(0xFFFFFFFFu, sum, o);
        const float inv = 1.0f / sum;
        for (int t = lane; t < Wq; t += 32) P[t] *= inv;
        __syncwarp();

        // write P image: [bh][qt][chunk 64][128 rows][64 cols], SW128 tiles
        char* ph = (char*)g_p_hi + (size_t)((b * H_ + hh) * 16 + qt) * (PQCH_ * 16384);
        char* pl = (char*)g_p_lo + (size_t)((b * H_ + hh) * 16 + qt) * (PQCH_ * 16384);
        for (int t = lane * 2; t < PWU; t += 64) {
            float v0 = (t     >= off && t     < off + Wq) ? P[t - off]     : 0.0f;
            float v1 = (t + 1 >= off && t + 1 < off + Wq) ? P[t + 1 - off] : 0.0f;
            __nv_bfloat16 h0 = __float2bfloat16_rn(v0);
            __nv_bfloat16 h1 = __float2bfloat16_rn(v1);
            const uint32_t o4 = (uint32_t)(t >> 6) * 16384
                              + SW128((uint32_t)(row * 128 + (t & 63) * 2));
            *(uint32_t*)(ph + o4) = pk_bf16(h0, h1);
            *(uint32_t*)(pl + o4) = pk_bf16(
                __float2bfloat16_rn(v0 - __bfloat162float(h0)),
                __float2bfloat16_rn(v1 - __bfloat162float(h1)));
        }
    }
    __syncthreads();

    float* arow = out_attn + (size_t)bq * S_;
    for (int j = tid; j < S_; j += 384) {
        float m = 0.0f;
        if (j >= jloq && j <= jhiq) {
            const int t = j - jloq;
            #pragma unroll
            for (int k = 0; k < H_; ++k) m += smP[k * 416 + t];
            m *= (1.0f / 12.0f);
        }
        arow[j] = m;
    }
}

// ================= pv_tc: P @ V, bulk-fed from images ========================
#define PV_SMEM 99328   // pad + P 2-stage hi/lo 64K + V 2-stage hi/lo 32K
__global__ __launch_bounds__(256, 2) void pv_tc_kernel() {
    const int qt = blockIdx.x, h = blockIdx.y, b = blockIdx.z;
    const int tid = threadIdx.x, wid = tid >> 5, lane = tid & 31;
    const int q0 = qt * 128;
    const int w = g_w[b];
    const int t0 = max(q0 - w, 0) >> 7;
    const int t1 = min(q0 + 127 + w, S_ - 1) >> 7;
    const int NC = (t1 - t0 + 1) * 2;                  // 64-key chunks, <= 12
    const int bh = b * H_ + h;
    const size_t pimg = (size_t)(bh * 16 + qt) * (PQCH_ * 16384);
#if GB_HAS_TC
    extern __shared__ char dsm[];
    __shared__ uint32_t s_tmem[1];
    __shared__ uint64_t s_mbar[5];    // full0, full1, empty0, empty1, final

    const uint32_t raw  = smem_u32(dsm);
    const uint32_t base = (raw + 1023u) & ~1023u;
    const uint32_t fu0 = smem_u32(&s_mbar[0]);
    const uint32_t fu1 = smem_u32(&s_mbar[1]);
    const uint32_t em0 = smem_u32(&s_mbar[2]);
    const uint32_t em1 = smem_u32(&s_mbar[3]);
    const uint32_t mbF = smem_u32(&s_mbar[4]);
    const uint32_t slot = smem_u32(&s_tmem[0]);

    if (tid == 0) {
        MBAR_INIT(fu0, 1); MBAR_INIT(fu1, 1);
        MBAR_INIT(em0, 1); MBAR_INIT(em1, 1);
        MBAR_INIT(mbF, 1);
    }
    if (wid == 0) TC_ALLOC(slot, 128);
    __syncthreads();
    const uint32_t tmem = s_tmem[0];

    if (wid == 0 && elect_one()) {
        {   // prefetch chunk 0
            const size_t vi = ((size_t)bh * 32 + t0 * 2) * 8192;
            MBAR_EXPECT(fu0, 49152);
            cp_bulk(base,          (const char*)g_p_hi + pimg, 16384, fu0);
            cp_bulk(base + 16384,  (const char*)g_p_lo + pimg, 16384, fu0);
            cp_bulk(base + 65536,  (const char*)g_vth + vi, 8192, fu0);
            cp_bulk(base + 73728,  (const char*)g_vtl + vi, 8192, fu0);
        }
        for (int c = 0; c < NC; ++c) {
            const int s = c & 1;
            if (c + 1 < NC) {
                const int s2 = (c + 1) & 1;
                const uint32_t fu2 = s2 ? fu1 : fu0;
                if (c + 1 >= 2) MBAR_WAIT(s2 ? em1 : em0, (((c + 1) >> 1) - 1) & 1);
                const uint32_t pb2 = base + (uint32_t)s2 * 32768;
                const uint32_t vb2 = base + 65536 + (uint32_t)s2 * 16384;
                const size_t vi = ((size_t)bh * 32 + t0 * 2 + c + 1) * 8192;
                MBAR_EXPECT(fu2, 49152);
                cp_bulk(pb2,         (const char*)g_p_hi + pimg + (c + 1) * 16384, 16384, fu2);
                cp_bulk(pb2 + 16384, (const char*)g_p_lo + pimg + (c + 1) * 16384, 16384, fu2);
                cp_bulk(vb2,        (const char*)g_vth + vi, 8192, fu2);
                cp_bulk(vb2 + 8192, (const char*)g_vtl + vi, 8192, fu2);
            }
            MBAR_WAIT(s ? fu1 : fu0, (c >> 1) & 1);
            const uint32_t pb = base + (uint32_t)s * 32768;
            const uint32_t vb = base + 65536 + (uint32_t)s * 16384;
            const uint64_t dPh = MK_DESC(pb);
            const uint64_t dPl = MK_DESC(pb + 16384);
            const uint64_t dVh = MK_DESC(vb);
            const uint64_t dVl = MK_DESC(vb + 8192);
            #pragma unroll
            for (int kk = 0; kk < 4; ++kk)
                mma_f16_ss(tmem, dPh + kk * 2, dVh + kk * 2, PV_IDESC,
                           (c == 0 && kk == 0) ? 0u : 1u);
            #pragma unroll
            for (int kk = 0; kk < 4; ++kk)
                mma_f16_ss(tmem, dPh + kk * 2, dVl + kk * 2, PV_IDESC, 1u);
            #pragma unroll
            for (int kk = 0; kk < 4; ++kk)
                mma_f16_ss(tmem, dPl + kk * 2, dVh + kk * 2, PV_IDESC, 1u);
            TC_COMMIT(s ? em1 : em0);
            if (c == NC - 1) TC_COMMIT(mbF);
        }
    }

    MBAR_WAIT(mbF, 0);
    TC_FENCE_AFTER();
    {
        const int rrow = (wid & 3) * 32 + lane;
        const int cb   = (wid >> 2) * 32;
        uint32_t r[32];
        TC_LD_X32(r, tmem + cb);
        TC_WAIT_LD();
        TC_FENCE_BEFORE();
        float* dst = g_vals + (size_t)(b * S_ + q0 + rrow) * E_ + h * 64 + cb;
        #pragma unroll
        for (int i = 0; i < 32; i += 4)
            *(float4*)(dst + i) = make_float4(
                __uint_as_float(r[i]),   __uint_as_float(r[i+1]),
                __uint_as_float(r[i+2]), __uint_as_float(r[i+3]));
    }
    __syncthreads();
    if (tid == 0)
        for (int i = 0; i < 5; ++i) MBAR_INVAL(smem_u32(&s_mbar[i]));
    if (wid == 0) TC_DEALLOC(tmem, 128);
#else
    const int PWU = NC * 64;
    for (int t = tid; t < 128 * 64; t += 256) {
        int rr = t >> 6, d = t & 63;
        float acc = 0.0f;
        for (int c = 0; c < PWU; ++c) {
            uint32_t o2 = (uint32_t)(c >> 6) * 16384
                        + SW128((uint32_t)(rr * 128 + (c & 63) * 2));
            float p = __bfloat162float(*(__nv_bfloat16*)((char*)g_p_hi + pimg + o2))
                    + __bfloat162float(*(__nv_bfloat16*)((char*)g_p_lo + pimg + o2));
            int j = min(t0 * 128 + c, S_ - 1);
            acc += p * g_qkv[(size_t)(b * S_ + j) * QKV3_ + h * 192 + 128 + d];
        }
        g_vals[(size_t)(b * S_ + q0 + rr) * E_ + h * 64 + d] = acc;
    }
#endif
}

// ---------------- launch -----------------------------------------------------
extern "C" void kernel_launch(void* const* d_in, const int* in_sizes, int n_in,
                              void* d_out, int out_size) {
    const float* x      = (const float*)d_in[0];
    const int*   skpm   = (const int*)  d_in[1];
    const float* mmask  = (const float*)d_in[2];
    const float* qkv_w  = (const float*)d_in[3];
    const float* qkv_b  = (const float*)d_in[4];
    const float* o_w    = (const float*)d_in[5];
    const float* o_b    = (const float*)d_in[6];

    float* out      = (float*)d_out;
    float* out_o    = out;
    float* out_attn = out + (size_t)B_ * S_ * E_;

    float* qkv_ptr = nullptr;
    float* val_ptr = nullptr;
    __nv_bfloat16 *ah, *al, *wh, *wl;
    cudaGetSymbolAddress((void**)&qkv_ptr, g_qkv);
    cudaGetSymbolAddress((void**)&val_ptr, g_vals);
    cudaGetSymbolAddress((void**)&ah, g_a_hi);
    cudaGetSymbolAddress((void**)&al, g_a_lo);
    cudaGetSymbolAddress((void**)&wh, g_w_hi);
    cudaGetSymbolAddress((void**)&wl, g_w_lo);

    cudaFuncSetAttribute(gemm_tc,
                         cudaFuncAttributeMaxDynamicSharedMemorySize, GSMEM);
    cudaFuncSetAttribute(qk_tc_kernel,
                         cudaFuncAttributeMaxDynamicSharedMemorySize, QK_SMEM);
    cudaFuncSetAttribute(pv_tc_kernel,
                         cudaFuncAttributeMaxDynamicSharedMemorySize, PV_SMEM);

    // 1) per-batch window size
    wsz_kernel<<<B_, 256>>>(skpm);

    // 2) QKV projection (tcgen05 bf16x3, bulk-fed from swizzled images)
    cvt_split_tiled<<<(NA_ / 8 + 255) / 256, 256>>>(x, ah, al, B_ * S_, DIN_);
    cvt_split_tiled<<<(NWQ_ / 8 + 255) / 256, 256>>>(qkv_w, wh, wl, QKV3_, DIN_);
    {
        dim3 grid(QKV3_ / GBN, (B_ * S_) / GBM);
        gemm_tc<<<grid, 256, GSMEM>>>(x, qkv_w, ah, al, wh, wl,
                                      qkv_b, qkv_ptr, B_ * S_, QKV3_, DIN_);
    }

    // 3) split Q/K (swizzled q-tile/key-tile images) and V^T (chunk images)
    {
        dim3 gq(16, B_);
        split_qk<<<gq, 256>>>();
        dim3 gv(32, B_);
        split_v<<<gv, 256>>>();
    }

    // 4) banded QK^T (aligned key tiles) -> logits scratch
    {
        dim3 grid(16, H_, B_);
        qk_tc_kernel<<<grid, 256, QK_SMEM>>>();
    }

    // 5) softmax + attn_mean + swizzled P-image write
    softmax_mean<<<B_ * S_, 384>>>(mmask, out_attn);

    // 6) P @ V -> g_vals
    {
        dim3 grid(16, H_, B_);
        pv_tc_kernel<<<grid, 256, PV_SMEM>>>();
    }

    // 7) output projection
    cvt_split_tiled<<<(NA_ / 8 + 255) / 256, 256>>>(val_ptr, ah, al, B_ * S_, E_);
    cvt_split_tiled<<<((E_ * E_) / 8 + 255) / 256, 256>>>(o_w, wh, wl, E_, E_);
    {
        dim3 grid(E_ / GBN, (B_ * S_) / GBM);
        gemm_tc<<<grid, 256, GSMEM>>>(val_ptr, o_w, ah, al, wh, wl,
                                      o_b, out_o, B_ * S_, E_, E_);
    }
}

// round 16
// speedup vs baseline: 4.9544x; 1.1039x over previous
#include <cuda_runtime.h>
#include <cuda_bf16.h>
#include <cuda_fp16.h>
#include <math.h>
#include <stdint.h>

#define B_    4
#define S_    2048
#define DIN_  768
#define E_    768
#define H_    12
#define HD_   64
#define QKV3_ 2304

#define NA_   (B_ * S_ * DIN_)
#define NWQ_  (QKV3_ * DIN_)

#define LSTRIDE_ 768       // logits row stride (fp16), up to 6 key tiles
#define PQCH_    12        // max P chunks (64 keys) per q-tile window

#if defined(__CUDA_ARCH_FEAT_SM103_ALL) || defined(__CUDA_ARCH_FEAT_SM100_ALL) || defined(__CUDA_ARCH_FEAT_SM101_ALL)
#define GB_HAS_TC 1
#else
#define GB_HAS_TC 0
#endif

#define SW128(off) ((off) ^ (((off) >> 3) & 0x70))

__device__ __forceinline__ uint32_t pk_bf16(__nv_bfloat16 a, __nv_bfloat16 b) {
    return ((uint32_t)__bfloat16_as_ushort(b) << 16) | __bfloat16_as_ushort(a);
}
__device__ __forceinline__ uint32_t pk_h2(float a, float b) {
    __half2 h = __floats2half2_rn(a, b);
    return *(uint32_t*)&h;
}
__device__ __forceinline__ uint32_t pk_half(__half a, __half b) {
    return ((uint32_t)__half_as_ushort(b) << 16) | __half_as_ushort(a);
}

// ---------------- scratch ----------------------------------------------------
__device__ float g_qkv[(size_t)B_ * S_ * QKV3_];
__device__ float g_vals[(size_t)B_ * S_ * E_];
__device__ int   g_w[B_];
// dense-GEMM operand tile images (SW128-swizzled 16KB tiles, bf16 hi/lo)
__device__ __align__(256) __nv_bfloat16 g_a_hi[NA_];
__device__ __align__(256) __nv_bfloat16 g_a_lo[NA_];
__device__ __align__(256) __nv_bfloat16 g_w_hi[NWQ_];
__device__ __align__(256) __nv_bfloat16 g_w_lo[NWQ_];
// attention tile images
__device__ __align__(256) __nv_bfloat16 g_qh[(size_t)B_ * H_ * S_ * HD_];
__device__ __align__(256) __nv_bfloat16 g_ql[(size_t)B_ * H_ * S_ * HD_];
__device__ __align__(256) __nv_bfloat16 g_kh[(size_t)B_ * H_ * S_ * HD_];
__device__ __align__(256) __nv_bfloat16 g_kl[(size_t)B_ * H_ * S_ * HD_];
__device__ __align__(256) __half g_vth[(size_t)B_ * H_ * S_ * HD_];   // fp16 V^T hi
__device__ __align__(256) __half g_vtl[(size_t)B_ * H_ * S_ * HD_];   // fp16 V^T lo
__device__ __align__(256) __half g_logits[(size_t)B_ * H_ * 16 * 128 * LSTRIDE_];
__device__ __align__(256) __half g_pf[(size_t)B_ * H_ * 16 * PQCH_ * 128 * 64];

// ---------------- fp32 -> bf16 hi/lo, tiled+swizzled image -------------------
__global__ __launch_bounds__(256) void cvt_split_tiled(
    const float* __restrict__ in, __nv_bfloat16* __restrict__ hi,
    __nv_bfloat16* __restrict__ lo, int M, int K)
{
    const int gu = blockIdx.x * 256 + threadIdx.x;
    const int upr = K >> 3;
    if (gu >= M * upr) return;
    const int m = gu / upr, ku = gu - m * upr;
    const float* p = in + (size_t)m * K + ku * 8;
    float4 v0 = *(const float4*)(p);
    float4 v1 = *(const float4*)(p + 4);
    float f[8] = {v0.x, v0.y, v0.z, v0.w, v1.x, v1.y, v1.z, v1.w};
    uint32_t hw[4], lw[4];
    #pragma unroll
    for (int i = 0; i < 4; ++i) {
        __nv_bfloat16 h0 = __float2bfloat16_rn(f[2*i]);
        __nv_bfloat16 h1 = __float2bfloat16_rn(f[2*i+1]);
        hw[i] = pk_bf16(h0, h1);
        lw[i] = pk_bf16(__float2bfloat16_rn(f[2*i]   - __bfloat162float(h0)),
                        __float2bfloat16_rn(f[2*i+1] - __bfloat162float(h1)));
    }
    const size_t tile = (size_t)(m >> 7) * (K >> 6) + (ku >> 3);
    const uint32_t off = SW128((uint32_t)((m & 127) * 128 + (ku & 7) * 16));
    *(uint4*)((char*)hi + tile * 16384 + off) = make_uint4(hw[0], hw[1], hw[2], hw[3]);
    *(uint4*)((char*)lo + tile * 16384 + off) = make_uint4(lw[0], lw[1], lw[2], lw[3]);
}

// ---------------- split Q/K into per-(bh, stile) swizzled images -------------
__global__ __launch_bounds__(256) void split_qk() {
    const int st = blockIdx.x, b = blockIdx.y;
    for (int t = threadIdx.x; t < 128 * 12 * 2 * 8; t += 256) {
        const int u = t & 7;
        int r = t >> 3;
        const int h = r % 12; r /= 12;
        const int qk = r & 1;
        const int sl = r >> 1;
        const float* p = g_qkv + ((size_t)(b * S_) + st * 128 + sl) * QKV3_
                       + h * 192 + qk * 64 + u * 8;
        float4 v0 = *(const float4*)(p);
        float4 v1 = *(const float4*)(p + 4);
        float f[8] = {v0.x, v0.y, v0.z, v0.w, v1.x, v1.y, v1.z, v1.w};
        uint32_t hw[4], lw[4];
        #pragma unroll
        for (int i = 0; i < 4; ++i) {
            __nv_bfloat16 h0 = __float2bfloat16_rn(f[2*i]);
            __nv_bfloat16 h1 = __float2bfloat16_rn(f[2*i+1]);
            hw[i] = pk_bf16(h0, h1);
            lw[i] = pk_bf16(__float2bfloat16_rn(f[2*i]   - __bfloat162float(h0)),
                            __float2bfloat16_rn(f[2*i+1] - __bfloat162float(h1)));
        }
        const size_t img = ((size_t)(b * H_ + h) * 16 + st) * 16384;
        const uint32_t off = SW128((uint32_t)(sl * 128 + u * 16));
        char* dh = (char*)(qk ? g_kh : g_qh) + img + off;
        char* dl = (char*)(qk ? g_kl : g_ql) + img + off;
        *(uint4*)dh = make_uint4(hw[0], hw[1], hw[2], hw[3]);
        *(uint4*)dl = make_uint4(lw[0], lw[1], lw[2], lw[3]);
    }
}

// ---------------- split V transposed into fp16 hi/lo chunk images ------------
// image: [64 d rows][64 keys] fp16, 128B rows, SW128 -> 8KB each
__global__ __launch_bounds__(256) void split_v() {
    __shared__ float sm[64 * 68];
    const int ch = blockIdx.x, b = blockIdx.y;
    for (int h = 0; h < H_; ++h) {
        for (int idx = threadIdx.x; idx < 64 * 64; idx += 256) {
            const int sl = idx >> 6, d = idx & 63;
            sm[sl * 68 + d] = g_qkv[((size_t)(b * S_) + ch * 64 + sl) * QKV3_
                                    + h * 192 + 128 + d];
        }
        __syncthreads();
        const size_t img = ((size_t)(b * H_ + h) * 32 + ch) * 8192;
        for (int task = threadIdx.x; task < 64 * 8; task += 256) {
            const int d = task >> 3, su = task & 7;
            uint32_t hw[4], lw[4];
            #pragma unroll
            for (int i = 0; i < 4; ++i) {
                float f0 = sm[(su * 8 + 2*i)     * 68 + d];
                float f1 = sm[(su * 8 + 2*i + 1) * 68 + d];
                __half h0 = __float2half_rn(f0);
                __half h1 = __float2half_rn(f1);
                hw[i] = pk_half(h0, h1);
                lw[i] = pk_half(__float2half_rn(f0 - __half2float(h0)),
                                __float2half_rn(f1 - __half2float(h1)));
            }
            const uint32_t off = SW128((uint32_t)(d * 128 + su * 16));
            *(uint4*)((char*)g_vth + img + off) = make_uint4(hw[0], hw[1], hw[2], hw[3]);
            *(uint4*)((char*)g_vtl + img + off) = make_uint4(lw[0], lw[1], lw[2], lw[3]);
        }
        __syncthreads();
    }
}

// ======================= tcgen05 helpers (feature-gated) =====================
#if GB_HAS_TC
__device__ __forceinline__ uint32_t smem_u32(const void* p) {
    uint32_t a;
    asm("{ .reg .u64 t; cvta.to.shared.u64 t, %1; cvt.u32.u64 %0, t; }"
        : "=r"(a) : "l"(p));
    return a;
}
__device__ __forceinline__ uint32_t elect_one() {
    uint32_t pred;
    asm volatile("{\n\t.reg .pred p;\n\telect.sync _|p, 0xFFFFFFFF;\n\t"
                 "selp.b32 %0, 1, 0, p;\n\t}" : "=r"(pred));
    return pred;
}
#define MBAR_INIT(addr, cnt) \
    asm volatile("mbarrier.init.shared.b64 [%0], %1;" :: "r"(addr), "r"(cnt) : "memory")
#define MBAR_INVAL(addr) \
    asm volatile("mbarrier.inval.shared.b64 [%0];" :: "r"(addr) : "memory")
#define MBAR_EXPECT(addr, bytes) \
    asm volatile("mbarrier.arrive.expect_tx.shared.b64 _, [%0], %1;" \
                 :: "r"(addr), "r"((uint32_t)(bytes)) : "memory")
#define MBAR_WAIT(addr, par) do {                                              \
    uint32_t _m = (addr), _p = (par), _d;                                      \
    asm volatile("{\n\t.reg .pred p;\n\t"                                      \
        "mbarrier.try_wait.parity.acquire.cta.shared::cta.b64 p, [%1], %2;\n\t"\
        "selp.b32 %0, 1, 0, p;\n\t}" : "=r"(_d) : "r"(_m), "r"(_p) : "memory");\
    if (!_d) {                                                                 \
        asm volatile("{\n\t.reg .pred P1;\n\tWL_%=: \n\t"                      \
            "mbarrier.try_wait.parity.acquire.cta.shared::cta.b64 P1, [%0], %1, 0x989680;\n\t" \
            "@P1 bra.uni WD_%=;\n\tbra.uni WL_%=;\n\tWD_%=: \n\t}"            \
            :: "r"(_m), "r"(_p) : "memory");                                   \
    }                                                                          \
} while (0)
#define TC_ALLOC(slot, n) \
    asm volatile("tcgen05.alloc.cta_group::1.sync.aligned.shared::cta.b32 [%0], %1;" \
                 :: "r"(slot), "r"((uint32_t)(n)) : "memory")
#define TC_DEALLOC(tm, n) \
    asm volatile("tcgen05.dealloc.cta_group::1.sync.aligned.b32 %0, %1;" \
                 :: "r"(tm), "r"((uint32_t)(n)))
#define TC_COMMIT(mb) \
    asm volatile("tcgen05.commit.cta_group::1.mbarrier::arrive::one.shared::cluster.b64 [%0];" \
                 :: "r"(mb) : "memory")
#define TC_FENCE_AFTER()  asm volatile("tcgen05.fence::after_thread_sync;" ::: "memory")
#define TC_FENCE_BEFORE() asm volatile("tcgen05.fence::before_thread_sync;" ::: "memory")
#define TC_WAIT_LD() asm volatile("tcgen05.wait::ld.sync.aligned;" ::: "memory")
#define TC_LD_X32(r, tm)                                                       \
    asm volatile("tcgen05.ld.sync.aligned.32x32b.x32.b32 "                     \
        "{%0, %1, %2, %3, %4, %5, %6, %7, %8, %9, %10, %11, %12, %13, %14, %15, " \
        " %16, %17, %18, %19, %20, %21, %22, %23, %24, %25, %26, %27, %28, %29, %30, %31}, [%32];" \
        : "=r"((r)[0]),  "=r"((r)[1]),  "=r"((r)[2]),  "=r"((r)[3]),           \
          "=r"((r)[4]),  "=r"((r)[5]),  "=r"((r)[6]),  "=r"((r)[7]),           \
          "=r"((r)[8]),  "=r"((r)[9]),  "=r"((r)[10]), "=r"((r)[11]),          \
          "=r"((r)[12]), "=r"((r)[13]), "=r"((r)[14]), "=r"((r)[15]),          \
          "=r"((r)[16]), "=r"((r)[17]), "=r"((r)[18]), "=r"((r)[19]),          \
          "=r"((r)[20]), "=r"((r)[21]), "=r"((r)[22]), "=r"((r)[23]),          \
          "=r"((r)[24]), "=r"((r)[25]), "=r"((r)[26]), "=r"((r)[27]),          \
          "=r"((r)[28]), "=r"((r)[29]), "=r"((r)[30]), "=r"((r)[31])           \
        : "r"(tm))

static constexpr uint64_t SDESC_BASE_SW128 =
    (uint64_t(2) << 61) | (uint64_t(1) << 46) | (uint64_t(64) << 32) | (uint64_t(1) << 16);
#define MK_DESC(addr) (SDESC_BASE_SW128 | ((uint64_t)((addr) >> 4) & 0x3FFF))

__device__ __forceinline__ void mma_f16_ss(uint32_t d_tmem, uint64_t a_desc,
                                           uint64_t b_desc, uint32_t idesc,
                                           uint32_t en) {
    asm volatile("{\n\t.reg .pred p;\n\tsetp.ne.u32 p, %5, 0;\n\t"
                 "tcgen05.mma.cta_group::1.kind::f16 [%0], %1, %2, %3, {%4, %4, %4, %4}, p;\n\t}"
                 :: "r"(d_tmem), "l"(a_desc), "l"(b_desc), "r"(idesc),
                    "r"(0u), "r"(en) : "memory");
}
__device__ __forceinline__ void cp_bulk(uint32_t dst, const void* src,
                                        uint32_t bytes, uint32_t mbar) {
    asm volatile(
        "cp.async.bulk.shared::cluster.global.mbarrier::complete_tx::bytes "
        "[%0], [%1], %2, [%3];"
        :: "r"(dst), "l"(src), "r"(bytes), "r"(mbar) : "memory");
}
#endif  // GB_HAS_TC

// ---------------- per-batch window size -------------------------------------
__global__ void wsz_kernel(const int* __restrict__ mask) {
    __shared__ int red[256];
    int b = blockIdx.x;
    int s = 0;
    for (int i = threadIdx.x; i < S_; i += 256) s += (mask[b * S_ + i] == 0);
    red[threadIdx.x] = s;
    __syncthreads();
    for (int o = 128; o > 0; o >>= 1) {
        if (threadIdx.x < o) red[threadIdx.x] += red[threadIdx.x + o];
        __syncthreads();
    }
    if (threadIdx.x == 0) {
        int len = red[0];
        if (len > 2048) len = 2048;
        float w = ceilf((float)len * 10.0f / 100.0f);
        w = fmaxf(w, 2.0f);
        g_w[b] = (int)w;
    }
}

// ================= dense GEMM: C = A @ Bw^T + bias, 128x256 tile =============
#define GBM 128
#define GBN 256
#define GKC 64
#define GTILE 16384
#define GSTAGE (6 * GTILE)                 // Ah, Al, Bh(2), Bl(2)
#define GSMEM (1024 + 2 * GSTAGE)          // 197632

#if GB_HAS_TC
static constexpr uint32_t IDESC_G =        // M=128, N=256, bf16
    (1u << 4) | (1u << 7) | (1u << 10) | ((GBN / 8) << 17) | ((GBM / 16) << 24);
static constexpr uint32_t IDESC_QK =       // M=128, N=128, bf16
    (1u << 4) | (1u << 7) | (1u << 10) | ((128 / 8) << 17) | ((128 / 16) << 24);
static constexpr uint32_t IDESC_PV =       // M=128, N=64, f16
    (1u << 4) | ((64 / 8) << 17) | ((128 / 16) << 24);
#endif

__global__ __launch_bounds__(256, 1) void gemm_tc(
    const float* __restrict__ A, const float* __restrict__ Bw,
    const __nv_bfloat16* __restrict__ Ah, const __nv_bfloat16* __restrict__ Al,
    const __nv_bfloat16* __restrict__ Bh, const __nv_bfloat16* __restrict__ Bl,
    const float* __restrict__ bias, float* __restrict__ C,
    int M, int N, int K)
{
    extern __shared__ char dsm[];
#if GB_HAS_TC
    __shared__ uint32_t s_tmem[1];
    __shared__ uint64_t s_mbar[5];

    const int tid = threadIdx.x;
    const int wid = tid >> 5;
    const int lane = tid & 31;
    const int m0 = blockIdx.y * GBM;
    const int n0 = blockIdx.x * GBN;

    const uint32_t raw  = smem_u32(dsm);
    const uint32_t base = (raw + 1023u) & ~1023u;

    const uint32_t fu0 = smem_u32(&s_mbar[0]);
    const uint32_t fu1 = smem_u32(&s_mbar[1]);
    const uint32_t em0 = smem_u32(&s_mbar[2]);
    const uint32_t em1 = smem_u32(&s_mbar[3]);
    const uint32_t mbF = smem_u32(&s_mbar[4]);
    const uint32_t slot = smem_u32(&s_tmem[0]);

    if (tid == 0) {
        MBAR_INIT(fu0, 1); MBAR_INIT(fu1, 1);
        MBAR_INIT(em0, 1); MBAR_INIT(em1, 1);
        MBAR_INIT(mbF, 1);
    }
    if (wid == 0) TC_ALLOC(slot, 256);
    __syncthreads();
    const uint32_t tmem = s_tmem[0];

    const int NC = K / GKC;
    const size_t at0  = (size_t)(m0 >> 7) * NC;
    const size_t bt0a = (size_t)(n0 >> 7) * NC;          // B rows 0-127
    const size_t bt0b = (size_t)((n0 >> 7) + 1) * NC;    // B rows 128-255

    if (wid == 0 && elect_one()) {
        {
            MBAR_EXPECT(fu0, GSTAGE);
            cp_bulk(base,             (const char*)Ah + at0  * GTILE, GTILE, fu0);
            cp_bulk(base + GTILE,     (const char*)Al + at0  * GTILE, GTILE, fu0);
            cp_bulk(base + 2 * GTILE, (const char*)Bh + bt0a * GTILE, GTILE, fu0);
            cp_bulk(base + 3 * GTILE, (const char*)Bh + bt0b * GTILE, GTILE, fu0);
            cp_bulk(base + 4 * GTILE, (const char*)Bl + bt0a * GTILE, GTILE, fu0);
            cp_bulk(base + 5 * GTILE, (const char*)Bl + bt0b * GTILE, GTILE, fu0);
        }
        for (int c = 0; c < NC; ++c) {
            const int s = c & 1;
            if (c + 1 < NC) {
                const int s2 = (c + 1) & 1;
                const uint32_t fu2 = s2 ? fu1 : fu0;
                if (c + 1 >= 2) MBAR_WAIT(s2 ? em1 : em0, (((c + 1) >> 1) - 1) & 1);
                const uint32_t st = base + s2 * GSTAGE;
                MBAR_EXPECT(fu2, GSTAGE);
                cp_bulk(st,             (const char*)Ah + (at0  + c + 1) * GTILE, GTILE, fu2);
                cp_bulk(st + GTILE,     (const char*)Al + (at0  + c + 1) * GTILE, GTILE, fu2);
                cp_bulk(st + 2 * GTILE, (const char*)Bh + (bt0a + c + 1) * GTILE, GTILE, fu2);
                cp_bulk(st + 3 * GTILE, (const char*)Bh + (bt0b + c + 1) * GTILE, GTILE, fu2);
                cp_bulk(st + 4 * GTILE, (const char*)Bl + (bt0a + c + 1) * GTILE, GTILE, fu2);
                cp_bulk(st + 5 * GTILE, (const char*)Bl + (bt0b + c + 1) * GTILE, GTILE, fu2);
            }
            MBAR_WAIT(s ? fu1 : fu0, (c >> 1) & 1);
            const uint32_t sb = base + s * GSTAGE;
            const uint64_t dAh = MK_DESC(sb);
            const uint64_t dAl = MK_DESC(sb + GTILE);
            const uint64_t dBh = MK_DESC(sb + 2 * GTILE);
            const uint64_t dBl = MK_DESC(sb + 4 * GTILE);
            #pragma unroll
            for (int kk = 0; kk < 4; ++kk)
                mma_f16_ss(tmem, dAh + kk * 2, dBh + kk * 2, IDESC_G,
                           (c == 0 && kk == 0) ? 0u : 1u);
            #pragma unroll
            for (int kk = 0; kk < 4; ++kk)
                mma_f16_ss(tmem, dAh + kk * 2, dBl + kk * 2, IDESC_G, 1u);
            #pragma unroll
            for (int kk = 0; kk < 4; ++kk)
                mma_f16_ss(tmem, dAl + kk * 2, dBh + kk * 2, IDESC_G, 1u);
            TC_COMMIT(s ? em1 : em0);
            if (c == NC - 1) TC_COMMIT(mbF);
        }
    }

    MBAR_WAIT(mbF, 0);
    TC_FENCE_AFTER();

    if (wid < 4) {
        const int row = wid * 32 + lane;
        float* crow = C + (size_t)(m0 + row) * N + n0;
        #pragma unroll
        for (int bb = 0; bb < 8; ++bb) {
            uint32_t r[32];
            TC_LD_X32(r, tmem + bb * 32);
            TC_WAIT_LD();
            #pragma unroll
            for (int i = 0; i < 32; i += 4) {
                float4 o;
                o.x = __uint_as_float(r[i + 0]) + bias[n0 + bb * 32 + i + 0];
                o.y = __uint_as_float(r[i + 1]) + bias[n0 + bb * 32 + i + 1];
                o.z = __uint_as_float(r[i + 2]) + bias[n0 + bb * 32 + i + 2];
                o.w = __uint_as_float(r[i + 3]) + bias[n0 + bb * 32 + i + 3];
                *(float4*)(crow + bb * 32 + i) = o;
            }
        }
        TC_FENCE_BEFORE();
    }
    __syncthreads();
    if (tid == 0)
        for (int i = 0; i < 5; ++i) MBAR_INVAL(smem_u32(&s_mbar[i]));
    if (wid == 0) TC_DEALLOC(tmem, 256);
#else
    float* As = (float*)dsm;
    float* Bs = As + 8 * 128;
    const int tid = threadIdx.x;
    const int lr = tid >> 1, lc = (tid & 1) * 4;
    const int tr = (tid >> 4) * 8, tc = (tid & 15) * 8;
    for (int nh = 0; nh < 2; ++nh) {
        const float* Ab = A  + (size_t)blockIdx.y * 128 * K;
        const float* Bb = Bw + ((size_t)blockIdx.x * 256 + nh * 128) * K;
        float acc[8][8];
        #pragma unroll
        for (int i = 0; i < 8; ++i)
            #pragma unroll
            for (int j = 0; j < 8; ++j) acc[i][j] = 0.0f;
        for (int k0 = 0; k0 < K; k0 += 8) {
            float4 a4 = *(const float4*)(Ab + (size_t)lr * K + k0 + lc);
            float4 b4 = *(const float4*)(Bb + (size_t)lr * K + k0 + lc);
            As[(lc+0)*128+lr] = a4.x; As[(lc+1)*128+lr] = a4.y;
            As[(lc+2)*128+lr] = a4.z; As[(lc+3)*128+lr] = a4.w;
            Bs[(lc+0)*128+lr] = b4.x; Bs[(lc+1)*128+lr] = b4.y;
            Bs[(lc+2)*128+lr] = b4.z; Bs[(lc+3)*128+lr] = b4.w;
            __syncthreads();
            #pragma unroll
            for (int k = 0; k < 8; ++k) {
                float ra[8], rb[8];
                #pragma unroll
                for (int i = 0; i < 8; ++i) ra[i] = As[k*128+tr+i];
                #pragma unroll
                for (int j = 0; j < 8; ++j) rb[j] = Bs[k*128+tc+j];
                #pragma unroll
                for (int i = 0; i < 8; ++i)
                    #pragma unroll
                    for (int j = 0; j < 8; ++j)
                        acc[i][j] = fmaf(ra[i], rb[j], acc[i][j]);
            }
            __syncthreads();
        }
        const int grow = blockIdx.y * 128 + tr;
        const int gcol = blockIdx.x * 256 + nh * 128 + tc;
        #pragma unroll
        for (int i = 0; i < 8; ++i)
            #pragma unroll
            for (int j = 0; j < 8; ++j)
                C[(size_t)(grow+i)*N + gcol+j] = acc[i][j] + bias[gcol+j];
        __syncthreads();
    }
#endif
}

// ================= qk_tc: banded QK^T, fp16 logits out =======================
#define QK_SMEM 99328
__global__ __launch_bounds__(256, 2) void qk_tc_kernel() {
    const int qt = blockIdx.x, h = blockIdx.y, b = blockIdx.z;
    const int tid = threadIdx.x, wid = tid >> 5, lane = tid & 31;
    const int q0 = qt * 128;
    const int w = g_w[b];
    const int t0 = max(q0 - w, 0) >> 7;
    const int t1 = min(q0 + 127 + w, S_ - 1) >> 7;
    const int NKC = t1 - t0 + 1;
    const int bh = b * H_ + h;
    __half* lbase = g_logits + (size_t)(bh * 16 + qt) * (128 * LSTRIDE_);
#if GB_HAS_TC
    extern __shared__ char dsm[];
    __shared__ uint32_t s_tmem[1];
    __shared__ uint64_t s_mbar[4];

    const uint32_t raw  = smem_u32(dsm);
    const uint32_t base = (raw + 1023u) & ~1023u;
    const uint32_t fu0 = smem_u32(&s_mbar[0]);
    const uint32_t fu1 = smem_u32(&s_mbar[1]);
    const uint32_t cm0 = smem_u32(&s_mbar[2]);
    const uint32_t cm1 = smem_u32(&s_mbar[3]);
    const uint32_t slot = smem_u32(&s_tmem[0]);

    if (tid == 0) {
        MBAR_INIT(fu0, 1); MBAR_INIT(fu1, 1);
        MBAR_INIT(cm0, 1); MBAR_INIT(cm1, 1);
    }
    if (wid == 0) TC_ALLOC(slot, 256);
    __syncthreads();
    const uint32_t tmem = s_tmem[0];

    const size_t qimg = ((size_t)bh * 16 + qt) * 16384;
    const size_t kimg0 = ((size_t)bh * 16 + t0) * 16384;

    if (wid == 0 && elect_one()) {
        MBAR_EXPECT(fu0, 65536);
        cp_bulk(base,         (const char*)g_qh + qimg, 16384, fu0);
        cp_bulk(base + 16384, (const char*)g_ql + qimg, 16384, fu0);
        cp_bulk(base + 32768, (const char*)g_kh + kimg0, 16384, fu0);
        cp_bulk(base + 49152, (const char*)g_kl + kimg0, 16384, fu0);
    }
    __syncthreads();

    const uint64_t dQh = MK_DESC(base);
    const uint64_t dQl = MK_DESC(base + 16384);

    for (int c = 0; c < NKC; ++c) {
        const uint32_t reg = tmem + (uint32_t)(c & 1) * 128;
        if (wid == 0 && elect_one()) {
            if (c + 1 < NKC) {
                const uint32_t fu2 = ((c + 1) & 1) ? fu1 : fu0;
                const uint32_t kb2 = base + 32768 + (uint32_t)((c + 1) & 1) * 32768;
                const size_t ki = ((size_t)bh * 16 + t0 + c + 1) * 16384;
                MBAR_EXPECT(fu2, 32768);
                cp_bulk(kb2,         (const char*)g_kh + ki, 16384, fu2);
                cp_bulk(kb2 + 16384, (const char*)g_kl + ki, 16384, fu2);
            }
            MBAR_WAIT((c & 1) ? fu1 : fu0, (c >> 1) & 1);
            const uint32_t kb = base + 32768 + (uint32_t)(c & 1) * 32768;
            const uint64_t dKh = MK_DESC(kb);
            const uint64_t dKl = MK_DESC(kb + 16384);
            #pragma unroll
            for (int kk = 0; kk < 4; ++kk)
                mma_f16_ss(reg, dQh + kk * 2, dKh + kk * 2, IDESC_QK, kk > 0 ? 1u : 0u);
            #pragma unroll
            for (int kk = 0; kk < 4; ++kk)
                mma_f16_ss(reg, dQh + kk * 2, dKl + kk * 2, IDESC_QK, 1u);
            #pragma unroll
            for (int kk = 0; kk < 4; ++kk)
                mma_f16_ss(reg, dQl + kk * 2, dKh + kk * 2, IDESC_QK, 1u);
            TC_COMMIT((c & 1) ? cm1 : cm0);
        }
        MBAR_WAIT((c & 1) ? cm1 : cm0, (c >> 1) & 1);
        TC_FENCE_AFTER();
        {
            const int rrow = (wid & 3) * 32 + lane;
            const int cb   = (wid >> 2) * 64;
            uint32_t r0[32], r1[32];
            TC_LD_X32(r0, reg + cb);
            TC_LD_X32(r1, reg + cb + 32);
            TC_WAIT_LD();
            __half* dst = lbase + (size_t)rrow * LSTRIDE_ + c * 128 + cb;
            #pragma unroll
            for (int i = 0; i < 32; i += 8) {
                uint4 u;
                u.x = pk_h2(__uint_as_float(r0[i+0]), __uint_as_float(r0[i+1]));
                u.y = pk_h2(__uint_as_float(r0[i+2]), __uint_as_float(r0[i+3]));
                u.z = pk_h2(__uint_as_float(r0[i+4]), __uint_as_float(r0[i+5]));
                u.w = pk_h2(__uint_as_float(r0[i+6]), __uint_as_float(r0[i+7]));
                *(uint4*)(dst + i) = u;
            }
            #pragma unroll
            for (int i = 0; i < 32; i += 8) {
                uint4 u;
                u.x = pk_h2(__uint_as_float(r1[i+0]), __uint_as_float(r1[i+1]));
                u.y = pk_h2(__uint_as_float(r1[i+2]), __uint_as_float(r1[i+3]));
                u.z = pk_h2(__uint_as_float(r1[i+4]), __uint_as_float(r1[i+5]));
                u.w = pk_h2(__uint_as_float(r1[i+6]), __uint_as_float(r1[i+7]));
                *(uint4*)(dst + 32 + i) = u;
            }
            TC_FENCE_BEFORE();
        }
        __syncthreads();
    }
    if (tid == 0)
        for (int i = 0; i < 4; ++i) MBAR_INVAL(smem_u32(&s_mbar[i]));
    __syncthreads();
    if (wid == 0) TC_DEALLOC(tmem, 256);
#else
    const int Wp = NKC * 128;
    const float* qkvb = g_qkv + (size_t)b * S_ * QKV3_;
    for (int t = tid; t < 128 * Wp; t += 256) {
        int rr = t / Wp, cc = t - rr * Wp;
        int j = min(t0 * 128 + cc, S_ - 1);
        const float* qp = qkvb + (size_t)(q0 + rr) * QKV3_ + h * 192;
        const float* kp = qkvb + (size_t)j * QKV3_ + h * 192 + 64;
        float acc = 0.0f;
        for (int d = 0; d < 64; ++d) acc += qp[d] * kp[d];
        lbase[(size_t)rr * LSTRIDE_ + cc] = __float2half_rn(acc);
    }
#endif
}

// ================= softmax + attn_mean + fp16 P-image write ==================
__global__ __launch_bounds__(384) void softmax_mean(
    const float* __restrict__ matrix_mask, float* __restrict__ out_attn)
{
    __shared__ float smMask[416];
    __shared__ float smP[12 * 416];

    const int bq = blockIdx.x;
    const int b = bq >> 11, q = bq & 2047;
    const int w = g_w[b];
    const int jloq = max(q - w, 0);
    const int jhiq = min(q + w, S_ - 1);
    const int Wq = jhiq - jloq + 1;
    const int qt = q >> 7, row = q & 127;
    const int q0 = qt * 128;
    const int t0 = max(q0 - w, 0) >> 7;
    const int t1 = min(q0 + 127 + w, S_ - 1) >> 7;
    const int PWU = (t1 - t0 + 1) * 128;
    const int off = jloq - t0 * 128;
    const int tid = threadIdx.x, hh = tid >> 5, lane = tid & 31;

    for (int t = tid; t < Wq; t += 384)
        smMask[t] = matrix_mask[(size_t)bq * S_ + jloq + t];
    __syncthreads();

    {
        const __half* lb = g_logits
            + ((size_t)((b * H_ + hh) * 16 + qt) * 128 + row) * LSTRIDE_ + off;
        float* P = smP + hh * 416;
        float mx = -3.0e38f;
        for (int t = lane; t < Wq; t += 32) {
            float v = __half2float(lb[t]) * 0.125f + smMask[t];
            P[t] = v;
            mx = fmaxf(mx, v);
        }
        #pragma unroll
        for (int o = 16; o > 0; o >>= 1)
            mx = fmaxf(mx, __shfl_xor_sync(0xFFFFFFFFu, mx, o));
        float sum = 0.0f;
        for (int t = lane; t < Wq; t += 32) {
            float e = __expf(P[t] - mx);
            P[t] = e;
            sum += e;
        }
        #pragma unroll
        for (int o = 16; o > 0; o >>= 1)
            sum += __shfl_xor_sync(0xFFFFFFFFu, sum, o);
        const float inv = 1.0f / sum;
        for (int t = lane; t < Wq; t += 32) P[t] *= inv;
        __syncwarp();

        char* pf = (char*)g_pf + (size_t)((b * H_ + hh) * 16 + qt) * (PQCH_ * 16384);
        for (int t = lane * 2; t < PWU; t += 64) {
            float v0 = (t     >= off && t     < off + Wq) ? P[t - off]     : 0.0f;
            float v1 = (t + 1 >= off && t + 1 < off + Wq) ? P[t + 1 - off] : 0.0f;
            const uint32_t o4 = (uint32_t)(t >> 6) * 16384
                              + SW128((uint32_t)(row * 128 + (t & 63) * 2));
            *(uint32_t*)(pf + o4) = pk_h2(v0, v1);
        }
    }
    __syncthreads();

    float* arow = out_attn + (size_t)bq * S_;
    for (int j = tid; j < S_; j += 384) {
        float m = 0.0f;
        if (j >= jloq && j <= jhiq) {
            const int t = j - jloq;
            #pragma unroll
            for (int k = 0; k < H_; ++k) m += smP[k * 416 + t];
            m *= (1.0f / 12.0f);
        }
        arow[j] = m;
    }
}

// ================= pv_tc: P(f16) @ V(f16 hi/lo), 2 MMAs/chunk ================
#define PV_STAGE 32768       // P 16K + Vh 8K + Vl 8K
#define PV_SMEM (1024 + 2 * PV_STAGE)
__global__ __launch_bounds__(256, 3) void pv_tc_kernel() {
    const int qt = blockIdx.x, h = blockIdx.y, b = blockIdx.z;
    const int tid = threadIdx.x, wid = tid >> 5, lane = tid & 31;
    const int q0 = qt * 128;
    const int w = g_w[b];
    const int t0 = max(q0 - w, 0) >> 7;
    const int t1 = min(q0 + 127 + w, S_ - 1) >> 7;
    const int NC = (t1 - t0 + 1) * 2;
    const int bh = b * H_ + h;
    const size_t pimg = (size_t)(bh * 16 + qt) * (PQCH_ * 16384);
#if GB_HAS_TC
    extern __shared__ char dsm[];
    __shared__ uint32_t s_tmem[1];
    __shared__ uint64_t s_mbar[5];

    const uint32_t raw  = smem_u32(dsm);
    const uint32_t base = (raw + 1023u) & ~1023u;
    const uint32_t fu0 = smem_u32(&s_mbar[0]);
    const uint32_t fu1 = smem_u32(&s_mbar[1]);
    const uint32_t em0 = smem_u32(&s_mbar[2]);
    const uint32_t em1 = smem_u32(&s_mbar[3]);
    const uint32_t mbF = smem_u32(&s_mbar[4]);
    const uint32_t slot = smem_u32(&s_tmem[0]);

    if (tid == 0) {
        MBAR_INIT(fu0, 1); MBAR_INIT(fu1, 1);
        MBAR_INIT(em0, 1); MBAR_INIT(em1, 1);
        MBAR_INIT(mbF, 1);
    }
    if (wid == 0) TC_ALLOC(slot, 128);
    __syncthreads();
    const uint32_t tmem = s_tmem[0];

    if (wid == 0 && elect_one()) {
        {
            const size_t vi = ((size_t)bh * 32 + t0 * 2) * 8192;
            MBAR_EXPECT(fu0, PV_STAGE);
            cp_bulk(base,         (const char*)g_pf + pimg, 16384, fu0);
            cp_bulk(base + 16384, (const char*)g_vth + vi, 8192, fu0);
            cp_bulk(base + 24576, (const char*)g_vtl + vi, 8192, fu0);
        }
        for (int c = 0; c < NC; ++c) {
            const int s = c & 1;
            if (c + 1 < NC) {
                const int s2 = (c + 1) & 1;
                const uint32_t fu2 = s2 ? fu1 : fu0;
                if (c + 1 >= 2) MBAR_WAIT(s2 ? em1 : em0, (((c + 1) >> 1) - 1) & 1);
                const uint32_t st = base + s2 * PV_STAGE;
                const size_t vi = ((size_t)bh * 32 + t0 * 2 + c + 1) * 8192;
                MBAR_EXPECT(fu2, PV_STAGE);
                cp_bulk(st,         (const char*)g_pf + pimg + (c + 1) * 16384, 16384, fu2);
                cp_bulk(st + 16384, (const char*)g_vth + vi, 8192, fu2);
                cp_bulk(st + 24576, (const char*)g_vtl + vi, 8192, fu2);
            }
            MBAR_WAIT(s ? fu1 : fu0, (c >> 1) & 1);
            const uint32_t sb = base + s * PV_STAGE;
            const uint64_t dP  = MK_DESC(sb);
            const uint64_t dVh = MK_DESC(sb + 16384);
            const uint64_t dVl = MK_DESC(sb + 24576);
            #pragma unroll
            for (int kk = 0; kk < 4; ++kk)
                mma_f16_ss(tmem, dP + kk * 2, dVh + kk * 2, IDESC_PV,
                           (c == 0 && kk == 0) ? 0u : 1u);
            #pragma unroll
            for (int kk = 0; kk < 4; ++kk)
                mma_f16_ss(tmem, dP + kk * 2, dVl + kk * 2, IDESC_PV, 1u);
            TC_COMMIT(s ? em1 : em0);
            if (c == NC - 1) TC_COMMIT(mbF);
        }
    }

    MBAR_WAIT(mbF, 0);
    TC_FENCE_AFTER();
    {
        const int rrow = (wid & 3) * 32 + lane;
        const int cb   = (wid >> 2) * 32;
        uint32_t r[32];
        TC_LD_X32(r, tmem + cb);
        TC_WAIT_LD();
        TC_FENCE_BEFORE();
        float* dst = g_vals + (size_t)(b * S_ + q0 + rrow) * E_ + h * 64 + cb;
        #pragma unroll
        for (int i = 0; i < 32; i += 4)
            *(float4*)(dst + i) = make_float4(
                __uint_as_float(r[i]),   __uint_as_float(r[i+1]),
                __uint_as_float(r[i+2]), __uint_as_float(r[i+3]));
    }
    __syncthreads();
    if (tid == 0)
        for (int i = 0; i < 5; ++i) MBAR_INVAL(smem_u32(&s_mbar[i]));
    if (wid == 0) TC_DEALLOC(tmem, 128);
#else
    const int PWU = NC * 64;
    for (int t = tid; t < 128 * 64; t += 256) {
        int rr = t >> 6, d = t & 63;
        float acc = 0.0f;
        for (int c = 0; c < PWU; ++c) {
            uint32_t o2 = (uint32_t)(c >> 6) * 16384
                        + SW128((uint32_t)(rr * 128 + (c & 63) * 2));
            float p = __half2float(*(__half*)((char*)g_pf + pimg + o2));
            int j = min(t0 * 128 + c, S_ - 1);
            acc += p * g_qkv[(size_t)(b * S_ + j) * QKV3_ + h * 192 + 128 + d];
        }
        g_vals[(size_t)(b * S_ + q0 + rr) * E_ + h * 64 + d] = acc;
    }
#endif
}

// ---------------- launch -----------------------------------------------------
extern "C" void kernel_launch(void* const* d_in, const int* in_sizes, int n_in,
                              void* d_out, int out_size) {
    const float* x      = (const float*)d_in[0];
    const int*   skpm   = (const int*)  d_in[1];
    const float* mmask  = (const float*)d_in[2];
    const float* qkv_w  = (const float*)d_in[3];
    const float* qkv_b  = (const float*)d_in[4];
    const float* o_w    = (const float*)d_in[5];
    const float* o_b    = (const float*)d_in[6];

    float* out      = (float*)d_out;
    float* out_o    = out;
    float* out_attn = out + (size_t)B_ * S_ * E_;

    float* qkv_ptr = nullptr;
    float* val_ptr = nullptr;
    __nv_bfloat16 *ah, *al, *wh, *wl;
    cudaGetSymbolAddress((void**)&qkv_ptr, g_qkv);
    cudaGetSymbolAddress((void**)&val_ptr, g_vals);
    cudaGetSymbolAddress((void**)&ah, g_a_hi);
    cudaGetSymbolAddress((void**)&al, g_a_lo);
    cudaGetSymbolAddress((void**)&wh, g_w_hi);
    cudaGetSymbolAddress((void**)&wl, g_w_lo);

    cudaFuncSetAttribute(gemm_tc,
                         cudaFuncAttributeMaxDynamicSharedMemorySize, GSMEM);
    cudaFuncSetAttribute(qk_tc_kernel,
                         cudaFuncAttributeMaxDynamicSharedMemorySize, QK_SMEM);
    cudaFuncSetAttribute(pv_tc_kernel,
                         cudaFuncAttributeMaxDynamicSharedMemorySize, PV_SMEM);

    // 1) per-batch window size
    wsz_kernel<<<B_, 256>>>(skpm);

    // 2) QKV projection (tcgen05 bf16x3, 128x256 tiles, bulk-fed)
    cvt_split_tiled<<<(NA_ / 8 + 255) / 256, 256>>>(x, ah, al, B_ * S_, DIN_);
    cvt_split_tiled<<<(NWQ_ / 8 + 255) / 256, 256>>>(qkv_w, wh, wl, QKV3_, DIN_);
    {
        dim3 grid(QKV3_ / GBN, (B_ * S_) / GBM);
        gemm_tc<<<grid, 256, GSMEM>>>(x, qkv_w, ah, al, wh, wl,
                                      qkv_b, qkv_ptr, B_ * S_, QKV3_, DIN_);
    }

    // 3) split Q/K images (bf16 hi/lo) and V^T chunk images (fp16 hi/lo)
    {
        dim3 gq(16, B_);
        split_qk<<<gq, 256>>>();
        dim3 gv(32, B_);
        split_v<<<gv, 256>>>();
    }

    // 4) banded QK^T -> fp16 logits scratch
    {
        dim3 grid(16, H_, B_);
        qk_tc_kernel<<<grid, 256, QK_SMEM>>>();
    }

    // 5) softmax + attn_mean + fp16 P-image write
    softmax_mean<<<B_ * S_, 384>>>(mmask, out_attn);

    // 6) P @ V (fp16) -> g_vals
    {
        dim3 grid(16, H_, B_);
        pv_tc_kernel<<<grid, 256, PV_SMEM>>>();
    }

    // 7) output projection
    cvt_split_tiled<<<(NA_ / 8 + 255) / 256, 256>>>(val_ptr, ah, al, B_ * S_, E_);
    cvt_split_tiled<<<((E_ * E_) / 8 + 255) / 256, 256>>>(o_w, wh, wl, E_, E_);
    {
        dim3 grid(E_ / GBN, (B_ * S_) / GBM);
        gemm_tc<<<grid, 256, GSMEM>>>(val_ptr, o_w, ah, al, wh, wl,
                                      o_b, out_o, B_ * S_, E_, E_);
    }
}